// round 3
// baseline (speedup 1.0000x reference)
#include <cuda_runtime.h>
#include <math.h>

#define NN 20000
#define NE 640000
#define NL 2
#define MAXR 2.5f
#define INV_NN 0.17677669529663687f   // 1/sqrt(32)

// ---------------- scratch (device globals; no allocs) ----------------
static __device__ float g_Q[64 * 2];
static __device__ float g_ys[2][NN * 64];
static __device__ float g_yv[2][NN * 192];
static __device__ float g_s1[NN * 64];
static __device__ float g_v1[NN * 192];          // [n][3][64] x-major
static __device__ float g_agg[NN * 256];         // (n, c, 4): vx,vy,vz,s
static __device__ float g_pos[NN * 3];
static __device__ float g_Bs[NL * 100 * 64 * 128];
static __device__ float g_Bv[NL * 100 * 64 * 64];

// ---------------- init: Q (per-block inline), y_v uplift, zero agg ----------
__global__ void __launch_bounds__(256) k_init(const float* __restrict__ x,
                                              const float* __restrict__ M) {
    __shared__ float sQ[128];
    int tid = threadIdx.x;
    if (tid == 0) {
        double a = 0, b = 0, c = 0;
        for (int i = 0; i < 64; i++) {
            double m0 = M[2 * i], m1 = M[2 * i + 1];
            a += m0 * m0; b += m0 * m1; c += m1 * m1;
        }
        double det = a * c - b * b;
        double s = sqrt(det);
        double t = a + c;
        double denom = sqrt(t + 2.0 * s);
        double p00 = (a + s) / denom, p01 = b / denom, p11 = (c + s) / denom;
        double pdet = p00 * p11 - p01 * p01;
        double i00 = p11 / pdet, i01 = -p01 / pdet, i11 = p00 / pdet;
        for (int i = 0; i < 64; i++) {
            double m0 = M[2 * i], m1 = M[2 * i + 1];
            sQ[2 * i]     = (float)(m0 * i00 + m1 * i01);
            sQ[2 * i + 1] = (float)(m0 * i01 + m1 * i11);
        }
        if (blockIdx.x == 0)
            for (int i = 0; i < 128; i++) g_Q[i] = sQ[i];
    }
    __syncthreads();
    int i = blockIdx.x * 256 + tid;
    if (i >= NN * 64) return;
    int n = i >> 6, c = i & 63;
    float q0 = sQ[c * 2], q1 = sQ[c * 2 + 1];
    const float* xp = x + n * 6;
    float v0 = xp[0] * q0 + xp[3] * q1;
    float v1 = xp[1] * q0 + xp[4] * q1;
    float v2 = xp[2] * q0 + xp[5] * q1;
    int base = n * 192 + c * 3;
    g_yv[0][base + 0] = v0; g_yv[0][base + 1] = v1; g_yv[0][base + 2] = v2;
    g_yv[1][base + 0] = v0; g_yv[1][base + 1] = v1; g_yv[1][base + 2] = v2;
    g_ys[0][i] = 0.f; g_ys[1][i] = 0.f;
    if (c < 3) g_pos[n * 3 + c] = xp[c];
    reinterpret_cast<float4*>(g_agg)[i] = make_float4(0.f, 0.f, 0.f, 0.f);
}

// ------- Bs[l,a,c,o] = sum_e emb[a,e]*sc_s_w[l,c,e,o]; same for Bv -------
__global__ void k_bs(const float* __restrict__ emb,
                     const float* __restrict__ scs,
                     const float* __restrict__ scv) {
    const int TOTS = NL * 100 * 64 * 128;
    const int TOTV = NL * 100 * 64 * 64;
    for (int idx = blockIdx.x * blockDim.x + threadIdx.x; idx < TOTS + TOTV;
         idx += gridDim.x * blockDim.x) {
        if (idx < TOTS) {
            int o = idx & 127;
            int c = (idx >> 7) & 63;
            int a = (idx >> 13) % 100;
            int l = idx / (128 * 64 * 100);
            const float* w = scs + ((size_t)(l * 64 + c) * 32) * 128 + o;
            const float* em = emb + a * 32;
            float acc = 0.f;
#pragma unroll 8
            for (int e = 0; e < 32; e++) acc += em[e] * w[e * 128];
            g_Bs[idx] = acc;
        } else {
            int j = idx - TOTS;
            int o = j & 63;
            int c = (j >> 6) & 63;
            int a = (j >> 12) % 100;
            int l = j / (64 * 64 * 100);
            const float* w = scv + ((size_t)(l * 64 + c) * 32) * 64 + o;
            const float* em = emb + a * 32;
            float acc = 0.f;
#pragma unroll 8
            for (int e = 0; e < 32; e++) acc += em[e] * w[e * 64];
            g_Bv[j] = acc;
        }
    }
}

// ---------------- zero aggregation buffer (between layers) ----------------
__global__ void k_zero() {
    float4 z = make_float4(0.f, 0.f, 0.f, 0.f);
    float4* p = reinterpret_cast<float4*>(g_agg);
    for (int i = blockIdx.x * blockDim.x + threadIdx.x; i < NN * 64;
         i += gridDim.x * blockDim.x)
        p[i] = z;
}

// ---------------- pre: s1 = y_s@lin1_s, v1 = y_v@lin1_v (v1 x-major) --------
__global__ void __launch_bounds__(256) k_pre(const float* __restrict__ lin1s,
                                             const float* __restrict__ lin1v,
                                             int layer, int cur) {
    __shared__ float sWs[4096], sWv[4096];
    __shared__ float sy[8][256];
    int tid = threadIdx.x;
    const float* Ws = lin1s + layer * 4096;
    const float* Wv = lin1v + layer * 4096;
    for (int k = tid; k < 4096; k += 256) { sWs[k] = Ws[k]; sWv[k] = Wv[k]; }
    const float* ys = g_ys[cur];
    const float* yv = g_yv[cur];
    int n0 = blockIdx.x * 8;
    for (int k = tid; k < 2048; k += 256) {
        int nn = k >> 8, j = k & 255;
        int n = n0 + nn;
        sy[nn][j] = (j < 64) ? ys[n * 64 + j] : yv[n * 192 + j - 64];
    }
    __syncthreads();
    for (int nn = 0; nn < 8; nn++) {
        int n = n0 + nn;
        if (tid < 64) {
            int d = tid;
            float acc = 0.f;
#pragma unroll 8
            for (int c = 0; c < 64; c++) acc += sy[nn][c] * sWs[c * 64 + d];
            g_s1[n * 64 + d] = acc;
        } else {
            int idx = tid - 64;
            int d = idx & 63, xx = idx >> 6;
            float acc = 0.f;
#pragma unroll 8
            for (int c = 0; c < 64; c++) acc += sy[nn][64 + c * 3 + xx] * sWv[c * 64 + d];
            g_v1[n * 192 + xx * 64 + d] = acc;   // x-major
        }
    }
}

// ---------------- edge kernel: warp per edge (unsorted) ----------------
__global__ void __launch_bounds__(256) k_edge(const int* __restrict__ esrc,
                                              const int* __restrict__ edst,
                                              const float* __restrict__ rW1,
                                              const float* __restrict__ rb1,
                                              const float* __restrict__ rW2,
                                              int layer) {
    __shared__ float sW1[256];
    __shared__ float sb1v[32];
    __shared__ float sW2t[4096];   // [k][lane][4] interleaved
    int tid = threadIdx.x;
    for (int k = tid; k < 256; k += 256) sW1[k] = rW1[layer * 256 + k];
    if (tid < 32) sb1v[tid] = rb1[layer * 32 + tid];
    for (int t = tid; t < 4096; t += 256) {
        int k = t >> 7, r = t & 127, ln = r >> 2, g = r & 3;
        sW2t[t] = rW2[layer * 4096 + k * 128 + g * 32 + ln];
    }
    __syncthreads();
    int lane = tid & 31;
    int gwarp = (blockIdx.x * 256 + tid) >> 5;
    int nw = gridDim.x * 8;
    const float PI = 3.14159265358979f;
    for (int e = gwarp; e < NE; e += nw) {
        int src = esrc[e], dst = edst[e];
        float ev0 = g_pos[src * 3 + 0] - g_pos[dst * 3 + 0];
        float ev1 = g_pos[src * 3 + 1] - g_pos[dst * 3 + 1];
        float ev2 = g_pos[src * 3 + 2] - g_pos[dst * 3 + 2];
        float l2 = ev0 * ev0 + ev1 * ev1 + ev2 * ev2;
        if (l2 >= MAXR * MAXR) continue;
        float elen = sqrtf(l2);
        float safe = fmaxf(elen, 1e-9f);
        float inv = 1.0f / safe;
        float u = 2.f * (elen * (1.0f / MAXR) - 1.f);
        float cut = 0.5f * (1.f - __cosf(PI * u));
        float ca = cut * 1.7320508075688772f * inv;
        float ea0 = ca * ev0, ea1 = ca * ev1, ea2 = ca * ev2;
        // radial basis via sin recurrence
        float th = (PI / MAXR) * safe;
        float sk = __sinf(th), c2 = 2.f * __cosf(th), skm1 = 0.f;
        float fac = 2.5298221281347035f * inv;
        float hs = sb1v[lane];
#pragma unroll
        for (int k = 0; k < 8; k++) {
            hs += (fac * sk) * sW1[k * 32 + lane];
            float t = c2 * sk - skm1; skm1 = sk; sk = t;
        }
        float hval = hs / (1.f + __expf(-hs));  // silu
        float w0 = 0.f, w1 = 0.f, w2 = 0.f, w3 = 0.f;
#pragma unroll
        for (int k = 0; k < 32; k++) {
            float hk = __shfl_sync(0xffffffffu, hval, k);
            float4 wv = *reinterpret_cast<const float4*>(&sW2t[k * 128 + lane * 4]);
            w0 = fmaf(hk, wv.x, w0);
            w1 = fmaf(hk, wv.y, w1);
            w2 = fmaf(hk, wv.z, w2);
            w3 = fmaf(hk, wv.w, w3);
        }
        const float* s1p = g_s1 + (size_t)src * 64;
        const float* v1p = g_v1 + (size_t)src * 192;  // [3][64]
        float sa = s1p[lane] * w0;
        float sb = s1p[lane + 32] * w1;
        float da = w2 * (v1p[lane] * ea0 + v1p[64 + lane] * ea1 + v1p[128 + lane] * ea2);
        float db = w3 * (v1p[lane + 32] * ea0 + v1p[96 + lane] * ea1 + v1p[160 + lane] * ea2);
        float4* ap = reinterpret_cast<float4*>(g_agg + (size_t)dst * 256);
        atomicAdd(ap + lane,      make_float4(sa * ea0, sa * ea1, sa * ea2, da));
        atomicAdd(ap + lane + 32, make_float4(sb * ea0, sb * ea1, sb * ea2, db));
    }
}

// ---------------- post ----------------
__global__ void __launch_bounds__(128) k_post(const float* __restrict__ lin2s,
                                              const float* __restrict__ lin2v,
                                              const float* __restrict__ sis,
                                              const float* __restrict__ siv,
                                              const int* __restrict__ attr,
                                              const float* __restrict__ hv,
                                              const float* __restrict__ mv,
                                              int layer, int cur,
                                              float* __restrict__ outp) {
    extern __shared__ float sw[];
    float* sL2s = sw;            // 8192
    float* sL2v = sw + 8192;     // 4096
    float* sSs  = sw + 12288;    // 4096
    float* sSv  = sw + 16384;    // 4096
    __shared__ float s_Q[128];
    __shared__ float s_ys[64], s_aggs[64];
    __shared__ float s_yv[192], s_aggv[192];
    __shared__ float s_outs[128], s_outv[192];
    __shared__ float s_y2s[64], s_y2v[192];
    __shared__ float s_newv[192];
    int tid = threadIdx.x;
    const float* L2s = lin2s + layer * 8192;
    const float* L2v = lin2v + layer * 4096;
    const float* Ss = sis + layer * 4096;
    const float* Sv = siv + layer * 4096;
    for (int k = tid; k < 8192; k += 128) sL2s[k] = L2s[k];
    for (int k = tid; k < 4096; k += 128) { sL2v[k] = L2v[k]; sSs[k] = Ss[k]; sSv[k] = Sv[k]; }
    s_Q[tid] = g_Q[tid];
    float hh = hv[layer] * hv[layer];
    float m = mv[layer];
    float* ys_new = g_ys[cur ^ 1];
    float* yv_new = g_yv[cur ^ 1];
    const float* ys_cur = g_ys[cur];
    const float* yv_cur = g_yv[cur];
    __syncthreads();
    int n0 = blockIdx.x * 8;
    for (int nn = 0; nn < 8; nn++) {
        int n = n0 + nn;
        if (tid < 64) {
            s_ys[tid] = ys_cur[n * 64 + tid];
            s_aggs[tid] = g_agg[n * 256 + tid * 4 + 3] * INV_NN;
        }
        for (int j = tid; j < 192; j += 128) {
            int c = j / 3, xx = j - 3 * c;
            s_yv[j] = yv_cur[n * 192 + j];
            s_aggv[j] = g_agg[n * 256 + c * 4 + xx] * INV_NN;
        }
        __syncthreads();
        int a = attr[n];
        const float* Bs = g_Bs + (size_t)(layer * 100 + a) * 8192;
        const float* Bv = g_Bv + (size_t)(layer * 100 + a) * 4096;
        {
            float acc = 0.f;
#pragma unroll 8
            for (int c = 0; c < 64; c++)
                acc += s_aggs[c] * sL2s[c * 128 + tid] + s_ys[c] * Bs[c * 128 + tid];
            s_outs[tid] = acc;
        }
        if (tid < 64) {
            int d = tid;
            float a0 = 0.f, a1 = 0.f, a2 = 0.f;
#pragma unroll 8
            for (int c = 0; c < 64; c++) {
                float w = sL2v[c * 64 + d], bw = Bv[c * 64 + d];
                a0 += s_aggv[c * 3 + 0] * w + s_yv[c * 3 + 0] * bw;
                a1 += s_aggv[c * 3 + 1] * w + s_yv[c * 3 + 1] * bw;
                a2 += s_aggv[c * 3 + 2] * w + s_yv[c * 3 + 2] * bw;
            }
            s_outv[d * 3 + 0] = a0; s_outv[d * 3 + 1] = a1; s_outv[d * 3 + 2] = a2;
        } else {
            int d = tid - 64;
            float y2 = 0.f, b0 = 0.f, b1 = 0.f, b2 = 0.f;
#pragma unroll 8
            for (int c = 0; c < 64; c++) {
                float wsv = sSv[c * 64 + d];
                y2 += s_ys[c] * sSs[c * 64 + d];
                b0 += s_yv[c * 3 + 0] * wsv;
                b1 += s_yv[c * 3 + 1] * wsv;
                b2 += s_yv[c * 3 + 2] * wsv;
            }
            s_y2s[d] = y2;
            s_y2v[d * 3 + 0] = b0; s_y2v[d * 3 + 1] = b1; s_y2v[d * 3 + 2] = b2;
        }
        __syncthreads();
        if (tid < 64) {
            int c = tid;
            float os = s_outs[c];
            float gs = os / (1.f + __expf(-os));
            float gate = 1.f / (1.f + __expf(-s_outs[64 + c]));
            float yo = ys_new[n * 64 + c];
            float ns = 2.f * s_ys[c] - yo + hh * (m * gs + (m - 1.f) * s_y2s[c]);
            ys_new[n * 64 + c] = ns;
#pragma unroll
            for (int xx = 0; xx < 3; xx++) {
                float yov = yv_new[n * 192 + c * 3 + xx];
                float nv = 2.f * s_yv[c * 3 + xx] - yov +
                           hh * (m * gate * s_outv[c * 3 + xx] + (m - 1.f) * s_y2v[c * 3 + xx]);
                yv_new[n * 192 + c * 3 + xx] = nv;
                s_newv[c * 3 + xx] = nv;
            }
        }
        __syncthreads();
        if (tid < 6) {
            int k = tid / 3, xx = tid - 3 * k;
            float acc = 0.f;
#pragma unroll 8
            for (int c = 0; c < 64; c++) acc += s_newv[c * 3 + xx] * s_Q[c * 2 + k];
            if (layer == 0) {
                if (k == 0) g_pos[n * 3 + xx] = acc;
            } else {
                outp[n * 6 + k * 3 + xx] = acc;
            }
        }
        __syncthreads();
    }
}

// ---------------- launch ----------------
extern "C" void kernel_launch(void* const* d_in, const int* in_sizes, int n_in,
                              void* d_out, int out_size) {
    const float* x        = (const float*)d_in[0];
    const int*   attr     = (const int*)d_in[2];
    const int*   esrc     = (const int*)d_in[3];
    const int*   edst     = (const int*)d_in[4];
    const float* emb      = (const float*)d_in[5];
    const float* uplift   = (const float*)d_in[6];
    const float* h        = (const float*)d_in[7];
    const float* mix      = (const float*)d_in[8];
    const float* rW1      = (const float*)d_in[9];
    const float* rb1      = (const float*)d_in[10];
    const float* rW2      = (const float*)d_in[11];
    const float* lin1s    = (const float*)d_in[12];
    const float* lin1v    = (const float*)d_in[13];
    const float* lin2s    = (const float*)d_in[14];
    const float* lin2v    = (const float*)d_in[15];
    const float* scs      = (const float*)d_in[16];
    const float* scv      = (const float*)d_in[17];
    const float* sis      = (const float*)d_in[18];
    const float* siv      = (const float*)d_in[19];
    float* out = (float*)d_out;

    cudaFuncSetAttribute(k_post, cudaFuncAttributeMaxDynamicSharedMemorySize, 84 * 1024);

    // launch index 3 (the ncu-profiled slot) = layer-0 k_edge
    k_init<<<(NN * 64 + 255) / 256, 256>>>(x, uplift);          // 0
    k_pre<<<NN / 8, 256>>>(lin1s, lin1v, 0, 0);                 // 1
    k_bs<<<2400, 256>>>(emb, scs, scv);                         // 2
    k_edge<<<2048, 256>>>(esrc, edst, rW1, rb1, rW2, 0);        // 3  <- profiled
    k_post<<<NN / 8, 128, 81920>>>(lin2s, lin2v, sis, siv, attr, h, mix, 0, 0, out);  // 4
    k_zero<<<1024, 256>>>();                                    // 5
    k_pre<<<NN / 8, 256>>>(lin1s, lin1v, 1, 1);                 // 6
    k_edge<<<2048, 256>>>(esrc, edst, rW1, rb1, rW2, 1);        // 7
    k_post<<<NN / 8, 128, 81920>>>(lin2s, lin2v, sis, siv, attr, h, mix, 1, 1, out);  // 8
}

// round 4
// speedup vs baseline: 1.3790x; 1.3790x over previous
#include <cuda_runtime.h>
#include <math.h>

#define NN 20000
#define NE 640000
#define NL 2
#define MAXR 2.5f
#define INV_NN 0.17677669529663687f   // 1/sqrt(32)

// ---------------- scratch (device globals; no allocs) ----------------
static __device__ float g_Q[64 * 2];
static __device__ float g_ys[2][NN * 64];
static __device__ float g_yv[2][NN * 192];
static __device__ float g_s1[NN * 64];
static __device__ float g_v1[NN * 192];          // [n][3][64] x-major
static __device__ float g_agg[NN * 256];         // (n, c, 4): vx,vy,vz,s
static __device__ float g_pos[NN * 3];
static __device__ float g_Bs[NL * 100 * 64 * 128];
static __device__ float g_Bv[NL * 100 * 64 * 64];

// ------- fused: init (blocks 0..4999) + B-precompute (blocks 5000..7399) ----
__global__ void __launch_bounds__(256) k_init(const float* __restrict__ x,
                                              const float* __restrict__ M,
                                              const float* __restrict__ emb,
                                              const float* __restrict__ scs,
                                              const float* __restrict__ scv) {
    int tid = threadIdx.x;
    if (blockIdx.x < 5000) {
        __shared__ float sQ[128];
        if (tid == 0) {
            double a = 0, b = 0, c = 0;
            for (int i = 0; i < 64; i++) {
                double m0 = M[2 * i], m1 = M[2 * i + 1];
                a += m0 * m0; b += m0 * m1; c += m1 * m1;
            }
            double det = a * c - b * b;
            double s = sqrt(det);
            double t = a + c;
            double denom = sqrt(t + 2.0 * s);
            double p00 = (a + s) / denom, p01 = b / denom, p11 = (c + s) / denom;
            double pdet = p00 * p11 - p01 * p01;
            double i00 = p11 / pdet, i01 = -p01 / pdet, i11 = p00 / pdet;
            for (int i = 0; i < 64; i++) {
                double m0 = M[2 * i], m1 = M[2 * i + 1];
                sQ[2 * i]     = (float)(m0 * i00 + m1 * i01);
                sQ[2 * i + 1] = (float)(m0 * i01 + m1 * i11);
            }
            if (blockIdx.x == 0)
                for (int i = 0; i < 128; i++) g_Q[i] = sQ[i];
        }
        __syncthreads();
        int i = blockIdx.x * 256 + tid;
        if (i >= NN * 64) return;
        int n = i >> 6, c = i & 63;
        float q0 = sQ[c * 2], q1 = sQ[c * 2 + 1];
        const float* xp = x + n * 6;
        float v0 = xp[0] * q0 + xp[3] * q1;
        float v1 = xp[1] * q0 + xp[4] * q1;
        float v2 = xp[2] * q0 + xp[5] * q1;
        int base = n * 192 + c * 3;
        g_yv[0][base + 0] = v0; g_yv[0][base + 1] = v1; g_yv[0][base + 2] = v2;
        g_yv[1][base + 0] = v0; g_yv[1][base + 1] = v1; g_yv[1][base + 2] = v2;
        g_ys[0][i] = 0.f; g_ys[1][i] = 0.f;
        if (c < 3) g_pos[n * 3 + c] = xp[c];
        reinterpret_cast<float4*>(g_agg)[i] = make_float4(0.f, 0.f, 0.f, 0.f);
    } else {
        const int TOTS = NL * 100 * 64 * 128;
        const int TOTV = NL * 100 * 64 * 64;
        const int NB = 2400;
        for (int idx = (blockIdx.x - 5000) * 256 + tid; idx < TOTS + TOTV;
             idx += NB * 256) {
            if (idx < TOTS) {
                int o = idx & 127;
                int c = (idx >> 7) & 63;
                int a = (idx >> 13) % 100;
                int l = idx / (128 * 64 * 100);
                const float* w = scs + ((size_t)(l * 64 + c) * 32) * 128 + o;
                const float* em = emb + a * 32;
                float acc = 0.f;
#pragma unroll 8
                for (int e = 0; e < 32; e++) acc += em[e] * w[e * 128];
                g_Bs[idx] = acc;
            } else {
                int j = idx - TOTS;
                int o = j & 63;
                int c = (j >> 6) & 63;
                int a = (j >> 12) % 100;
                int l = j / (64 * 64 * 100);
                const float* w = scv + ((size_t)(l * 64 + c) * 32) * 64 + o;
                const float* em = emb + a * 32;
                float acc = 0.f;
#pragma unroll 8
                for (int e = 0; e < 32; e++) acc += em[e] * w[e * 64];
                g_Bv[j] = acc;
            }
        }
    }
}

// ---------------- zero aggregation buffer (between layers) ----------------
__global__ void k_zero() {
    float4 z = make_float4(0.f, 0.f, 0.f, 0.f);
    float4* p = reinterpret_cast<float4*>(g_agg);
    for (int i = blockIdx.x * blockDim.x + threadIdx.x; i < NN * 64;
         i += gridDim.x * blockDim.x)
        p[i] = z;
}

// ---------------- pre: s1 = y_s@lin1_s, v1 = y_v@lin1_v (v1 x-major) --------
__global__ void __launch_bounds__(256) k_pre(const float* __restrict__ lin1s,
                                             const float* __restrict__ lin1v,
                                             int layer, int cur) {
    __shared__ float sWs[4096], sWv[4096];
    __shared__ float sy[8][256];
    int tid = threadIdx.x;
    const float* Ws = lin1s + layer * 4096;
    const float* Wv = lin1v + layer * 4096;
    for (int k = tid; k < 4096; k += 256) { sWs[k] = Ws[k]; sWv[k] = Wv[k]; }
    const float* ys = g_ys[cur];
    const float* yv = g_yv[cur];
    int n0 = blockIdx.x * 8;
    for (int k = tid; k < 2048; k += 256) {
        int nn = k >> 8, j = k & 255;
        int n = n0 + nn;
        sy[nn][j] = (j < 64) ? ys[n * 64 + j] : yv[n * 192 + j - 64];
    }
    __syncthreads();
    for (int nn = 0; nn < 8; nn++) {
        int n = n0 + nn;
        if (tid < 64) {
            int d = tid;
            float acc = 0.f;
#pragma unroll 8
            for (int c = 0; c < 64; c++) acc += sy[nn][c] * sWs[c * 64 + d];
            g_s1[n * 64 + d] = acc;
        } else {
            int idx = tid - 64;
            int d = idx & 63, xx = idx >> 6;
            float acc = 0.f;
#pragma unroll 8
            for (int c = 0; c < 64; c++) acc += sy[nn][64 + c * 3 + xx] * sWv[c * 64 + d];
            g_v1[n * 192 + xx * 64 + d] = acc;   // x-major
        }
    }
}

// ---------------- edge kernel: warp per edge (unsorted) ----------------
__global__ void __launch_bounds__(256) k_edge(const int* __restrict__ esrc,
                                              const int* __restrict__ edst,
                                              const float* __restrict__ rW1,
                                              const float* __restrict__ rb1,
                                              const float* __restrict__ rW2,
                                              int layer) {
    __shared__ float sW1[256];
    __shared__ float sb1v[32];
    __shared__ float sW2t[4096];   // [k][lane][4] interleaved
    int tid = threadIdx.x;
    for (int k = tid; k < 256; k += 256) sW1[k] = rW1[layer * 256 + k];
    if (tid < 32) sb1v[tid] = rb1[layer * 32 + tid];
    for (int t = tid; t < 4096; t += 256) {
        int k = t >> 7, r = t & 127, ln = r >> 2, g = r & 3;
        sW2t[t] = rW2[layer * 4096 + k * 128 + g * 32 + ln];
    }
    __syncthreads();
    int lane = tid & 31;
    int gwarp = (blockIdx.x * 256 + tid) >> 5;
    int nw = gridDim.x * 8;
    const float PI = 3.14159265358979f;
    for (int e = gwarp; e < NE; e += nw) {
        int src = esrc[e], dst = edst[e];
        float ev0 = g_pos[src * 3 + 0] - g_pos[dst * 3 + 0];
        float ev1 = g_pos[src * 3 + 1] - g_pos[dst * 3 + 1];
        float ev2 = g_pos[src * 3 + 2] - g_pos[dst * 3 + 2];
        float l2 = ev0 * ev0 + ev1 * ev1 + ev2 * ev2;
        if (l2 >= MAXR * MAXR) continue;
        float elen = sqrtf(l2);
        float safe = fmaxf(elen, 1e-9f);
        float inv = 1.0f / safe;
        float u = 2.f * (elen * (1.0f / MAXR) - 1.f);
        float cut = 0.5f * (1.f - __cosf(PI * u));
        float ca = cut * 1.7320508075688772f * inv;
        float ea0 = ca * ev0, ea1 = ca * ev1, ea2 = ca * ev2;
        float th = (PI / MAXR) * safe;
        float sk = __sinf(th), c2 = 2.f * __cosf(th), skm1 = 0.f;
        float fac = 2.5298221281347035f * inv;
        float hs = sb1v[lane];
#pragma unroll
        for (int k = 0; k < 8; k++) {
            hs += (fac * sk) * sW1[k * 32 + lane];
            float t = c2 * sk - skm1; skm1 = sk; sk = t;
        }
        float hval = hs / (1.f + __expf(-hs));  // silu
        float w0 = 0.f, w1 = 0.f, w2 = 0.f, w3 = 0.f;
#pragma unroll
        for (int k = 0; k < 32; k++) {
            float hk = __shfl_sync(0xffffffffu, hval, k);
            float4 wv = *reinterpret_cast<const float4*>(&sW2t[k * 128 + lane * 4]);
            w0 = fmaf(hk, wv.x, w0);
            w1 = fmaf(hk, wv.y, w1);
            w2 = fmaf(hk, wv.z, w2);
            w3 = fmaf(hk, wv.w, w3);
        }
        const float* s1p = g_s1 + (size_t)src * 64;
        const float* v1p = g_v1 + (size_t)src * 192;  // [3][64]
        float sa = s1p[lane] * w0;
        float sb = s1p[lane + 32] * w1;
        float da = w2 * (v1p[lane] * ea0 + v1p[64 + lane] * ea1 + v1p[128 + lane] * ea2);
        float db = w3 * (v1p[lane + 32] * ea0 + v1p[96 + lane] * ea1 + v1p[160 + lane] * ea2);
        float4* ap = reinterpret_cast<float4*>(g_agg + (size_t)dst * 256);
        atomicAdd(ap + lane,      make_float4(sa * ea0, sa * ea1, sa * ea2, da));
        atomicAdd(ap + lane + 32, make_float4(sb * ea0, sb * ea1, sb * ea2, db));
    }
}

// ------ post v2: 256 threads, 32 nodes/block, 2 nodes concurrent ------
__global__ void __launch_bounds__(256) k_post(const float* __restrict__ lin2s,
                                              const float* __restrict__ lin2v,
                                              const float* __restrict__ sis,
                                              const float* __restrict__ siv,
                                              const int* __restrict__ attr,
                                              const float* __restrict__ hv,
                                              const float* __restrict__ mv,
                                              int layer, int cur,
                                              float* __restrict__ outp) {
    extern __shared__ float sw[];
    float* sL2s = sw;            // 8192
    float* sL2v = sw + 8192;     // 4096
    float* sSs  = sw + 12288;    // 4096
    float* sSv  = sw + 16384;    // 4096
    __shared__ float s_Q[128];
    __shared__ float s_ys[2][64], s_aggs[2][64];
    __shared__ float s_yv[2][192], s_aggv[2][192];
    __shared__ float s_outs[2][128], s_outv[2][192];
    __shared__ float s_y2s[2][64], s_y2v[2][192];
    __shared__ float s_newv[2][192];
    int tid = threadIdx.x;
    int half = tid >> 7, ltid = tid & 127;
    const float* L2s = lin2s + layer * 8192;
    const float* L2v = lin2v + layer * 4096;
    const float* Ss = sis + layer * 4096;
    const float* Sv = siv + layer * 4096;
    for (int k = tid; k < 8192; k += 256) sL2s[k] = L2s[k];
    for (int k = tid; k < 4096; k += 256) { sL2v[k] = L2v[k]; sSs[k] = Ss[k]; sSv[k] = Sv[k]; }
    if (tid < 128) s_Q[tid] = g_Q[tid];
    float hh = hv[layer] * hv[layer];
    float m = mv[layer];
    float* ys_new = g_ys[cur ^ 1];
    float* yv_new = g_yv[cur ^ 1];
    const float* ys_cur = g_ys[cur];
    const float* yv_cur = g_yv[cur];
    __syncthreads();
    int n0 = blockIdx.x * 32;
    for (int nn = 0; nn < 16; nn++) {
        int n = n0 + nn * 2 + half;
        if (ltid < 64) {
            s_ys[half][ltid] = ys_cur[n * 64 + ltid];
            s_aggs[half][ltid] = g_agg[n * 256 + ltid * 4 + 3] * INV_NN;
        }
        for (int j = ltid; j < 192; j += 128) {
            int c = j / 3, xx = j - 3 * c;
            s_yv[half][j] = yv_cur[n * 192 + j];
            s_aggv[half][j] = g_agg[n * 256 + c * 4 + xx] * INV_NN;
        }
        __syncthreads();
        int a = attr[n];
        const float* Bs = g_Bs + (size_t)(layer * 100 + a) * 8192;
        const float* Bv = g_Bv + (size_t)(layer * 100 + a) * 4096;
        {
            float acc = 0.f;
#pragma unroll 16
            for (int c = 0; c < 64; c++)
                acc += s_aggs[half][c] * sL2s[c * 128 + ltid] + s_ys[half][c] * Bs[c * 128 + ltid];
            s_outs[half][ltid] = acc;
        }
        if (ltid < 64) {
            int d = ltid;
            float a0 = 0.f, a1 = 0.f, a2 = 0.f;
#pragma unroll 16
            for (int c = 0; c < 64; c++) {
                float w = sL2v[c * 64 + d], bw = Bv[c * 64 + d];
                a0 += s_aggv[half][c * 3 + 0] * w + s_yv[half][c * 3 + 0] * bw;
                a1 += s_aggv[half][c * 3 + 1] * w + s_yv[half][c * 3 + 1] * bw;
                a2 += s_aggv[half][c * 3 + 2] * w + s_yv[half][c * 3 + 2] * bw;
            }
            s_outv[half][d * 3 + 0] = a0; s_outv[half][d * 3 + 1] = a1; s_outv[half][d * 3 + 2] = a2;
        } else {
            int d = ltid - 64;
            float y2 = 0.f, b0 = 0.f, b1 = 0.f, b2 = 0.f;
#pragma unroll 16
            for (int c = 0; c < 64; c++) {
                float wsv = sSv[c * 64 + d];
                y2 += s_ys[half][c] * sSs[c * 64 + d];
                b0 += s_yv[half][c * 3 + 0] * wsv;
                b1 += s_yv[half][c * 3 + 1] * wsv;
                b2 += s_yv[half][c * 3 + 2] * wsv;
            }
            s_y2s[half][d] = y2;
            s_y2v[half][d * 3 + 0] = b0; s_y2v[half][d * 3 + 1] = b1; s_y2v[half][d * 3 + 2] = b2;
        }
        __syncthreads();
        if (ltid < 64) {
            int c = ltid;
            float os = s_outs[half][c];
            float gs = os / (1.f + __expf(-os));
            float gate = 1.f / (1.f + __expf(-s_outs[half][64 + c]));
            float yo = ys_new[n * 64 + c];
            float ns = 2.f * s_ys[half][c] - yo + hh * (m * gs + (m - 1.f) * s_y2s[half][c]);
            ys_new[n * 64 + c] = ns;
#pragma unroll
            for (int xx = 0; xx < 3; xx++) {
                float yov = yv_new[n * 192 + c * 3 + xx];
                float nv = 2.f * s_yv[half][c * 3 + xx] - yov +
                           hh * (m * gate * s_outv[half][c * 3 + xx] + (m - 1.f) * s_y2v[half][c * 3 + xx]);
                yv_new[n * 192 + c * 3 + xx] = nv;
                s_newv[half][c * 3 + xx] = nv;
            }
        }
        __syncthreads();
        if (ltid < 6) {
            int k = ltid / 3, xx = ltid - 3 * k;
            float acc = 0.f;
#pragma unroll 16
            for (int c = 0; c < 64; c++) acc += s_newv[half][c * 3 + xx] * s_Q[c * 2 + k];
            if (layer == 0) {
                if (k == 0) g_pos[n * 3 + xx] = acc;
            } else {
                outp[n * 6 + k * 3 + xx] = acc;
            }
        }
        __syncthreads();
    }
}

// ---------------- launch ----------------
extern "C" void kernel_launch(void* const* d_in, const int* in_sizes, int n_in,
                              void* d_out, int out_size) {
    const float* x        = (const float*)d_in[0];
    const int*   attr     = (const int*)d_in[2];
    const int*   esrc     = (const int*)d_in[3];
    const int*   edst     = (const int*)d_in[4];
    const float* emb      = (const float*)d_in[5];
    const float* uplift   = (const float*)d_in[6];
    const float* h        = (const float*)d_in[7];
    const float* mix      = (const float*)d_in[8];
    const float* rW1      = (const float*)d_in[9];
    const float* rb1      = (const float*)d_in[10];
    const float* rW2      = (const float*)d_in[11];
    const float* lin1s    = (const float*)d_in[12];
    const float* lin1v    = (const float*)d_in[13];
    const float* lin2s    = (const float*)d_in[14];
    const float* lin2v    = (const float*)d_in[15];
    const float* scs      = (const float*)d_in[16];
    const float* scv      = (const float*)d_in[17];
    const float* sis      = (const float*)d_in[18];
    const float* siv      = (const float*)d_in[19];
    float* out = (float*)d_out;

    cudaFuncSetAttribute(k_post, cudaFuncAttributeMaxDynamicSharedMemorySize, 84 * 1024);

    // launch index 3 (the ncu-profiled slot) = layer-0 k_post
    k_init<<<7400, 256>>>(x, uplift, emb, scs, scv);            // 0 (init + B precompute)
    k_pre<<<NN / 8, 256>>>(lin1s, lin1v, 0, 0);                 // 1
    k_edge<<<2048, 256>>>(esrc, edst, rW1, rb1, rW2, 0);        // 2
    k_post<<<NN / 32, 256, 81920>>>(lin2s, lin2v, sis, siv, attr, h, mix, 0, 0, out);  // 3 <- profiled
    k_zero<<<1024, 256>>>();                                    // 4
    k_pre<<<NN / 8, 256>>>(lin1s, lin1v, 1, 1);                 // 5
    k_edge<<<2048, 256>>>(esrc, edst, rW1, rb1, rW2, 1);        // 6
    k_post<<<NN / 32, 256, 81920>>>(lin2s, lin2v, sis, siv, attr, h, mix, 1, 1, out);  // 7
}

// round 5
// speedup vs baseline: 1.4392x; 1.0436x over previous
#include <cuda_runtime.h>
#include <math.h>

#define NN 20000
#define NE 640000
#define NL 2
#define MAXR 2.5f
#define INV_NN 0.17677669529663687f   // 1/sqrt(32)

// ---------------- scratch (device globals; no allocs) ----------------
static __device__ float g_Q[64 * 2];
static __device__ float g_ys[2][NN * 64];
static __device__ float g_yv[2][NN * 192];
static __device__ float g_s1[NN * 64];
static __device__ float g_v1[NN * 192];          // [n][3][64] x-major
static __device__ float g_agg[NN * 256];         // (n, c, 4): vx,vy,vz,s
static __device__ float g_pos[NN * 3];
static __device__ float g_Bs[NL * 100 * 64 * 128];
static __device__ float g_Bv[NL * 100 * 64 * 64];
// edge sort (by dst)
static __device__ int g_ecnt[NN];
static __device__ int g_eoff[NN];
static __device__ int g_eppos[NN];
static __device__ int g_ssrc[NE];
static __device__ int g_sdst[NE];
// node sort (by attr)
static __device__ int g_ncnt[128];
static __device__ int g_noff[128];
static __device__ int g_nppos[128];
static __device__ int g_nidx[NN];

// ---- fused init: Q + y init + layer0 v1 + B precompute + counter zero ----
__global__ void __launch_bounds__(256) k_init(const float* __restrict__ x,
                                              const float* __restrict__ M,
                                              const float* __restrict__ emb,
                                              const float* __restrict__ scs,
                                              const float* __restrict__ scv,
                                              const float* __restrict__ lin1v) {
    int tid = threadIdx.x;
    if (blockIdx.x < 5000) {
        __shared__ float sQ[128];
        __shared__ float sR[128];   // R[k][d] = sum_c Q[c,k]*lin1v0[c,d]
        if (tid == 0) {
            double a = 0, b = 0, c = 0;
            for (int i = 0; i < 64; i++) {
                double m0 = M[2 * i], m1 = M[2 * i + 1];
                a += m0 * m0; b += m0 * m1; c += m1 * m1;
            }
            double det = a * c - b * b;
            double s = sqrt(det);
            double t = a + c;
            double denom = sqrt(t + 2.0 * s);
            double p00 = (a + s) / denom, p01 = b / denom, p11 = (c + s) / denom;
            double pdet = p00 * p11 - p01 * p01;
            double i00 = p11 / pdet, i01 = -p01 / pdet, i11 = p00 / pdet;
            for (int i = 0; i < 64; i++) {
                double m0 = M[2 * i], m1 = M[2 * i + 1];
                sQ[2 * i]     = (float)(m0 * i00 + m1 * i01);
                sQ[2 * i + 1] = (float)(m0 * i01 + m1 * i11);
            }
            if (blockIdx.x == 0)
                for (int i = 0; i < 128; i++) g_Q[i] = sQ[i];
        }
        __syncthreads();
        if (tid < 128) {
            int k = tid >> 6, d = tid & 63;
            float acc = 0.f;
#pragma unroll 8
            for (int c = 0; c < 64; c++) acc += sQ[c * 2 + k] * lin1v[c * 64 + d];
            sR[k * 64 + d] = acc;
        }
        __syncthreads();
        int i = blockIdx.x * 256 + tid;
        if (i >= NN * 64) return;
        int n = i >> 6, c = i & 63;
        float q0 = sQ[c * 2], q1 = sQ[c * 2 + 1];
        const float* xp = x + n * 6;
        float v0 = xp[0] * q0 + xp[3] * q1;
        float v1 = xp[1] * q0 + xp[4] * q1;
        float v2 = xp[2] * q0 + xp[5] * q1;
        int base = n * 192 + c * 3;
        g_yv[0][base + 0] = v0; g_yv[0][base + 1] = v1; g_yv[0][base + 2] = v2;
        g_yv[1][base + 0] = v0; g_yv[1][base + 1] = v1; g_yv[1][base + 2] = v2;
        g_ys[0][i] = 0.f; g_ys[1][i] = 0.f;
        if (c < 3) g_pos[n * 3 + c] = xp[c];
        reinterpret_cast<float4*>(g_agg)[i] = make_float4(0.f, 0.f, 0.f, 0.f);
        // layer-0 v1 (s1 is identically zero, skipped)
        int d = c;
        float r0 = sR[d], r1 = sR[64 + d];
#pragma unroll
        for (int xx = 0; xx < 3; xx++)
            g_v1[n * 192 + xx * 64 + d] = xp[xx] * r0 + xp[3 + xx] * r1;
    } else if (blockIdx.x < 7400) {
        const int TOTS = NL * 100 * 64 * 128;
        const int TOTV = NL * 100 * 64 * 64;
        const int NB = 2400;
        for (int idx = (blockIdx.x - 5000) * 256 + tid; idx < TOTS + TOTV;
             idx += NB * 256) {
            if (idx < TOTS) {
                int o = idx & 127;
                int c = (idx >> 7) & 63;
                int a = (idx >> 13) % 100;
                int l = idx / (128 * 64 * 100);
                const float* w = scs + ((size_t)(l * 64 + c) * 32) * 128 + o;
                const float* em = emb + a * 32;
                float acc = 0.f;
#pragma unroll 8
                for (int e = 0; e < 32; e++) acc += em[e] * w[e * 128];
                g_Bs[idx] = acc;
            } else {
                int j = idx - TOTS;
                int o = j & 63;
                int c = (j >> 6) & 63;
                int a = (j >> 12) % 100;
                int l = j / (64 * 64 * 100);
                const float* w = scv + ((size_t)(l * 64 + c) * 32) * 64 + o;
                const float* em = emb + a * 32;
                float acc = 0.f;
#pragma unroll 8
                for (int e = 0; e < 32; e++) acc += em[e] * w[e * 64];
                g_Bv[j] = acc;
            }
        }
    } else {
        int i = (blockIdx.x - 7400) * 256 + tid;
        if (i < NN) { g_ecnt[i] = 0; g_eppos[i] = 0; }
        if (i < 128) { g_ncnt[i] = 0; g_nppos[i] = 0; }
    }
}

// ---------------- hist: edges (blocks 0..1279) + nodes (1280..1359) --------
__global__ void k_hist(const int* __restrict__ edst, const int* __restrict__ attr) {
    int tid = threadIdx.x;
    if (blockIdx.x < 1280) {
        for (int e = blockIdx.x * 256 + tid; e < NE; e += 1280 * 256)
            atomicAdd(&g_ecnt[edst[e]], 1);
    } else {
        int n = (blockIdx.x - 1280) * 256 + tid;
        if (n < NN) atomicAdd(&g_ncnt[attr[n]], 1);
    }
}

// ---------------- scan: block 0 edges, block 1 nodes ----------------
__global__ void __launch_bounds__(512) k_scan() {
    __shared__ int sp[512];
    int t = threadIdx.x;
    if (blockIdx.x == 0) {
        const int CH = 40;
        int base = t * CH;
        int part = 0;
        for (int i = 0; i < CH; i++) {
            int idx = base + i;
            if (idx < NN) part += g_ecnt[idx];
        }
        sp[t] = part;
        __syncthreads();
        for (int off = 1; off < 512; off <<= 1) {
            int v = (t >= off) ? sp[t - off] : 0;
            __syncthreads();
            sp[t] += v;
            __syncthreads();
        }
        int run = sp[t] - part;
        for (int i = 0; i < CH; i++) {
            int idx = base + i;
            if (idx < NN) { g_eoff[idx] = run; run += g_ecnt[idx]; }
        }
    } else {
        int part = (t < 100) ? g_ncnt[t] : 0;
        sp[t] = part;
        __syncthreads();
        for (int off = 1; off < 128; off <<= 1) {
            int v = (t >= off && t < 128) ? sp[t - off] : 0;
            __syncthreads();
            if (t < 128) sp[t] += v;
            __syncthreads();
        }
        if (t < 100) g_noff[t] = sp[t] - part;
    }
}

// ---------------- scatter: edges + nodes ----------------
__global__ void k_scat(const int* __restrict__ esrc, const int* __restrict__ edst,
                       const int* __restrict__ attr) {
    int tid = threadIdx.x;
    if (blockIdx.x < 1280) {
        for (int e = blockIdx.x * 256 + tid; e < NE; e += 1280 * 256) {
            int d = edst[e];
            int p = g_eoff[d] + atomicAdd(&g_eppos[d], 1);
            g_ssrc[p] = esrc[e];
            g_sdst[p] = d;
        }
    } else {
        int n = (blockIdx.x - 1280) * 256 + tid;
        if (n < NN) {
            int a = attr[n];
            int p = g_noff[a] + atomicAdd(&g_nppos[a], 1);
            g_nidx[p] = n;
        }
    }
}

// ---------------- zero aggregation buffer (between layers) ----------------
__global__ void k_zero() {
    float4 z = make_float4(0.f, 0.f, 0.f, 0.f);
    float4* p = reinterpret_cast<float4*>(g_agg);
    for (int i = blockIdx.x * blockDim.x + threadIdx.x; i < NN * 64;
         i += gridDim.x * blockDim.x)
        p[i] = z;
}

// ---------------- pre (layer 1 only) ----------------
__global__ void __launch_bounds__(256) k_pre(const float* __restrict__ lin1s,
                                             const float* __restrict__ lin1v,
                                             int layer, int cur) {
    __shared__ float sWs[4096], sWv[4096];
    __shared__ float sy[8][256];
    int tid = threadIdx.x;
    const float* Ws = lin1s + layer * 4096;
    const float* Wv = lin1v + layer * 4096;
    for (int k = tid; k < 4096; k += 256) { sWs[k] = Ws[k]; sWv[k] = Wv[k]; }
    const float* ys = g_ys[cur];
    const float* yv = g_yv[cur];
    int n0 = blockIdx.x * 8;
    for (int k = tid; k < 2048; k += 256) {
        int nn = k >> 8, j = k & 255;
        int n = n0 + nn;
        sy[nn][j] = (j < 64) ? ys[n * 64 + j] : yv[n * 192 + j - 64];
    }
    __syncthreads();
    for (int nn = 0; nn < 8; nn++) {
        int n = n0 + nn;
        if (tid < 64) {
            int d = tid;
            float acc = 0.f;
#pragma unroll 8
            for (int c = 0; c < 64; c++) acc += sy[nn][c] * sWs[c * 64 + d];
            g_s1[n * 64 + d] = acc;
        } else {
            int idx = tid - 64;
            int d = idx & 63, xx = idx >> 6;
            float acc = 0.f;
#pragma unroll 8
            for (int c = 0; c < 64; c++) acc += sy[nn][64 + c * 3 + xx] * sWv[c * 64 + d];
            g_v1[n * 192 + xx * 64 + d] = acc;   // x-major
        }
    }
}

// -------- edge kernel: dst-sorted, register accumulation, K=40/warp --------
__global__ void __launch_bounds__(256) k_edge(const float* __restrict__ rW1,
                                              const float* __restrict__ rb1,
                                              const float* __restrict__ rW2,
                                              int layer, int skip_s1) {
    __shared__ float sW1[256];
    __shared__ float sb1v[32];
    __shared__ float sW2t[4096];   // [k][lane][4] interleaved
    int tid = threadIdx.x;
    for (int k = tid; k < 256; k += 256) sW1[k] = rW1[layer * 256 + k];
    if (tid < 32) sb1v[tid] = rb1[layer * 32 + tid];
    for (int t = tid; t < 4096; t += 256) {
        int k = t >> 7, r = t & 127, ln = r >> 2, g = r & 3;
        sW2t[t] = rW2[layer * 4096 + k * 128 + g * 32 + ln];
    }
    __syncthreads();
    int lane = tid & 31;
    int warp = (blockIdx.x * 256 + tid) >> 5;
    const int K = 40;
    int e0 = warp * K;
    if (e0 >= NE) return;
    int e1 = e0 + K; if (e1 > NE) e1 = NE;
    float4 acc0 = make_float4(0.f, 0.f, 0.f, 0.f);
    float4 acc1 = make_float4(0.f, 0.f, 0.f, 0.f);
    bool touched = false;
    int cur = -1;
    float dp0 = 0.f, dp1 = 0.f, dp2 = 0.f;
    const float PI = 3.14159265358979f;
    for (int e = e0; e < e1; e++) {
        int dst = g_sdst[e];
        if (dst != cur) {
            if (touched) {
                float4* ap = reinterpret_cast<float4*>(g_agg + (size_t)cur * 256);
                atomicAdd(ap + lane, acc0);
                atomicAdd(ap + lane + 32, acc1);
                acc0 = make_float4(0.f, 0.f, 0.f, 0.f);
                acc1 = make_float4(0.f, 0.f, 0.f, 0.f);
                touched = false;
            }
            cur = dst;
            dp0 = g_pos[dst * 3 + 0];
            dp1 = g_pos[dst * 3 + 1];
            dp2 = g_pos[dst * 3 + 2];
        }
        int src = g_ssrc[e];
        float ev0 = g_pos[src * 3 + 0] - dp0;
        float ev1 = g_pos[src * 3 + 1] - dp1;
        float ev2 = g_pos[src * 3 + 2] - dp2;
        float l2 = ev0 * ev0 + ev1 * ev1 + ev2 * ev2;
        if (l2 >= MAXR * MAXR) continue;
        float elen = sqrtf(l2);
        float safe = fmaxf(elen, 1e-9f);
        float inv = 1.0f / safe;
        float u = 2.f * (elen * (1.0f / MAXR) - 1.f);
        float cut = 0.5f * (1.f - __cosf(PI * u));
        float ca = cut * 1.7320508075688772f * inv;
        float ea0 = ca * ev0, ea1 = ca * ev1, ea2 = ca * ev2;
        float th = (PI / MAXR) * safe;
        float sk = __sinf(th), c2 = 2.f * __cosf(th), skm1 = 0.f;
        float fac = 2.5298221281347035f * inv;
        float hs = sb1v[lane];
#pragma unroll
        for (int k = 0; k < 8; k++) {
            hs += (fac * sk) * sW1[k * 32 + lane];
            float t = c2 * sk - skm1; skm1 = sk; sk = t;
        }
        float hval = hs / (1.f + __expf(-hs));  // silu
        float w0 = 0.f, w1 = 0.f, w2 = 0.f, w3 = 0.f;
#pragma unroll
        for (int k = 0; k < 32; k++) {
            float hk = __shfl_sync(0xffffffffu, hval, k);
            float4 wv = *reinterpret_cast<const float4*>(&sW2t[k * 128 + lane * 4]);
            w0 = fmaf(hk, wv.x, w0);
            w1 = fmaf(hk, wv.y, w1);
            w2 = fmaf(hk, wv.z, w2);
            w3 = fmaf(hk, wv.w, w3);
        }
        float sa = 0.f, sb = 0.f;
        if (!skip_s1) {
            const float* s1p = g_s1 + (size_t)src * 64;
            sa = s1p[lane] * w0;
            sb = s1p[lane + 32] * w1;
        }
        const float* v1p = g_v1 + (size_t)src * 192;  // [3][64]
        float da = w2 * (v1p[lane] * ea0 + v1p[64 + lane] * ea1 + v1p[128 + lane] * ea2);
        float db = w3 * (v1p[lane + 32] * ea0 + v1p[96 + lane] * ea1 + v1p[160 + lane] * ea2);
        acc0.x += sa * ea0; acc0.y += sa * ea1; acc0.z += sa * ea2; acc0.w += da;
        acc1.x += sb * ea0; acc1.y += sb * ea1; acc1.z += sb * ea2; acc1.w += db;
        touched = true;
    }
    if (touched) {
        float4* ap = reinterpret_cast<float4*>(g_agg + (size_t)cur * 256);
        atomicAdd(ap + lane, acc0);
        atomicAdd(ap + lane + 32, acc1);
    }
}

// ------ post v3: attr-sorted nodes (Bs/Bv L1-hot), 32 nodes/block ------
__global__ void __launch_bounds__(256) k_post(const float* __restrict__ lin2s,
                                              const float* __restrict__ lin2v,
                                              const float* __restrict__ sis,
                                              const float* __restrict__ siv,
                                              const int* __restrict__ attr,
                                              const float* __restrict__ hv,
                                              const float* __restrict__ mv,
                                              int layer, int cur,
                                              float* __restrict__ outp) {
    extern __shared__ float sw[];
    float* sL2s = sw;            // 8192
    float* sL2v = sw + 8192;     // 4096
    float* sSs  = sw + 12288;    // 4096
    float* sSv  = sw + 16384;    // 4096
    __shared__ float s_Q[128];
    __shared__ float s_ys[2][64], s_aggs[2][64];
    __shared__ float s_yv[2][192], s_aggv[2][192];
    __shared__ float s_outs[2][128], s_outv[2][192];
    __shared__ float s_y2s[2][64], s_y2v[2][192];
    __shared__ float s_newv[2][192];
    int tid = threadIdx.x;
    int half = tid >> 7, ltid = tid & 127;
    const float* L2s = lin2s + layer * 8192;
    const float* L2v = lin2v + layer * 4096;
    const float* Ss = sis + layer * 4096;
    const float* Sv = siv + layer * 4096;
    for (int k = tid; k < 8192; k += 256) sL2s[k] = L2s[k];
    for (int k = tid; k < 4096; k += 256) { sL2v[k] = L2v[k]; sSs[k] = Ss[k]; sSv[k] = Sv[k]; }
    if (tid < 128) s_Q[tid] = g_Q[tid];
    float hh = hv[layer] * hv[layer];
    float m = mv[layer];
    float* ys_new = g_ys[cur ^ 1];
    float* yv_new = g_yv[cur ^ 1];
    const float* ys_cur = g_ys[cur];
    const float* yv_cur = g_yv[cur];
    __syncthreads();
    int n0 = blockIdx.x * 32;
    for (int nn = 0; nn < 16; nn++) {
        int n = g_nidx[n0 + nn * 2 + half];   // attr-sorted
        if (ltid < 64) {
            s_ys[half][ltid] = ys_cur[n * 64 + ltid];
            s_aggs[half][ltid] = g_agg[n * 256 + ltid * 4 + 3] * INV_NN;
        }
        for (int j = ltid; j < 192; j += 128) {
            int c = j / 3, xx = j - 3 * c;
            s_yv[half][j] = yv_cur[n * 192 + j];
            s_aggv[half][j] = g_agg[n * 256 + c * 4 + xx] * INV_NN;
        }
        __syncthreads();
        int a = attr[n];
        const float* Bs = g_Bs + (size_t)(layer * 100 + a) * 8192;
        const float* Bv = g_Bv + (size_t)(layer * 100 + a) * 4096;
        {
            float acc = 0.f;
#pragma unroll 16
            for (int c = 0; c < 64; c++)
                acc += s_aggs[half][c] * sL2s[c * 128 + ltid] + s_ys[half][c] * Bs[c * 128 + ltid];
            s_outs[half][ltid] = acc;
        }
        if (ltid < 64) {
            int d = ltid;
            float a0 = 0.f, a1 = 0.f, a2 = 0.f;
#pragma unroll 16
            for (int c = 0; c < 64; c++) {
                float w = sL2v[c * 64 + d], bw = Bv[c * 64 + d];
                a0 += s_aggv[half][c * 3 + 0] * w + s_yv[half][c * 3 + 0] * bw;
                a1 += s_aggv[half][c * 3 + 1] * w + s_yv[half][c * 3 + 1] * bw;
                a2 += s_aggv[half][c * 3 + 2] * w + s_yv[half][c * 3 + 2] * bw;
            }
            s_outv[half][d * 3 + 0] = a0; s_outv[half][d * 3 + 1] = a1; s_outv[half][d * 3 + 2] = a2;
        } else {
            int d = ltid - 64;
            float y2 = 0.f, b0 = 0.f, b1 = 0.f, b2 = 0.f;
#pragma unroll 16
            for (int c = 0; c < 64; c++) {
                float wsv = sSv[c * 64 + d];
                y2 += s_ys[half][c] * sSs[c * 64 + d];
                b0 += s_yv[half][c * 3 + 0] * wsv;
                b1 += s_yv[half][c * 3 + 1] * wsv;
                b2 += s_yv[half][c * 3 + 2] * wsv;
            }
            s_y2s[half][d] = y2;
            s_y2v[half][d * 3 + 0] = b0; s_y2v[half][d * 3 + 1] = b1; s_y2v[half][d * 3 + 2] = b2;
        }
        __syncthreads();
        if (ltid < 64) {
            int c = ltid;
            float os = s_outs[half][c];
            float gs = os / (1.f + __expf(-os));
            float gate = 1.f / (1.f + __expf(-s_outs[half][64 + c]));
            float yo = ys_new[n * 64 + c];
            float ns = 2.f * s_ys[half][c] - yo + hh * (m * gs + (m - 1.f) * s_y2s[half][c]);
            ys_new[n * 64 + c] = ns;
#pragma unroll
            for (int xx = 0; xx < 3; xx++) {
                float yov = yv_new[n * 192 + c * 3 + xx];
                float nv = 2.f * s_yv[half][c * 3 + xx] - yov +
                           hh * (m * gate * s_outv[half][c * 3 + xx] + (m - 1.f) * s_y2v[half][c * 3 + xx]);
                yv_new[n * 192 + c * 3 + xx] = nv;
                s_newv[half][c * 3 + xx] = nv;
            }
        }
        __syncthreads();
        if (ltid < 6) {
            int k = ltid / 3, xx = ltid - 3 * k;
            float acc = 0.f;
#pragma unroll 16
            for (int c = 0; c < 64; c++) acc += s_newv[half][c * 3 + xx] * s_Q[c * 2 + k];
            if (layer == 0) {
                if (k == 0) g_pos[n * 3 + xx] = acc;
            } else {
                outp[n * 6 + k * 3 + xx] = acc;
            }
        }
        __syncthreads();
    }
}

// ---------------- launch ----------------
extern "C" void kernel_launch(void* const* d_in, const int* in_sizes, int n_in,
                              void* d_out, int out_size) {
    const float* x        = (const float*)d_in[0];
    const int*   attr     = (const int*)d_in[2];
    const int*   esrc     = (const int*)d_in[3];
    const int*   edst     = (const int*)d_in[4];
    const float* emb      = (const float*)d_in[5];
    const float* uplift   = (const float*)d_in[6];
    const float* h        = (const float*)d_in[7];
    const float* mix      = (const float*)d_in[8];
    const float* rW1      = (const float*)d_in[9];
    const float* rb1      = (const float*)d_in[10];
    const float* rW2      = (const float*)d_in[11];
    const float* lin1s    = (const float*)d_in[12];
    const float* lin1v    = (const float*)d_in[13];
    const float* lin2s    = (const float*)d_in[14];
    const float* lin2v    = (const float*)d_in[15];
    const float* scs      = (const float*)d_in[16];
    const float* scv      = (const float*)d_in[17];
    const float* sis      = (const float*)d_in[18];
    const float* siv      = (const float*)d_in[19];
    float* out = (float*)d_out;

    cudaFuncSetAttribute(k_post, cudaFuncAttributeMaxDynamicSharedMemorySize, 84 * 1024);

    k_init<<<7500, 256>>>(x, uplift, emb, scs, scv, lin1v);      // 0
    k_hist<<<1360, 256>>>(edst, attr);                           // 1
    k_scan<<<2, 512>>>();                                        // 2
    k_scat<<<1360, 256>>>(esrc, edst, attr);                     // 3 <- profiled
    k_edge<<<2000, 256>>>(rW1, rb1, rW2, 0, 1);                  // 4 (layer0, s1==0)
    k_post<<<NN / 32, 256, 81920>>>(lin2s, lin2v, sis, siv, attr, h, mix, 0, 0, out);  // 5
    k_zero<<<1024, 256>>>();                                     // 6
    k_pre<<<NN / 8, 256>>>(lin1s, lin1v, 1, 1);                  // 7
    k_edge<<<2000, 256>>>(rW1, rb1, rW2, 1, 0);                  // 8
    k_post<<<NN / 32, 256, 81920>>>(lin2s, lin2v, sis, siv, attr, h, mix, 1, 1, out);  // 9
}

// round 6
// speedup vs baseline: 1.7289x; 1.2013x over previous
#include <cuda_runtime.h>
#include <math.h>

#define NN 20000
#define NE 640000
#define NL 2
#define MAXR 2.5f
#define INV_NN 0.17677669529663687f   // 1/sqrt(32)

// ---------------- scratch (device globals; no allocs) ----------------
static __device__ float g_Q[64 * 2];
static __device__ float g_ys[2][NN * 64];
static __device__ float g_yv[2][NN * 192];
static __device__ float g_s1[NN * 64];
static __device__ float g_v1[NN * 192];          // [n][3][64] x-major
static __device__ float g_agg[NN * 256];         // (n, c, 4): vx,vy,vz,s
static __device__ float g_pos[NN * 3];
static __device__ float g_Bs[NL * 100 * 64 * 128];
static __device__ float g_Bv[NL * 100 * 64 * 64];
// edge sort (by dst)
static __device__ int g_ecnt[NN];
static __device__ int g_eoff[NN];
static __device__ int g_eppos[NN];
static __device__ int g_ssrc[NE];
static __device__ int g_sdst[NE];
// node sort (by attr)
static __device__ int g_nidx[NN];
static __device__ int g_nattr[NN];

// ---- fused init: Q + y init + layer0 v1 + B precompute + cnt zero + node sort ----
__global__ void __launch_bounds__(256) k_init(const float* __restrict__ x,
                                              const float* __restrict__ M,
                                              const float* __restrict__ emb,
                                              const float* __restrict__ scs,
                                              const float* __restrict__ scv,
                                              const float* __restrict__ lin1v,
                                              const int* __restrict__ attr) {
    int tid = threadIdx.x;
    if (blockIdx.x < 5000) {
        __shared__ float sQ[128];
        __shared__ float sR[128];   // R[k][d] = sum_c Q[c,k]*lin1v0[c,d]
        if (tid == 0) {
            double a = 0, b = 0, c = 0;
            for (int i = 0; i < 64; i++) {
                double m0 = M[2 * i], m1 = M[2 * i + 1];
                a += m0 * m0; b += m0 * m1; c += m1 * m1;
            }
            double det = a * c - b * b;
            double s = sqrt(det);
            double t = a + c;
            double denom = sqrt(t + 2.0 * s);
            double p00 = (a + s) / denom, p01 = b / denom, p11 = (c + s) / denom;
            double pdet = p00 * p11 - p01 * p01;
            double i00 = p11 / pdet, i01 = -p01 / pdet, i11 = p00 / pdet;
            for (int i = 0; i < 64; i++) {
                double m0 = M[2 * i], m1 = M[2 * i + 1];
                sQ[2 * i]     = (float)(m0 * i00 + m1 * i01);
                sQ[2 * i + 1] = (float)(m0 * i01 + m1 * i11);
            }
            if (blockIdx.x == 0)
                for (int i = 0; i < 128; i++) g_Q[i] = sQ[i];
        }
        __syncthreads();
        if (tid < 128) {
            int k = tid >> 6, d = tid & 63;
            float acc = 0.f;
#pragma unroll 8
            for (int c = 0; c < 64; c++) acc += sQ[c * 2 + k] * lin1v[c * 64 + d];
            sR[k * 64 + d] = acc;
        }
        __syncthreads();
        int i = blockIdx.x * 256 + tid;
        if (i >= NN * 64) return;
        int n = i >> 6, c = i & 63;
        float q0 = sQ[c * 2], q1 = sQ[c * 2 + 1];
        const float* xp = x + n * 6;
        float v0 = xp[0] * q0 + xp[3] * q1;
        float v1 = xp[1] * q0 + xp[4] * q1;
        float v2 = xp[2] * q0 + xp[5] * q1;
        int base = n * 192 + c * 3;
        g_yv[0][base + 0] = v0; g_yv[0][base + 1] = v1; g_yv[0][base + 2] = v2;
        g_yv[1][base + 0] = v0; g_yv[1][base + 1] = v1; g_yv[1][base + 2] = v2;
        g_ys[0][i] = 0.f; g_ys[1][i] = 0.f;
        if (c < 3) g_pos[n * 3 + c] = xp[c];
        reinterpret_cast<float4*>(g_agg)[i] = make_float4(0.f, 0.f, 0.f, 0.f);
        // layer-0 v1 (s1 is identically zero at layer 0)
        int d = c;
        float r0 = sR[d], r1 = sR[64 + d];
#pragma unroll
        for (int xx = 0; xx < 3; xx++)
            g_v1[n * 192 + xx * 64 + d] = xp[xx] * r0 + xp[3 + xx] * r1;
    } else if (blockIdx.x < 7400) {
        const int TOTS = NL * 100 * 64 * 128;
        const int TOTV = NL * 100 * 64 * 64;
        const int NB = 2400;
        for (int idx = (blockIdx.x - 5000) * 256 + tid; idx < TOTS + TOTV;
             idx += NB * 256) {
            if (idx < TOTS) {
                int o = idx & 127;
                int c = (idx >> 7) & 63;
                int a = (idx >> 13) % 100;
                int l = idx / (128 * 64 * 100);
                const float* w = scs + ((size_t)(l * 64 + c) * 32) * 128 + o;
                const float* em = emb + a * 32;
                float acc = 0.f;
#pragma unroll 8
                for (int e = 0; e < 32; e++) acc += em[e] * w[e * 128];
                g_Bs[idx] = acc;
            } else {
                int j = idx - TOTS;
                int o = j & 63;
                int c = (j >> 6) & 63;
                int a = (j >> 12) % 100;
                int l = j / (64 * 64 * 100);
                const float* w = scv + ((size_t)(l * 64 + c) * 32) * 64 + o;
                const float* em = emb + a * 32;
                float acc = 0.f;
#pragma unroll 8
                for (int e = 0; e < 32; e++) acc += em[e] * w[e * 64];
                g_Bv[j] = acc;
            }
        }
    } else if (blockIdx.x < 7479) {
        int i = (blockIdx.x - 7400) * 256 + tid;
        if (i < NN) { g_ecnt[i] = 0; g_eppos[i] = 0; }
    } else {
        // single-block node counting sort by attr
        __shared__ int scnt[128], soff[128], spos[128];
        if (tid < 128) { scnt[tid] = 0; spos[tid] = 0; }
        __syncthreads();
        for (int n = tid; n < NN; n += 256) atomicAdd(&scnt[attr[n]], 1);
        __syncthreads();
        if (tid < 128) {
            int part = scnt[tid];
            soff[tid] = part;
        }
        __syncthreads();
        for (int off = 1; off < 128; off <<= 1) {
            int v = 0;
            if (tid < 128 && tid >= off) v = soff[tid - off];
            __syncthreads();
            if (tid < 128) soff[tid] += v;
            __syncthreads();
        }
        if (tid < 128) soff[tid] -= scnt[tid];  // exclusive
        __syncthreads();
        for (int n = tid; n < NN; n += 256) {
            int a = attr[n];
            int p = soff[a] + atomicAdd(&spos[a], 1);
            g_nidx[p] = n;
            g_nattr[p] = a;
        }
    }
}

// ---------------- edge histogram (dst) ----------------
__global__ void k_hist_e(const int* __restrict__ edst) {
    for (int e = blockIdx.x * 256 + threadIdx.x; e < NE; e += 1280 * 256)
        atomicAdd(&g_ecnt[edst[e]], 1);
}

// ---------------- edge offset scan (one block) ----------------
__global__ void __launch_bounds__(512) k_scan_e() {
    __shared__ int sp[512];
    int t = threadIdx.x;
    const int CH = 40;
    int base = t * CH;
    int part = 0;
    for (int i = 0; i < CH; i++) {
        int idx = base + i;
        if (idx < NN) part += g_ecnt[idx];
    }
    sp[t] = part;
    __syncthreads();
    for (int off = 1; off < 512; off <<= 1) {
        int v = (t >= off) ? sp[t - off] : 0;
        __syncthreads();
        sp[t] += v;
        __syncthreads();
    }
    int run = sp[t] - part;
    for (int i = 0; i < CH; i++) {
        int idx = base + i;
        if (idx < NN) { g_eoff[idx] = run; run += g_ecnt[idx]; }
    }
}

// ---------------- edge scatter ----------------
__global__ void k_scat_e(const int* __restrict__ esrc, const int* __restrict__ edst) {
    for (int e = blockIdx.x * 256 + threadIdx.x; e < NE; e += 1280 * 256) {
        int d = edst[e];
        int p = g_eoff[d] + atomicAdd(&g_eppos[d], 1);
        g_ssrc[p] = esrc[e];
        g_sdst[p] = d;
    }
}

// ---------------- zero aggregation buffer (between layers) ----------------
__global__ void k_zero() {
    float4 z = make_float4(0.f, 0.f, 0.f, 0.f);
    float4* p = reinterpret_cast<float4*>(g_agg);
    for (int i = blockIdx.x * blockDim.x + threadIdx.x; i < NN * 64;
         i += gridDim.x * blockDim.x)
        p[i] = z;
}

// ---------------- pre (layer 1 only) ----------------
__global__ void __launch_bounds__(256) k_pre(const float* __restrict__ lin1s,
                                             const float* __restrict__ lin1v,
                                             int layer, int cur) {
    __shared__ float sWs[4096], sWv[4096];
    __shared__ float sy[8][256];
    int tid = threadIdx.x;
    const float* Ws = lin1s + layer * 4096;
    const float* Wv = lin1v + layer * 4096;
    for (int k = tid; k < 4096; k += 256) { sWs[k] = Ws[k]; sWv[k] = Wv[k]; }
    const float* ys = g_ys[cur];
    const float* yv = g_yv[cur];
    int n0 = blockIdx.x * 8;
    for (int k = tid; k < 2048; k += 256) {
        int nn = k >> 8, j = k & 255;
        int n = n0 + nn;
        sy[nn][j] = (j < 64) ? ys[n * 64 + j] : yv[n * 192 + j - 64];
    }
    __syncthreads();
    for (int nn = 0; nn < 8; nn++) {
        int n = n0 + nn;
        if (tid < 64) {
            int d = tid;
            float acc = 0.f;
#pragma unroll 8
            for (int c = 0; c < 64; c++) acc += sy[nn][c] * sWs[c * 64 + d];
            g_s1[n * 64 + d] = acc;
        } else {
            int idx = tid - 64;
            int d = idx & 63, xx = idx >> 6;
            float acc = 0.f;
#pragma unroll 8
            for (int c = 0; c < 64; c++) acc += sy[nn][64 + c * 3 + xx] * sWv[c * 64 + d];
            g_v1[n * 192 + xx * 64 + d] = acc;   // x-major
        }
    }
}

// -------- edge math common --------
__device__ __forceinline__ void edge_core(float ev0, float ev1, float ev2, float l2,
                                          const float* sW1, const float* sb1v,
                                          const float* sW2t, int lane,
                                          float& ea0, float& ea1, float& ea2,
                                          float& w0, float& w1, float& w2, float& w3) {
    const float PI = 3.14159265358979f;
    float elen = sqrtf(l2);
    float safe = fmaxf(elen, 1e-9f);
    float inv = 1.0f / safe;
    float u = 2.f * (elen * (1.0f / MAXR) - 1.f);
    float cut = 0.5f * (1.f - __cosf(PI * u));
    float ca = cut * 1.7320508075688772f * inv;
    ea0 = ca * ev0; ea1 = ca * ev1; ea2 = ca * ev2;
    float th = (PI / MAXR) * safe;
    float sk = __sinf(th), c2 = 2.f * __cosf(th), skm1 = 0.f;
    float fac = 2.5298221281347035f * inv;
    float hs = sb1v[lane];
#pragma unroll
    for (int k = 0; k < 8; k++) {
        hs += (fac * sk) * sW1[k * 32 + lane];
        float t = c2 * sk - skm1; skm1 = sk; sk = t;
    }
    float hval = hs / (1.f + __expf(-hs));  // silu
    w0 = 0.f; w1 = 0.f; w2 = 0.f; w3 = 0.f;
#pragma unroll
    for (int k = 0; k < 32; k++) {
        float hk = __shfl_sync(0xffffffffu, hval, k);
        float4 wv = *reinterpret_cast<const float4*>(&sW2t[k * 128 + lane * 4]);
        w0 = fmaf(hk, wv.x, w0);
        w1 = fmaf(hk, wv.y, w1);
        w2 = fmaf(hk, wv.z, w2);
        w3 = fmaf(hk, wv.w, w3);
    }
}

// -------- layer-0 edge: unsorted, s1==0 --------
__global__ void __launch_bounds__(256) k_edge_u(const int* __restrict__ esrc,
                                                const int* __restrict__ edst,
                                                const float* __restrict__ rW1,
                                                const float* __restrict__ rb1,
                                                const float* __restrict__ rW2) {
    __shared__ float sW1[256];
    __shared__ float sb1v[32];
    __shared__ float sW2t[4096];
    int tid = threadIdx.x;
    for (int k = tid; k < 256; k += 256) sW1[k] = rW1[k];
    if (tid < 32) sb1v[tid] = rb1[tid];
    for (int t = tid; t < 4096; t += 256) {
        int k = t >> 7, r = t & 127, ln = r >> 2, g = r & 3;
        sW2t[t] = rW2[k * 128 + g * 32 + ln];
    }
    __syncthreads();
    int lane = tid & 31;
    int gwarp = (blockIdx.x * 256 + tid) >> 5;
    int nw = gridDim.x * 8;
    for (int e = gwarp; e < NE; e += nw) {
        int src = esrc[e], dst = edst[e];
        float ev0 = g_pos[src * 3 + 0] - g_pos[dst * 3 + 0];
        float ev1 = g_pos[src * 3 + 1] - g_pos[dst * 3 + 1];
        float ev2 = g_pos[src * 3 + 2] - g_pos[dst * 3 + 2];
        float l2 = ev0 * ev0 + ev1 * ev1 + ev2 * ev2;
        if (l2 >= MAXR * MAXR) continue;
        float ea0, ea1, ea2, w0, w1, w2, w3;
        edge_core(ev0, ev1, ev2, l2, sW1, sb1v, sW2t, lane, ea0, ea1, ea2, w0, w1, w2, w3);
        const float* v1p = g_v1 + (size_t)src * 192;
        float da = w2 * (v1p[lane] * ea0 + v1p[64 + lane] * ea1 + v1p[128 + lane] * ea2);
        float db = w3 * (v1p[lane + 32] * ea0 + v1p[96 + lane] * ea1 + v1p[160 + lane] * ea2);
        float4* ap = reinterpret_cast<float4*>(g_agg + (size_t)dst * 256);
        atomicAdd(ap + lane,      make_float4(0.f, 0.f, 0.f, da));
        atomicAdd(ap + lane + 32, make_float4(0.f, 0.f, 0.f, db));
    }
}

// -------- layer-1 edge: dst-sorted, register accumulation --------
__global__ void __launch_bounds__(256) k_edge(const float* __restrict__ rW1,
                                              const float* __restrict__ rb1,
                                              const float* __restrict__ rW2,
                                              int layer) {
    __shared__ float sW1[256];
    __shared__ float sb1v[32];
    __shared__ float sW2t[4096];
    int tid = threadIdx.x;
    for (int k = tid; k < 256; k += 256) sW1[k] = rW1[layer * 256 + k];
    if (tid < 32) sb1v[tid] = rb1[layer * 32 + tid];
    for (int t = tid; t < 4096; t += 256) {
        int k = t >> 7, r = t & 127, ln = r >> 2, g = r & 3;
        sW2t[t] = rW2[layer * 4096 + k * 128 + g * 32 + ln];
    }
    __syncthreads();
    int lane = tid & 31;
    int warp = (blockIdx.x * 256 + tid) >> 5;
    const int K = 40;
    int e0 = warp * K;
    if (e0 >= NE) return;
    int e1 = e0 + K; if (e1 > NE) e1 = NE;
    float4 acc0 = make_float4(0.f, 0.f, 0.f, 0.f);
    float4 acc1 = make_float4(0.f, 0.f, 0.f, 0.f);
    bool touched = false;
    int cur = -1;
    float dp0 = 0.f, dp1 = 0.f, dp2 = 0.f;
    for (int e = e0; e < e1; e++) {
        int dst = g_sdst[e];
        if (dst != cur) {
            if (touched) {
                float4* ap = reinterpret_cast<float4*>(g_agg + (size_t)cur * 256);
                atomicAdd(ap + lane, acc0);
                atomicAdd(ap + lane + 32, acc1);
                acc0 = make_float4(0.f, 0.f, 0.f, 0.f);
                acc1 = make_float4(0.f, 0.f, 0.f, 0.f);
                touched = false;
            }
            cur = dst;
            dp0 = g_pos[dst * 3 + 0];
            dp1 = g_pos[dst * 3 + 1];
            dp2 = g_pos[dst * 3 + 2];
        }
        int src = g_ssrc[e];
        float ev0 = g_pos[src * 3 + 0] - dp0;
        float ev1 = g_pos[src * 3 + 1] - dp1;
        float ev2 = g_pos[src * 3 + 2] - dp2;
        float l2 = ev0 * ev0 + ev1 * ev1 + ev2 * ev2;
        if (l2 >= MAXR * MAXR) continue;
        float ea0, ea1, ea2, w0, w1, w2, w3;
        edge_core(ev0, ev1, ev2, l2, sW1, sb1v, sW2t, lane, ea0, ea1, ea2, w0, w1, w2, w3);
        const float* s1p = g_s1 + (size_t)src * 64;
        float sa = s1p[lane] * w0;
        float sb = s1p[lane + 32] * w1;
        const float* v1p = g_v1 + (size_t)src * 192;
        float da = w2 * (v1p[lane] * ea0 + v1p[64 + lane] * ea1 + v1p[128 + lane] * ea2);
        float db = w3 * (v1p[lane + 32] * ea0 + v1p[96 + lane] * ea1 + v1p[160 + lane] * ea2);
        acc0.x += sa * ea0; acc0.y += sa * ea1; acc0.z += sa * ea2; acc0.w += da;
        acc1.x += sb * ea0; acc1.y += sb * ea1; acc1.z += sb * ea2; acc1.w += db;
        touched = true;
    }
    if (touched) {
        float4* ap = reinterpret_cast<float4*>(g_agg + (size_t)cur * 256);
        atomicAdd(ap + lane, acc0);
        atomicAdd(ap + lane + 32, acc1);
    }
}

// ------ post v4: no smem weights, float4 LDG tasks, 24 nodes/block ------
__global__ void __launch_bounds__(256) k_post(const float* __restrict__ lin2s,
                                              const float* __restrict__ lin2v,
                                              const float* __restrict__ sis,
                                              const float* __restrict__ siv,
                                              const float* __restrict__ hv,
                                              const float* __restrict__ mv,
                                              int layer, int cur,
                                              float* __restrict__ outp) {
    __shared__ float s_Q[128];
    __shared__ float s_ys[3][64], s_aggs[3][64];
    __shared__ __align__(16) float s_yv[3][192], s_aggv[3][192];   // [comp*64+c]
    __shared__ __align__(16) float s_outs[3][128];
    __shared__ __align__(16) float s_outv[3][192];                 // [comp*64+d]
    __shared__ __align__(16) float s_y2s[3][64];
    __shared__ __align__(16) float s_y2v[3][192];
    __shared__ float s_newv[3][192];
    int tid = threadIdx.x;
    if (tid < 128) s_Q[tid] = g_Q[tid];
    const float4* L2s4 = (const float4*)(lin2s + layer * 8192);
    const float4* L2v4 = (const float4*)(lin2v + layer * 4096);
    const float4* Ss4  = (const float4*)(sis + layer * 4096);
    const float4* Sv4  = (const float4*)(siv + layer * 4096);
    float hh = hv[layer] * hv[layer];
    float m = mv[layer];
    float* ys_new = g_ys[cur ^ 1];
    float* yv_new = g_yv[cur ^ 1];
    const float* ys_cur = g_ys[cur];
    const float* yv_cur = g_yv[cur];
    for (int it = 0; it < 8; it++) {
        int pbase = blockIdx.x * 24 + it * 3;
        // ---- stage node inputs ----
        if (tid < 192) {
            int node = tid >> 6, j = tid & 63;
            int p = pbase + node;
            if (p < NN) {
                int n = g_nidx[p];
                s_ys[node][j] = ys_cur[n * 64 + j];
                float4 a4 = ((const float4*)g_agg)[n * 64 + j];
                s_aggs[node][j] = a4.w * INV_NN;
                s_aggv[node][j] = a4.x * INV_NN;
                s_aggv[node][64 + j] = a4.y * INV_NN;
                s_aggv[node][128 + j] = a4.z * INV_NN;
                const float* yvp = yv_cur + n * 192 + j * 3;
                s_yv[node][j] = yvp[0];
                s_yv[node][64 + j] = yvp[1];
                s_yv[node][128 + j] = yvp[2];
            }
        }
        __syncthreads();
        // ---- matvec tasks ----
        if (tid < 240) {
            int node = tid / 80, j = tid % 80;
            int p = pbase + node;
            if (p < NN) {
                int a = g_nattr[p];
                if (j < 32) {
                    const float4* B = (const float4*)g_Bs + (size_t)(layer * 100 + a) * 2048;
                    float4 acc = make_float4(0.f, 0.f, 0.f, 0.f);
#pragma unroll 8
                    for (int c = 0; c < 64; c++) {
                        float av = s_aggs[node][c], yy = s_ys[node][c];
                        float4 w = __ldg(L2s4 + c * 32 + j);
                        float4 b = __ldg(B + c * 32 + j);
                        acc.x += av * w.x + yy * b.x;
                        acc.y += av * w.y + yy * b.y;
                        acc.z += av * w.z + yy * b.z;
                        acc.w += av * w.w + yy * b.w;
                    }
                    ((float4*)s_outs[node])[j] = acc;
                } else if (j < 48) {
                    int d4 = j - 32;
                    const float4* B = (const float4*)g_Bv + (size_t)(layer * 100 + a) * 1024;
                    float4 a0 = make_float4(0.f, 0.f, 0.f, 0.f);
                    float4 a1 = a0, a2 = a0;
#pragma unroll 8
                    for (int c = 0; c < 64; c++) {
                        float4 w = __ldg(L2v4 + c * 16 + d4);
                        float4 b = __ldg(B + c * 16 + d4);
                        float g0 = s_aggv[node][c], y0 = s_yv[node][c];
                        float g1 = s_aggv[node][64 + c], y1 = s_yv[node][64 + c];
                        float g2 = s_aggv[node][128 + c], y2 = s_yv[node][128 + c];
                        a0.x += g0 * w.x + y0 * b.x; a0.y += g0 * w.y + y0 * b.y;
                        a0.z += g0 * w.z + y0 * b.z; a0.w += g0 * w.w + y0 * b.w;
                        a1.x += g1 * w.x + y1 * b.x; a1.y += g1 * w.y + y1 * b.y;
                        a1.z += g1 * w.z + y1 * b.z; a1.w += g1 * w.w + y1 * b.w;
                        a2.x += g2 * w.x + y2 * b.x; a2.y += g2 * w.y + y2 * b.y;
                        a2.z += g2 * w.z + y2 * b.z; a2.w += g2 * w.w + y2 * b.w;
                    }
                    ((float4*)s_outv[node])[d4] = a0;
                    ((float4*)s_outv[node])[16 + d4] = a1;
                    ((float4*)s_outv[node])[32 + d4] = a2;
                } else if (j < 64) {
                    int d4 = j - 48;
                    float4 acc = make_float4(0.f, 0.f, 0.f, 0.f);
#pragma unroll 8
                    for (int c = 0; c < 64; c++) {
                        float yy = s_ys[node][c];
                        float4 w = __ldg(Ss4 + c * 16 + d4);
                        acc.x += yy * w.x; acc.y += yy * w.y;
                        acc.z += yy * w.z; acc.w += yy * w.w;
                    }
                    ((float4*)s_y2s[node])[d4] = acc;
                } else {
                    int d4 = j - 64;
                    float4 a0 = make_float4(0.f, 0.f, 0.f, 0.f);
                    float4 a1 = a0, a2 = a0;
#pragma unroll 8
                    for (int c = 0; c < 64; c++) {
                        float4 w = __ldg(Sv4 + c * 16 + d4);
                        float y0 = s_yv[node][c], y1 = s_yv[node][64 + c], y2 = s_yv[node][128 + c];
                        a0.x += y0 * w.x; a0.y += y0 * w.y; a0.z += y0 * w.z; a0.w += y0 * w.w;
                        a1.x += y1 * w.x; a1.y += y1 * w.y; a1.z += y1 * w.z; a1.w += y1 * w.w;
                        a2.x += y2 * w.x; a2.y += y2 * w.y; a2.z += y2 * w.z; a2.w += y2 * w.w;
                    }
                    ((float4*)s_y2v[node])[d4] = a0;
                    ((float4*)s_y2v[node])[16 + d4] = a1;
                    ((float4*)s_y2v[node])[32 + d4] = a2;
                }
            }
        }
        __syncthreads();
        // ---- state update ----
        if (tid < 192) {
            int node = tid >> 6, c = tid & 63;
            int p = pbase + node;
            if (p < NN) {
                int n = g_nidx[p];
                float os = s_outs[node][c];
                float gs = os / (1.f + __expf(-os));
                float gate = 1.f / (1.f + __expf(-s_outs[node][64 + c]));
                float yo = ys_new[n * 64 + c];
                float ns = 2.f * s_ys[node][c] - yo + hh * (m * gs + (m - 1.f) * s_y2s[node][c]);
                ys_new[n * 64 + c] = ns;
#pragma unroll
                for (int xx = 0; xx < 3; xx++) {
                    float yov = yv_new[n * 192 + c * 3 + xx];
                    float nv = 2.f * s_yv[node][xx * 64 + c] - yov +
                               hh * (m * gate * s_outv[node][xx * 64 + c] +
                                     (m - 1.f) * s_y2v[node][xx * 64 + c]);
                    yv_new[n * 192 + c * 3 + xx] = nv;
                    s_newv[node][xx * 64 + c] = nv;
                }
            }
        }
        __syncthreads();
        // ---- projection ----
        if (tid < 18) {
            int node = tid / 6, r = tid % 6, k = r / 3, xx = r % 3;
            int p = pbase + node;
            if (p < NN) {
                int n = g_nidx[p];
                float acc = 0.f;
#pragma unroll 8
                for (int c = 0; c < 64; c++) acc += s_newv[node][xx * 64 + c] * s_Q[c * 2 + k];
                if (layer == 0) {
                    if (k == 0) g_pos[n * 3 + xx] = acc;
                } else {
                    outp[n * 6 + k * 3 + xx] = acc;
                }
            }
        }
        __syncthreads();
    }
}

// ---------------- launch ----------------
extern "C" void kernel_launch(void* const* d_in, const int* in_sizes, int n_in,
                              void* d_out, int out_size) {
    const float* x        = (const float*)d_in[0];
    const int*   attr     = (const int*)d_in[2];
    const int*   esrc     = (const int*)d_in[3];
    const int*   edst     = (const int*)d_in[4];
    const float* emb      = (const float*)d_in[5];
    const float* uplift   = (const float*)d_in[6];
    const float* h        = (const float*)d_in[7];
    const float* mix      = (const float*)d_in[8];
    const float* rW1      = (const float*)d_in[9];
    const float* rb1      = (const float*)d_in[10];
    const float* rW2      = (const float*)d_in[11];
    const float* lin1s    = (const float*)d_in[12];
    const float* lin1v    = (const float*)d_in[13];
    const float* lin2s    = (const float*)d_in[14];
    const float* lin2v    = (const float*)d_in[15];
    const float* scs      = (const float*)d_in[16];
    const float* scv      = (const float*)d_in[17];
    const float* sis      = (const float*)d_in[18];
    const float* siv      = (const float*)d_in[19];
    float* out = (float*)d_out;

    const int PB = (NN + 23) / 24;  // 834

    k_init<<<7480, 256>>>(x, uplift, emb, scs, scv, lin1v, attr);   // 0
    k_edge_u<<<2048, 256>>>(esrc, edst, rW1, rb1, rW2);             // 1 (layer0)
    k_hist_e<<<1280, 256>>>(edst);                                  // 2
    k_post<<<PB, 256>>>(lin2s, lin2v, sis, siv, h, mix, 0, 0, out); // 3 <- profiled
    k_scan_e<<<1, 512>>>();                                         // 4
    k_scat_e<<<1280, 256>>>(esrc, edst);                            // 5
    k_zero<<<1024, 256>>>();                                        // 6
    k_pre<<<NN / 8, 256>>>(lin1s, lin1v, 1, 1);                     // 7
    k_edge<<<2000, 256>>>(rW1, rb1, rW2, 1);                        // 8
    k_post<<<PB, 256>>>(lin2s, lin2v, sis, siv, h, mix, 1, 1, out); // 9
}

// round 7
// speedup vs baseline: 1.9313x; 1.1171x over previous
#include <cuda_runtime.h>
#include <cuda_bf16.h>
#include <math.h>

#define NN 20000
#define NE 640000
#define NL 2
#define MAXR 2.5f
#define INV_NN 0.17677669529663687f   // 1/sqrt(32)
#define NPAD 20800                    // attr-sorted node list padded to 8-aligned segments

// ---------------- scratch (device globals; no allocs) ----------------
static __device__ float g_Q[64 * 2];
static __device__ float g_ys[2][NN * 64];
static __device__ float g_yv[2][NN * 192];
static __device__ float g_s1[NN * 64];
static __device__ float g_v1[NN * 192];          // [n][3][64] x-major
static __device__ float g_agg[NN * 256];         // (n, c, 4): vx,vy,vz,s
static __device__ float g_pos[NN * 3];
static __device__ float g_Bs[NL * 100 * 64 * 128];
static __device__ float g_Bv[NL * 100 * 64 * 64];
// edge sort (by dst)
static __device__ int g_ecnt[NN];
static __device__ int g_eoff[NN];
static __device__ int g_eppos[NN];
static __device__ int g_ssrc[NE];
static __device__ int g_sdst[NE];
// node sort (by attr), 8-aligned segments, -1 = sentinel
static __device__ int g_nidx[NPAD];
static __device__ int g_nattr[NPAD];

// ---- fused init: Q + y init + layer0 v1 + B precompute + cnt zero + node sort ----
__global__ void __launch_bounds__(256) k_init(const float* __restrict__ x,
                                              const float* __restrict__ M,
                                              const float* __restrict__ emb,
                                              const float* __restrict__ scs,
                                              const float* __restrict__ scv,
                                              const float* __restrict__ lin1v,
                                              const int* __restrict__ attr) {
    int tid = threadIdx.x;
    if (blockIdx.x < 5000) {
        __shared__ float sQ[128];
        __shared__ float sR[128];
        if (tid == 0) {
            double a = 0, b = 0, c = 0;
            for (int i = 0; i < 64; i++) {
                double m0 = M[2 * i], m1 = M[2 * i + 1];
                a += m0 * m0; b += m0 * m1; c += m1 * m1;
            }
            double det = a * c - b * b;
            double s = sqrt(det);
            double t = a + c;
            double denom = sqrt(t + 2.0 * s);
            double p00 = (a + s) / denom, p01 = b / denom, p11 = (c + s) / denom;
            double pdet = p00 * p11 - p01 * p01;
            double i00 = p11 / pdet, i01 = -p01 / pdet, i11 = p00 / pdet;
            for (int i = 0; i < 64; i++) {
                double m0 = M[2 * i], m1 = M[2 * i + 1];
                sQ[2 * i]     = (float)(m0 * i00 + m1 * i01);
                sQ[2 * i + 1] = (float)(m0 * i01 + m1 * i11);
            }
            if (blockIdx.x == 0)
                for (int i = 0; i < 128; i++) g_Q[i] = sQ[i];
        }
        __syncthreads();
        if (tid < 128) {
            int k = tid >> 6, d = tid & 63;
            float acc = 0.f;
#pragma unroll 8
            for (int c = 0; c < 64; c++) acc += sQ[c * 2 + k] * lin1v[c * 64 + d];
            sR[k * 64 + d] = acc;
        }
        __syncthreads();
        int i = blockIdx.x * 256 + tid;
        if (i >= NN * 64) return;
        int n = i >> 6, c = i & 63;
        float q0 = sQ[c * 2], q1 = sQ[c * 2 + 1];
        const float* xp = x + n * 6;
        float v0 = xp[0] * q0 + xp[3] * q1;
        float v1 = xp[1] * q0 + xp[4] * q1;
        float v2 = xp[2] * q0 + xp[5] * q1;
        int base = n * 192 + c * 3;
        g_yv[0][base + 0] = v0; g_yv[0][base + 1] = v1; g_yv[0][base + 2] = v2;
        g_yv[1][base + 0] = v0; g_yv[1][base + 1] = v1; g_yv[1][base + 2] = v2;
        g_ys[0][i] = 0.f; g_ys[1][i] = 0.f;
        if (c < 3) g_pos[n * 3 + c] = xp[c];
        reinterpret_cast<float4*>(g_agg)[i] = make_float4(0.f, 0.f, 0.f, 0.f);
        int d = c;
        float r0 = sR[d], r1 = sR[64 + d];
#pragma unroll
        for (int xx = 0; xx < 3; xx++)
            g_v1[n * 192 + xx * 64 + d] = xp[xx] * r0 + xp[3 + xx] * r1;
    } else if (blockIdx.x < 7400) {
        const int TOTS = NL * 100 * 64 * 128;
        const int TOTV = NL * 100 * 64 * 64;
        const int NB = 2400;
        for (int idx = (blockIdx.x - 5000) * 256 + tid; idx < TOTS + TOTV;
             idx += NB * 256) {
            if (idx < TOTS) {
                int o = idx & 127;
                int c = (idx >> 7) & 63;
                int a = (idx >> 13) % 100;
                int l = idx / (128 * 64 * 100);
                const float* w = scs + ((size_t)(l * 64 + c) * 32) * 128 + o;
                const float* em = emb + a * 32;
                float acc = 0.f;
#pragma unroll 8
                for (int e = 0; e < 32; e++) acc += em[e] * w[e * 128];
                g_Bs[idx] = acc;
            } else {
                int j = idx - TOTS;
                int o = j & 63;
                int c = (j >> 6) & 63;
                int a = (j >> 12) % 100;
                int l = j / (64 * 64 * 100);
                const float* w = scv + ((size_t)(l * 64 + c) * 32) * 64 + o;
                const float* em = emb + a * 32;
                float acc = 0.f;
#pragma unroll 8
                for (int e = 0; e < 32; e++) acc += em[e] * w[e * 64];
                g_Bv[j] = acc;
            }
        }
    } else if (blockIdx.x < 7479) {
        int i = (blockIdx.x - 7400) * 256 + tid;
        if (i < NN) { g_ecnt[i] = 0; g_eppos[i] = 0; }
    } else {
        // single-block node counting sort by attr, segments padded to 8
        __shared__ int scnt[128], soff[128], spos[128];
        if (tid < 128) { scnt[tid] = 0; spos[tid] = 0; }
        __syncthreads();
        for (int n = tid; n < NN; n += 256) atomicAdd(&scnt[attr[n]], 1);
        __syncthreads();
        int pc = 0;
        if (tid < 128) { pc = (scnt[tid] + 7) & ~7; soff[tid] = pc; }
        __syncthreads();
        for (int off = 1; off < 128; off <<= 1) {
            int v = 0;
            if (tid < 128 && tid >= off) v = soff[tid - off];
            __syncthreads();
            if (tid < 128) soff[tid] += v;
            __syncthreads();
        }
        if (tid < 128) soff[tid] -= pc;  // exclusive, 8-aligned
        __syncthreads();
        for (int i = tid; i < NPAD; i += 256) g_nidx[i] = -1;
        __syncthreads();
        for (int n = tid; n < NN; n += 256) {
            int a = attr[n];
            int p = soff[a] + atomicAdd(&spos[a], 1);
            g_nidx[p] = n;
            g_nattr[p] = a;
        }
    }
}

// ---------------- edge histogram / scan / scatter ----------------
__global__ void k_hist_e(const int* __restrict__ edst) {
    for (int e = blockIdx.x * 256 + threadIdx.x; e < NE; e += 1280 * 256)
        atomicAdd(&g_ecnt[edst[e]], 1);
}
__global__ void __launch_bounds__(512) k_scan_e() {
    __shared__ int sp[512];
    int t = threadIdx.x;
    const int CH = 40;
    int base = t * CH;
    int part = 0;
    for (int i = 0; i < CH; i++) {
        int idx = base + i;
        if (idx < NN) part += g_ecnt[idx];
    }
    sp[t] = part;
    __syncthreads();
    for (int off = 1; off < 512; off <<= 1) {
        int v = (t >= off) ? sp[t - off] : 0;
        __syncthreads();
        sp[t] += v;
        __syncthreads();
    }
    int run = sp[t] - part;
    for (int i = 0; i < CH; i++) {
        int idx = base + i;
        if (idx < NN) { g_eoff[idx] = run; run += g_ecnt[idx]; }
    }
}
__global__ void k_scat_e(const int* __restrict__ esrc, const int* __restrict__ edst) {
    for (int e = blockIdx.x * 256 + threadIdx.x; e < NE; e += 1280 * 256) {
        int d = edst[e];
        int p = g_eoff[d] + atomicAdd(&g_eppos[d], 1);
        g_ssrc[p] = esrc[e];
        g_sdst[p] = d;
    }
}

// ---------------- zero aggregation buffer ----------------
__global__ void k_zero() {
    float4 z = make_float4(0.f, 0.f, 0.f, 0.f);
    float4* p = reinterpret_cast<float4*>(g_agg);
    for (int i = blockIdx.x * blockDim.x + threadIdx.x; i < NN * 64;
         i += gridDim.x * blockDim.x)
        p[i] = z;
}

// ---------------- pre (layer 1 only) ----------------
__global__ void __launch_bounds__(256) k_pre(const float* __restrict__ lin1s,
                                             const float* __restrict__ lin1v,
                                             int layer, int cur) {
    __shared__ float sWs[4096], sWv[4096];
    __shared__ float sy[8][256];
    int tid = threadIdx.x;
    const float* Ws = lin1s + layer * 4096;
    const float* Wv = lin1v + layer * 4096;
    for (int k = tid; k < 4096; k += 256) { sWs[k] = Ws[k]; sWv[k] = Wv[k]; }
    const float* ys = g_ys[cur];
    const float* yv = g_yv[cur];
    int n0 = blockIdx.x * 8;
    for (int k = tid; k < 2048; k += 256) {
        int nn = k >> 8, j = k & 255;
        int n = n0 + nn;
        sy[nn][j] = (j < 64) ? ys[n * 64 + j] : yv[n * 192 + j - 64];
    }
    __syncthreads();
    for (int nn = 0; nn < 8; nn++) {
        int n = n0 + nn;
        if (tid < 64) {
            int d = tid;
            float acc = 0.f;
#pragma unroll 8
            for (int c = 0; c < 64; c++) acc += sy[nn][c] * sWs[c * 64 + d];
            g_s1[n * 64 + d] = acc;
        } else {
            int idx = tid - 64;
            int d = idx & 63, xx = idx >> 6;
            float acc = 0.f;
#pragma unroll 8
            for (int c = 0; c < 64; c++) acc += sy[nn][64 + c * 3 + xx] * sWv[c * 64 + d];
            g_v1[n * 192 + xx * 64 + d] = acc;
        }
    }
}

// -------- edge math common (bf16 W2 in smem) --------
__device__ __forceinline__ void edge_core(float ev0, float ev1, float ev2, float l2,
                                          const float* sW1, const float* sb1v,
                                          const unsigned* sW2b, int lane,
                                          float& ea0, float& ea1, float& ea2,
                                          float& w0, float& w1, float& w2, float& w3) {
    const float PI = 3.14159265358979f;
    float elen = sqrtf(l2);
    float safe = fmaxf(elen, 1e-9f);
    float inv = 1.0f / safe;
    float u = 2.f * (elen * (1.0f / MAXR) - 1.f);
    float cut = 0.5f * (1.f - __cosf(PI * u));
    float ca = cut * 1.7320508075688772f * inv;
    ea0 = ca * ev0; ea1 = ca * ev1; ea2 = ca * ev2;
    float th = (PI / MAXR) * safe;
    float sk = __sinf(th), c2 = 2.f * __cosf(th), skm1 = 0.f;
    float fac = 2.5298221281347035f * inv;
    float hs = sb1v[lane];
#pragma unroll
    for (int k = 0; k < 8; k++) {
        hs += (fac * sk) * sW1[k * 32 + lane];
        float t = c2 * sk - skm1; skm1 = sk; sk = t;
    }
    float hval = hs / (1.f + __expf(-hs));  // silu
    w0 = 0.f; w1 = 0.f; w2 = 0.f; w3 = 0.f;
#pragma unroll
    for (int k = 0; k < 32; k++) {
        float hk = __shfl_sync(0xffffffffu, hval, k);
        uint2 uv = *reinterpret_cast<const uint2*>(&sW2b[k * 64 + lane * 2]);
        float2 f01 = __bfloat1622float2(*reinterpret_cast<__nv_bfloat162*>(&uv.x));
        float2 f23 = __bfloat1622float2(*reinterpret_cast<__nv_bfloat162*>(&uv.y));
        w0 = fmaf(hk, f01.x, w0);
        w1 = fmaf(hk, f01.y, w1);
        w2 = fmaf(hk, f23.x, w2);
        w3 = fmaf(hk, f23.y, w3);
    }
}

__device__ __forceinline__ void fill_w2(unsigned* sW2b, const float* rW2, int layer,
                                        int tid) {
    for (int t = tid; t < 2048; t += 256) {
        int k = t >> 6, r = t & 63, ln = r >> 1, g = r & 1;
        const float* base = rW2 + layer * 4096 + k * 128 + g * 64;
        __nv_bfloat162 p = __floats2bfloat162_rn(base[ln], base[32 + ln]);
        sW2b[t] = *reinterpret_cast<unsigned*>(&p);
    }
}

// -------- layer-0 edge: unsorted, s1==0 --------
__global__ void __launch_bounds__(256) k_edge_u(const int* __restrict__ esrc,
                                                const int* __restrict__ edst,
                                                const float* __restrict__ rW1,
                                                const float* __restrict__ rb1,
                                                const float* __restrict__ rW2) {
    __shared__ float sW1[256];
    __shared__ float sb1v[32];
    __shared__ unsigned sW2b[2048];
    int tid = threadIdx.x;
    for (int k = tid; k < 256; k += 256) sW1[k] = rW1[k];
    if (tid < 32) sb1v[tid] = rb1[tid];
    fill_w2(sW2b, rW2, 0, tid);
    __syncthreads();
    int lane = tid & 31;
    int gwarp = (blockIdx.x * 256 + tid) >> 5;
    int nw = gridDim.x * 8;
    for (int e = gwarp; e < NE; e += nw) {
        int src = esrc[e], dst = edst[e];
        float ev0 = g_pos[src * 3 + 0] - g_pos[dst * 3 + 0];
        float ev1 = g_pos[src * 3 + 1] - g_pos[dst * 3 + 1];
        float ev2 = g_pos[src * 3 + 2] - g_pos[dst * 3 + 2];
        float l2 = ev0 * ev0 + ev1 * ev1 + ev2 * ev2;
        if (l2 >= MAXR * MAXR) continue;
        float ea0, ea1, ea2, w0, w1, w2, w3;
        edge_core(ev0, ev1, ev2, l2, sW1, sb1v, sW2b, lane, ea0, ea1, ea2, w0, w1, w2, w3);
        const float* v1p = g_v1 + (size_t)src * 192;
        float da = w2 * (v1p[lane] * ea0 + v1p[64 + lane] * ea1 + v1p[128 + lane] * ea2);
        float db = w3 * (v1p[lane + 32] * ea0 + v1p[96 + lane] * ea1 + v1p[160 + lane] * ea2);
        float4* ap = reinterpret_cast<float4*>(g_agg + (size_t)dst * 256);
        atomicAdd(ap + lane,      make_float4(0.f, 0.f, 0.f, da));
        atomicAdd(ap + lane + 32, make_float4(0.f, 0.f, 0.f, db));
    }
}

// -------- layer-1 edge: dst-sorted, register accumulation --------
__global__ void __launch_bounds__(256) k_edge(const float* __restrict__ rW1,
                                              const float* __restrict__ rb1,
                                              const float* __restrict__ rW2,
                                              int layer) {
    __shared__ float sW1[256];
    __shared__ float sb1v[32];
    __shared__ unsigned sW2b[2048];
    int tid = threadIdx.x;
    for (int k = tid; k < 256; k += 256) sW1[k] = rW1[layer * 256 + k];
    if (tid < 32) sb1v[tid] = rb1[layer * 32 + tid];
    fill_w2(sW2b, rW2, layer, tid);
    __syncthreads();
    int lane = tid & 31;
    int warp = (blockIdx.x * 256 + tid) >> 5;
    const int K = 40;
    int e0 = warp * K;
    if (e0 >= NE) return;
    int e1 = e0 + K; if (e1 > NE) e1 = NE;
    float4 acc0 = make_float4(0.f, 0.f, 0.f, 0.f);
    float4 acc1 = make_float4(0.f, 0.f, 0.f, 0.f);
    bool touched = false;
    int cur = -1;
    float dp0 = 0.f, dp1 = 0.f, dp2 = 0.f;
    for (int e = e0; e < e1; e++) {
        int dst = g_sdst[e];
        if (dst != cur) {
            if (touched) {
                float4* ap = reinterpret_cast<float4*>(g_agg + (size_t)cur * 256);
                atomicAdd(ap + lane, acc0);
                atomicAdd(ap + lane + 32, acc1);
                acc0 = make_float4(0.f, 0.f, 0.f, 0.f);
                acc1 = make_float4(0.f, 0.f, 0.f, 0.f);
                touched = false;
            }
            cur = dst;
            dp0 = g_pos[dst * 3 + 0];
            dp1 = g_pos[dst * 3 + 1];
            dp2 = g_pos[dst * 3 + 2];
        }
        int src = g_ssrc[e];
        float ev0 = g_pos[src * 3 + 0] - dp0;
        float ev1 = g_pos[src * 3 + 1] - dp1;
        float ev2 = g_pos[src * 3 + 2] - dp2;
        float l2 = ev0 * ev0 + ev1 * ev1 + ev2 * ev2;
        if (l2 >= MAXR * MAXR) continue;
        float ea0, ea1, ea2, w0, w1, w2, w3;
        edge_core(ev0, ev1, ev2, l2, sW1, sb1v, sW2b, lane, ea0, ea1, ea2, w0, w1, w2, w3);
        const float* s1p = g_s1 + (size_t)src * 64;
        float sa = s1p[lane] * w0;
        float sb = s1p[lane + 32] * w1;
        const float* v1p = g_v1 + (size_t)src * 192;
        float da = w2 * (v1p[lane] * ea0 + v1p[64 + lane] * ea1 + v1p[128 + lane] * ea2);
        float db = w3 * (v1p[lane + 32] * ea0 + v1p[96 + lane] * ea1 + v1p[160 + lane] * ea2);
        acc0.x += sa * ea0; acc0.y += sa * ea1; acc0.z += sa * ea2; acc0.w += da;
        acc1.x += sb * ea0; acc1.y += sb * ea1; acc1.z += sb * ea2; acc1.w += db;
        touched = true;
    }
    if (touched) {
        float4* ap = reinterpret_cast<float4*>(g_agg + (size_t)cur * 256);
        atomicAdd(ap + lane, acc0);
        atomicAdd(ap + lane + 32, acc1);
    }
}

// ------ post v5: 8-node attr-uniform chunks, register-blocked matvec ------
__global__ void __launch_bounds__(256) k_post(const float* __restrict__ lin2s,
                                              const float* __restrict__ lin2v,
                                              const float* __restrict__ sis,
                                              const float* __restrict__ siv,
                                              const float* __restrict__ hv,
                                              const float* __restrict__ mv,
                                              int layer, int cur,
                                              float* __restrict__ outp) {
    __shared__ float s_Q[128];
    __shared__ float s_zero[64];
    __shared__ float s_ys[8][64], s_aggs[8][64];
    __shared__ __align__(16) float s_yv[8][192], s_aggv[8][192];   // [xx*64+c]
    __shared__ __align__(16) float s_outs[8][128];
    __shared__ __align__(16) float s_outv[8][192];
    __shared__ __align__(16) float s_y2s[8][64];
    __shared__ __align__(16) float s_y2v[8][192];
    __shared__ float s_newv[8][192];
    int tid = threadIdx.x;
    if (tid < 128) s_Q[tid] = g_Q[tid];
    if (tid < 64) s_zero[tid] = 0.f;
    const float4* L2s4 = (const float4*)(lin2s + layer * 8192);
    const float4* L2v4 = (const float4*)(lin2v + layer * 4096);
    const float4* Ss4  = (const float4*)(sis + layer * 4096);
    const float4* Sv4  = (const float4*)(siv + layer * 4096);
    float hh = hv[layer] * hv[layer];
    float m = mv[layer];
    float* ys_new = g_ys[cur ^ 1];
    float* yv_new = g_yv[cur ^ 1];
    const float* ys_cur = g_ys[cur];
    const float* yv_cur = g_yv[cur];
    for (int it = 0; it < 2; it++) {
        int pbase = blockIdx.x * 16 + it * 8;
        // ---- stage ----
        for (int t = tid; t < 512; t += 256) {
            int node = t >> 6, j = t & 63;
            int n = g_nidx[pbase + node];
            if (n >= 0) {
                s_ys[node][j] = ys_cur[n * 64 + j];
                float4 a4 = ((const float4*)g_agg)[n * 64 + j];
                s_aggs[node][j] = a4.w * INV_NN;
                s_aggv[node][j] = a4.x * INV_NN;
                s_aggv[node][64 + j] = a4.y * INV_NN;
                s_aggv[node][128 + j] = a4.z * INV_NN;
                const float* yvp = yv_cur + n * 192 + j * 3;
                s_yv[node][j] = yvp[0];
                s_yv[node][64 + j] = yvp[1];
                s_yv[node][128 + j] = yvp[2];
            }
        }
        __syncthreads();
        // ---- matvec (unified, 144 active threads) ----
        if (tid < 144) {
            int a = g_nattr[pbase];   // chunk is attr-uniform by construction
            const float4 *wp, *bp;
            int wst;
            const float *in1, *in2;
            int istr1, istr2;
            float4* o4;
            int ostr;
            if (tid < 32) {            // out_s: agg_s@L2s + ys@Bs
                int j = tid;
                wp = L2s4 + j; bp = (const float4*)g_Bs + (size_t)(layer * 100 + a) * 2048 + j;
                wst = 32;
                in1 = &s_aggs[0][0]; istr1 = 64;
                in2 = &s_ys[0][0];   istr2 = 64;
                o4 = (float4*)&s_outs[0][0] + j; ostr = 32;
            } else if (tid < 80) {     // out_v: aggv@L2v + yv@Bv (per component)
                int id = tid - 32, j = id & 15, xx = id >> 4;
                wp = L2v4 + j; bp = (const float4*)g_Bv + (size_t)(layer * 100 + a) * 1024 + j;
                wst = 16;
                in1 = &s_aggv[0][xx * 64]; istr1 = 192;
                in2 = &s_yv[0][xx * 64];   istr2 = 192;
                o4 = (float4*)&s_outv[0][0] + xx * 16 + j; ostr = 48;
            } else if (tid < 96) {     // y2_s: ys@Ss
                int j = tid - 80;
                wp = Ss4 + j; bp = Ss4 + j;
                wst = 16;
                in1 = &s_ys[0][0]; istr1 = 64;
                in2 = s_zero;      istr2 = 0;
                o4 = (float4*)&s_y2s[0][0] + j; ostr = 16;
            } else {                   // y2_v: yv@Sv (per component)
                int id = tid - 96, j = id & 15, xx = id >> 4;
                wp = Sv4 + j; bp = Sv4 + j;
                wst = 16;
                in1 = &s_yv[0][xx * 64]; istr1 = 192;
                in2 = s_zero;            istr2 = 0;
                o4 = (float4*)&s_y2v[0][0] + xx * 16 + j; ostr = 48;
            }
            float4 acc[8];
#pragma unroll
            for (int nn = 0; nn < 8; nn++) acc[nn] = make_float4(0.f, 0.f, 0.f, 0.f);
#pragma unroll 4
            for (int c = 0; c < 64; c++) {
                float4 w = __ldg(wp); wp += wst;
                float4 b = __ldg(bp); bp += wst;
                const float* q1 = in1 + c;
                const float* q2 = in2 + c * (istr2 ? 1 : 0);
#pragma unroll
                for (int nn = 0; nn < 8; nn++) {
                    float u1 = q1[nn * istr1];
                    float u2 = q2[nn * istr2];
                    acc[nn].x += u1 * w.x + u2 * b.x;
                    acc[nn].y += u1 * w.y + u2 * b.y;
                    acc[nn].z += u1 * w.z + u2 * b.z;
                    acc[nn].w += u1 * w.w + u2 * b.w;
                }
            }
#pragma unroll
            for (int nn = 0; nn < 8; nn++) o4[nn * ostr] = acc[nn];
        }
        __syncthreads();
        // ---- state update ----
        for (int t = tid; t < 512; t += 256) {
            int node = t >> 6, c = t & 63;
            int n = g_nidx[pbase + node];
            if (n >= 0) {
                float os = s_outs[node][c];
                float gs = os / (1.f + __expf(-os));
                float gate = 1.f / (1.f + __expf(-s_outs[node][64 + c]));
                float yo = ys_new[n * 64 + c];
                float ns = 2.f * s_ys[node][c] - yo + hh * (m * gs + (m - 1.f) * s_y2s[node][c]);
                ys_new[n * 64 + c] = ns;
#pragma unroll
                for (int xx = 0; xx < 3; xx++) {
                    float yov = yv_new[n * 192 + c * 3 + xx];
                    float nv = 2.f * s_yv[node][xx * 64 + c] - yov +
                               hh * (m * gate * s_outv[node][xx * 64 + c] +
                                     (m - 1.f) * s_y2v[node][xx * 64 + c]);
                    yv_new[n * 192 + c * 3 + xx] = nv;
                    s_newv[node][xx * 64 + c] = nv;
                }
            }
        }
        __syncthreads();
        // ---- projection ----
        if (tid < 48) {
            int node = tid / 6, r = tid % 6, k = r / 3, xx = r % 3;
            int n = g_nidx[pbase + node];
            if (n >= 0) {
                float acc = 0.f;
#pragma unroll 8
                for (int c = 0; c < 64; c++) acc += s_newv[node][xx * 64 + c] * s_Q[c * 2 + k];
                if (layer == 0) {
                    if (k == 0) g_pos[n * 3 + xx] = acc;
                } else {
                    outp[n * 6 + k * 3 + xx] = acc;
                }
            }
        }
        __syncthreads();
    }
}

// ---------------- launch ----------------
extern "C" void kernel_launch(void* const* d_in, const int* in_sizes, int n_in,
                              void* d_out, int out_size) {
    const float* x        = (const float*)d_in[0];
    const int*   attr     = (const int*)d_in[2];
    const int*   esrc     = (const int*)d_in[3];
    const int*   edst     = (const int*)d_in[4];
    const float* emb      = (const float*)d_in[5];
    const float* uplift   = (const float*)d_in[6];
    const float* h        = (const float*)d_in[7];
    const float* mix      = (const float*)d_in[8];
    const float* rW1      = (const float*)d_in[9];
    const float* rb1      = (const float*)d_in[10];
    const float* rW2      = (const float*)d_in[11];
    const float* lin1s    = (const float*)d_in[12];
    const float* lin1v    = (const float*)d_in[13];
    const float* lin2s    = (const float*)d_in[14];
    const float* lin2v    = (const float*)d_in[15];
    const float* scs      = (const float*)d_in[16];
    const float* scv      = (const float*)d_in[17];
    const float* sis      = (const float*)d_in[18];
    const float* siv      = (const float*)d_in[19];
    float* out = (float*)d_out;

    const int PB = NPAD / 16;  // 1300

    k_init<<<7480, 256>>>(x, uplift, emb, scs, scv, lin1v, attr);   // 0
    k_edge_u<<<2048, 256>>>(esrc, edst, rW1, rb1, rW2);             // 1 (layer0)
    k_hist_e<<<1280, 256>>>(edst);                                  // 2
    k_post<<<PB, 256>>>(lin2s, lin2v, sis, siv, h, mix, 0, 0, out); // 3 <- profiled
    k_scan_e<<<1, 512>>>();                                         // 4
    k_scat_e<<<1280, 256>>>(esrc, edst);                            // 5
    k_zero<<<1024, 256>>>();                                        // 6
    k_pre<<<NN / 8, 256>>>(lin1s, lin1v, 1, 1);                     // 7
    k_edge<<<2000, 256>>>(rW1, rb1, rW2, 1);                        // 8
    k_post<<<PB, 256>>>(lin2s, lin2v, sis, siv, h, mix, 1, 1, out); // 9
}

// round 8
// speedup vs baseline: 3.1529x; 1.6325x over previous
#include <cuda_runtime.h>
#include <cuda_bf16.h>
#include <math.h>

#define NN 20000
#define NE 640000
#define NL 2
#define MAXR 2.5f
#define INV_NN 0.17677669529663687f   // 1/sqrt(32)
#define NPAD 20800                    // attr-sorted node list padded to 8-aligned segments

// ---------------- scratch (device globals; no allocs) ----------------
static __device__ float g_Q[64 * 2];
static __device__ float g_ys[2][NN * 64];
static __device__ float g_yv[2][NN * 192];
static __device__ float g_s1[NN * 64];
static __device__ float g_v1[NN * 192];          // [n][3][64] x-major
static __device__ float g_agg[NN * 256];         // (n, c, 4): vx,vy,vz,s
static __device__ float g_pos[NN * 3];
static __device__ float g_Bs[NL * 100 * 64 * 128];
static __device__ float g_Bv[NL * 100 * 64 * 64];
// edge sort (by dst); counters zeroed by k_zero of the PREVIOUS call (.bss on first)
static __device__ int g_ecnt[NN];
static __device__ int g_eoff[NN];
static __device__ int g_eppos[NN];
static __device__ int g_ssrc[NE];
static __device__ int g_sdst[NE];
// node sort (by attr), 8-aligned segments, -1 = sentinel
static __device__ int g_nidx[NPAD];
static __device__ int g_nattr[NPAD];

// ---------------- edge histogram / scan / scatter ----------------
__global__ void k_hist_e(const int* __restrict__ edst) {
    for (int e = blockIdx.x * 256 + threadIdx.x; e < NE; e += 1280 * 256)
        atomicAdd(&g_ecnt[edst[e]], 1);
}
__global__ void __launch_bounds__(512) k_scan_e() {
    __shared__ int sp[512];
    int t = threadIdx.x;
    const int CH = 40;
    int base = t * CH;
    int part = 0;
    for (int i = 0; i < CH; i++) {
        int idx = base + i;
        if (idx < NN) part += g_ecnt[idx];
    }
    sp[t] = part;
    __syncthreads();
    for (int off = 1; off < 512; off <<= 1) {
        int v = (t >= off) ? sp[t - off] : 0;
        __syncthreads();
        sp[t] += v;
        __syncthreads();
    }
    int run = sp[t] - part;
    for (int i = 0; i < CH; i++) {
        int idx = base + i;
        if (idx < NN) { g_eoff[idx] = run; run += g_ecnt[idx]; }
    }
}
__global__ void k_scat_e(const int* __restrict__ esrc, const int* __restrict__ edst) {
    for (int e = blockIdx.x * 256 + threadIdx.x; e < NE; e += 1280 * 256) {
        int d = edst[e];
        int p = g_eoff[d] + atomicAdd(&g_eppos[d], 1);
        g_ssrc[p] = esrc[e];
        g_sdst[p] = d;
    }
}

// ---- fused init: Q (warp-parallel) + y init + layer0 v1 + B precompute + node sort ----
__global__ void __launch_bounds__(256) k_init(const float* __restrict__ x,
                                              const float* __restrict__ M,
                                              const float* __restrict__ emb,
                                              const float* __restrict__ scs,
                                              const float* __restrict__ scv,
                                              const float* __restrict__ lin1v,
                                              const int* __restrict__ attr) {
    int tid = threadIdx.x;
    if (blockIdx.x < 5000) {
        __shared__ double dI[3];
        __shared__ float sQ[128];
        __shared__ float sR[128];
        if (tid < 32) {
            double m0a = M[2 * tid], m1a = M[2 * tid + 1];
            double m0b = M[2 * (tid + 32)], m1b = M[2 * (tid + 32) + 1];
            double pa = m0a * m0a + m0b * m0b;
            double pb = m0a * m1a + m0b * m1b;
            double pc = m1a * m1a + m1b * m1b;
#pragma unroll
            for (int off = 16; off > 0; off >>= 1) {
                pa += __shfl_down_sync(0xffffffffu, pa, off);
                pb += __shfl_down_sync(0xffffffffu, pb, off);
                pc += __shfl_down_sync(0xffffffffu, pc, off);
            }
            if (tid == 0) {
                double det = pa * pc - pb * pb;
                double s = sqrt(det);
                double t = pa + pc;
                double denom = sqrt(t + 2.0 * s);
                double p00 = (pa + s) / denom, p01 = pb / denom, p11 = (pc + s) / denom;
                double pdet = p00 * p11 - p01 * p01;
                dI[0] = p11 / pdet; dI[1] = -p01 / pdet; dI[2] = p00 / pdet;
            }
        }
        __syncthreads();
        if (tid < 64) {
            double m0 = M[2 * tid], m1 = M[2 * tid + 1];
            sQ[2 * tid]     = (float)(m0 * dI[0] + m1 * dI[1]);
            sQ[2 * tid + 1] = (float)(m0 * dI[1] + m1 * dI[2]);
        }
        __syncthreads();
        if (blockIdx.x == 0 && tid < 128) g_Q[tid] = sQ[tid];
        if (tid < 128) {
            int k = tid >> 6, d = tid & 63;
            float acc = 0.f;
#pragma unroll 8
            for (int c = 0; c < 64; c++) acc += sQ[c * 2 + k] * lin1v[c * 64 + d];
            sR[k * 64 + d] = acc;
        }
        __syncthreads();
        int i = blockIdx.x * 256 + tid;
        if (i >= NN * 64) return;
        int n = i >> 6, c = i & 63;
        float q0 = sQ[c * 2], q1 = sQ[c * 2 + 1];
        const float* xp = x + n * 6;
        float v0 = xp[0] * q0 + xp[3] * q1;
        float v1 = xp[1] * q0 + xp[4] * q1;
        float v2 = xp[2] * q0 + xp[5] * q1;
        int base = n * 192 + c * 3;
        g_yv[0][base + 0] = v0; g_yv[0][base + 1] = v1; g_yv[0][base + 2] = v2;
        g_yv[1][base + 0] = v0; g_yv[1][base + 1] = v1; g_yv[1][base + 2] = v2;
        g_ys[0][i] = 0.f; g_ys[1][i] = 0.f;
        if (c < 3) g_pos[n * 3 + c] = xp[c];
        reinterpret_cast<float4*>(g_agg)[i] = make_float4(0.f, 0.f, 0.f, 0.f);
        int d = c;
        float r0 = sR[d], r1 = sR[64 + d];
#pragma unroll
        for (int xx = 0; xx < 3; xx++)
            g_v1[n * 192 + xx * 64 + d] = xp[xx] * r0 + xp[3 + xx] * r1;
    } else if (blockIdx.x < 7400) {
        const int TOTS = NL * 100 * 64 * 128;
        const int TOTV = NL * 100 * 64 * 64;
        const int NB = 2400;
        for (int idx = (blockIdx.x - 5000) * 256 + tid; idx < TOTS + TOTV;
             idx += NB * 256) {
            if (idx < TOTS) {
                int o = idx & 127;
                int c = (idx >> 7) & 63;
                int a = (idx >> 13) % 100;
                int l = idx / (128 * 64 * 100);
                const float* w = scs + ((size_t)(l * 64 + c) * 32) * 128 + o;
                const float* em = emb + a * 32;
                float acc = 0.f;
#pragma unroll 8
                for (int e = 0; e < 32; e++) acc += em[e] * w[e * 128];
                g_Bs[idx] = acc;
            } else {
                int j = idx - TOTS;
                int o = j & 63;
                int c = (j >> 6) & 63;
                int a = (j >> 12) % 100;
                int l = j / (64 * 64 * 100);
                const float* w = scv + ((size_t)(l * 64 + c) * 32) * 64 + o;
                const float* em = emb + a * 32;
                float acc = 0.f;
#pragma unroll 8
                for (int e = 0; e < 32; e++) acc += em[e] * w[e * 64];
                g_Bv[j] = acc;
            }
        }
    } else {
        // single-block node counting sort by attr, segments padded to 8
        __shared__ int scnt[128], soff[128], spos[128];
        if (tid < 128) { scnt[tid] = 0; spos[tid] = 0; }
        __syncthreads();
        for (int n = tid; n < NN; n += 256) atomicAdd(&scnt[attr[n]], 1);
        __syncthreads();
        int pc = 0;
        if (tid < 128) { pc = (scnt[tid] + 7) & ~7; soff[tid] = pc; }
        __syncthreads();
        for (int off = 1; off < 128; off <<= 1) {
            int v = 0;
            if (tid < 128 && tid >= off) v = soff[tid - off];
            __syncthreads();
            if (tid < 128) soff[tid] += v;
            __syncthreads();
        }
        if (tid < 128) soff[tid] -= pc;  // exclusive, 8-aligned
        __syncthreads();
        for (int i = tid; i < NPAD; i += 256) g_nidx[i] = -1;
        __syncthreads();
        for (int n = tid; n < NN; n += 256) {
            int a = attr[n];
            int p = soff[a] + atomicAdd(&spos[a], 1);
            g_nidx[p] = n;
            g_nattr[p] = a;
        }
    }
}

// -------- zero agg + cleanup sort counters (for next call's hist) --------
__global__ void k_zero() {
    float4 z = make_float4(0.f, 0.f, 0.f, 0.f);
    float4* p = reinterpret_cast<float4*>(g_agg);
    for (int i = blockIdx.x * blockDim.x + threadIdx.x; i < NN * 64;
         i += gridDim.x * blockDim.x)
        p[i] = z;
    for (int i = blockIdx.x * blockDim.x + threadIdx.x; i < NN;
         i += gridDim.x * blockDim.x) {
        g_ecnt[i] = 0; g_eppos[i] = 0;
    }
}

// ---------------- pre (layer 1 only) ----------------
__global__ void __launch_bounds__(256) k_pre(const float* __restrict__ lin1s,
                                             const float* __restrict__ lin1v,
                                             int layer, int cur) {
    __shared__ float sWs[4096], sWv[4096];
    __shared__ float sy[8][256];
    int tid = threadIdx.x;
    const float* Ws = lin1s + layer * 4096;
    const float* Wv = lin1v + layer * 4096;
    for (int k = tid; k < 4096; k += 256) { sWs[k] = Ws[k]; sWv[k] = Wv[k]; }
    const float* ys = g_ys[cur];
    const float* yv = g_yv[cur];
    int n0 = blockIdx.x * 8;
    for (int k = tid; k < 2048; k += 256) {
        int nn = k >> 8, j = k & 255;
        int n = n0 + nn;
        sy[nn][j] = (j < 64) ? ys[n * 64 + j] : yv[n * 192 + j - 64];
    }
    __syncthreads();
    for (int nn = 0; nn < 8; nn++) {
        int n = n0 + nn;
        if (tid < 64) {
            int d = tid;
            float acc = 0.f;
#pragma unroll 8
            for (int c = 0; c < 64; c++) acc += sy[nn][c] * sWs[c * 64 + d];
            g_s1[n * 64 + d] = acc;
        } else {
            int idx = tid - 64;
            int d = idx & 63, xx = idx >> 6;
            float acc = 0.f;
#pragma unroll 8
            for (int c = 0; c < 64; c++) acc += sy[nn][64 + c * 3 + xx] * sWv[c * 64 + d];
            g_v1[n * 192 + xx * 64 + d] = acc;
        }
    }
}

// -------- edge math common (bf16 W2 in smem) --------
__device__ __forceinline__ void edge_core(float ev0, float ev1, float ev2, float l2,
                                          const float* sW1, const float* sb1v,
                                          const unsigned* sW2b, int lane,
                                          float& ea0, float& ea1, float& ea2,
                                          float& w0, float& w1, float& w2, float& w3) {
    const float PI = 3.14159265358979f;
    float elen = sqrtf(l2);
    float safe = fmaxf(elen, 1e-9f);
    float inv = 1.0f / safe;
    float u = 2.f * (elen * (1.0f / MAXR) - 1.f);
    float cut = 0.5f * (1.f - __cosf(PI * u));
    float ca = cut * 1.7320508075688772f * inv;
    ea0 = ca * ev0; ea1 = ca * ev1; ea2 = ca * ev2;
    float th = (PI / MAXR) * safe;
    float sk = __sinf(th), c2 = 2.f * __cosf(th), skm1 = 0.f;
    float fac = 2.5298221281347035f * inv;
    float hs = sb1v[lane];
#pragma unroll
    for (int k = 0; k < 8; k++) {
        hs += (fac * sk) * sW1[k * 32 + lane];
        float t = c2 * sk - skm1; skm1 = sk; sk = t;
    }
    float hval = hs / (1.f + __expf(-hs));  // silu
    w0 = 0.f; w1 = 0.f; w2 = 0.f; w3 = 0.f;
#pragma unroll
    for (int k = 0; k < 32; k++) {
        float hk = __shfl_sync(0xffffffffu, hval, k);
        uint2 uv = *reinterpret_cast<const uint2*>(&sW2b[k * 64 + lane * 2]);
        float2 f01 = __bfloat1622float2(*reinterpret_cast<__nv_bfloat162*>(&uv.x));
        float2 f23 = __bfloat1622float2(*reinterpret_cast<__nv_bfloat162*>(&uv.y));
        w0 = fmaf(hk, f01.x, w0);
        w1 = fmaf(hk, f01.y, w1);
        w2 = fmaf(hk, f23.x, w2);
        w3 = fmaf(hk, f23.y, w3);
    }
}

__device__ __forceinline__ void fill_w2(unsigned* sW2b, const float* rW2, int layer,
                                        int tid) {
    for (int t = tid; t < 2048; t += 256) {
        int k = t >> 6, r = t & 63, ln = r >> 1, g = r & 1;
        const float* base = rW2 + layer * 4096 + k * 128 + g * 64;
        __nv_bfloat162 p = __floats2bfloat162_rn(base[ln], base[32 + ln]);
        sW2b[t] = *reinterpret_cast<unsigned*>(&p);
    }
}

// -------- edge: dst-sorted, register accumulation (both layers) --------
__global__ void __launch_bounds__(256) k_edge(const float* __restrict__ rW1,
                                              const float* __restrict__ rb1,
                                              const float* __restrict__ rW2,
                                              int layer, int skip_s1) {
    __shared__ float sW1[256];
    __shared__ float sb1v[32];
    __shared__ unsigned sW2b[2048];
    int tid = threadIdx.x;
    for (int k = tid; k < 256; k += 256) sW1[k] = rW1[layer * 256 + k];
    if (tid < 32) sb1v[tid] = rb1[layer * 32 + tid];
    fill_w2(sW2b, rW2, layer, tid);
    __syncthreads();
    int lane = tid & 31;
    int warp = (blockIdx.x * 256 + tid) >> 5;
    const int K = 40;
    int e0 = warp * K;
    if (e0 >= NE) return;
    int e1 = e0 + K; if (e1 > NE) e1 = NE;
    float4 acc0 = make_float4(0.f, 0.f, 0.f, 0.f);
    float4 acc1 = make_float4(0.f, 0.f, 0.f, 0.f);
    bool touched = false;
    int cur = -1;
    float dp0 = 0.f, dp1 = 0.f, dp2 = 0.f;
    for (int e = e0; e < e1; e++) {
        int dst = g_sdst[e];
        if (dst != cur) {
            if (touched) {
                float4* ap = reinterpret_cast<float4*>(g_agg + (size_t)cur * 256);
                atomicAdd(ap + lane, acc0);
                atomicAdd(ap + lane + 32, acc1);
                acc0 = make_float4(0.f, 0.f, 0.f, 0.f);
                acc1 = make_float4(0.f, 0.f, 0.f, 0.f);
                touched = false;
            }
            cur = dst;
            dp0 = g_pos[dst * 3 + 0];
            dp1 = g_pos[dst * 3 + 1];
            dp2 = g_pos[dst * 3 + 2];
        }
        int src = g_ssrc[e];
        float ev0 = g_pos[src * 3 + 0] - dp0;
        float ev1 = g_pos[src * 3 + 1] - dp1;
        float ev2 = g_pos[src * 3 + 2] - dp2;
        float l2 = ev0 * ev0 + ev1 * ev1 + ev2 * ev2;
        if (l2 >= MAXR * MAXR) continue;
        float ea0, ea1, ea2, w0, w1, w2, w3;
        edge_core(ev0, ev1, ev2, l2, sW1, sb1v, sW2b, lane, ea0, ea1, ea2, w0, w1, w2, w3);
        float sa = 0.f, sb = 0.f;
        if (!skip_s1) {
            const float* s1p = g_s1 + (size_t)src * 64;
            sa = s1p[lane] * w0;
            sb = s1p[lane + 32] * w1;
        }
        const float* v1p = g_v1 + (size_t)src * 192;
        float da = w2 * (v1p[lane] * ea0 + v1p[64 + lane] * ea1 + v1p[128 + lane] * ea2);
        float db = w3 * (v1p[lane + 32] * ea0 + v1p[96 + lane] * ea1 + v1p[160 + lane] * ea2);
        acc0.x += sa * ea0; acc0.y += sa * ea1; acc0.z += sa * ea2; acc0.w += da;
        acc1.x += sb * ea0; acc1.y += sb * ea1; acc1.z += sb * ea2; acc1.w += db;
        touched = true;
    }
    if (touched) {
        float4* ap = reinterpret_cast<float4*>(g_agg + (size_t)cur * 256);
        atomicAdd(ap + lane, acc0);
        atomicAdd(ap + lane + 32, acc1);
    }
}

// ------ post v6: float4 input LDS, float2 tasks, 3 blocks/SM ------
__global__ void __launch_bounds__(256, 3) k_post(const float* __restrict__ lin2s,
                                                 const float* __restrict__ lin2v,
                                                 const float* __restrict__ sis,
                                                 const float* __restrict__ siv,
                                                 const float* __restrict__ hv,
                                                 const float* __restrict__ mv,
                                                 int layer, int cur,
                                                 float* __restrict__ outp) {
    __shared__ float s_Q[128];
    __shared__ __align__(16) float s_ys[8][64], s_aggs[8][64];
    __shared__ __align__(16) float s_yv[8][192], s_aggv[8][192];   // [xx*64+c]
    __shared__ __align__(16) float s_outs[8][128];
    __shared__ __align__(16) float s_outv[8][192];
    __shared__ __align__(16) float s_y2s[8][64];
    __shared__ __align__(16) float s_y2v[8][192];
    __shared__ float s_newv[8][192];
    int tid = threadIdx.x;
    int wid = tid >> 5;
    if (tid < 128) s_Q[tid] = g_Q[tid];
    float hh = hv[layer] * hv[layer];
    float m = mv[layer];
    float* ys_new = g_ys[cur ^ 1];
    float* yv_new = g_yv[cur ^ 1];
    const float* ys_cur = g_ys[cur];
    const float* yv_cur = g_yv[cur];
    for (int it = 0; it < 2; it++) {
        int pbase = blockIdx.x * 16 + it * 8;
        // ---- stage ----
        for (int t = tid; t < 512; t += 256) {
            int node = t >> 6, j = t & 63;
            int n = g_nidx[pbase + node];
            if (n >= 0) {
                s_ys[node][j] = ys_cur[n * 64 + j];
                float4 a4 = ((const float4*)g_agg)[n * 64 + j];
                s_aggs[node][j] = a4.w * INV_NN;
                s_aggv[node][j] = a4.x * INV_NN;
                s_aggv[node][64 + j] = a4.y * INV_NN;
                s_aggv[node][128 + j] = a4.z * INV_NN;
                const float* yvp = yv_cur + n * 192 + j * 3;
                s_yv[node][j] = yvp[0];
                s_yv[node][64 + j] = yvp[1];
                s_yv[node][128 + j] = yvp[2];
            }
        }
        __syncthreads();
        int a = g_nattr[pbase];   // chunk is attr-uniform
        if (wid < 5) {
            // two-matrix float2 tasks: outs (tid<64), outv (64..159)
            const float2 *wp, *bp;
            int wstr;
            const float *in1, *in2;
            int istr;
            float2* o2;
            int ostr;
            if (tid < 64) {
                int j = tid;
                wp = (const float2*)(lin2s + layer * 8192) + j;
                bp = (const float2*)(g_Bs + (size_t)(layer * 100 + a) * 8192) + j;
                wstr = 64;
                in1 = &s_aggs[0][0]; in2 = &s_ys[0][0]; istr = 64;
                o2 = (float2*)&s_outs[0][0] + j; ostr = 64;
            } else {
                int id = tid - 64, xx = id >> 5, j = id & 31;
                wp = (const float2*)(lin2v + layer * 4096) + j;
                bp = (const float2*)(g_Bv + (size_t)(layer * 100 + a) * 4096) + j;
                wstr = 32;
                in1 = &s_aggv[0][xx * 64]; in2 = &s_yv[0][xx * 64]; istr = 192;
                o2 = (float2*)&s_outv[0][0] + xx * 32 + j; ostr = 96;
            }
            float2 acc[8];
#pragma unroll
            for (int nn = 0; nn < 8; nn++) acc[nn] = make_float2(0.f, 0.f);
            for (int c = 0; c < 64; c += 4) {
                float2 w0 = __ldg(wp + (c + 0) * wstr);
                float2 w1 = __ldg(wp + (c + 1) * wstr);
                float2 w2 = __ldg(wp + (c + 2) * wstr);
                float2 w3 = __ldg(wp + (c + 3) * wstr);
                float2 b0 = __ldg(bp + (c + 0) * wstr);
                float2 b1 = __ldg(bp + (c + 1) * wstr);
                float2 b2 = __ldg(bp + (c + 2) * wstr);
                float2 b3 = __ldg(bp + (c + 3) * wstr);
#pragma unroll
                for (int nn = 0; nn < 8; nn++) {
                    float4 u1 = *(const float4*)(in1 + nn * istr + c);
                    float4 u2 = *(const float4*)(in2 + nn * istr + c);
                    acc[nn].x += u1.x * w0.x + u2.x * b0.x;
                    acc[nn].y += u1.x * w0.y + u2.x * b0.y;
                    acc[nn].x += u1.y * w1.x + u2.y * b1.x;
                    acc[nn].y += u1.y * w1.y + u2.y * b1.y;
                    acc[nn].x += u1.z * w2.x + u2.z * b2.x;
                    acc[nn].y += u1.z * w2.y + u2.z * b2.y;
                    acc[nn].x += u1.w * w3.x + u2.w * b3.x;
                    acc[nn].y += u1.w * w3.y + u2.w * b3.y;
                }
            }
#pragma unroll
            for (int nn = 0; nn < 8; nn++) o2[nn * ostr] = acc[nn];
        } else if (wid == 5) {
            // y2s: single-matrix float2, tid 160..191
            int j = tid - 160;
            const float2* wp = (const float2*)(sis + layer * 4096) + j;
            float2 acc[8];
#pragma unroll
            for (int nn = 0; nn < 8; nn++) acc[nn] = make_float2(0.f, 0.f);
            for (int c = 0; c < 64; c += 4) {
                float2 w0 = __ldg(wp + (c + 0) * 32);
                float2 w1 = __ldg(wp + (c + 1) * 32);
                float2 w2 = __ldg(wp + (c + 2) * 32);
                float2 w3 = __ldg(wp + (c + 3) * 32);
#pragma unroll
                for (int nn = 0; nn < 8; nn++) {
                    float4 u = *(const float4*)(&s_ys[nn][c]);
                    acc[nn].x += u.x * w0.x + u.y * w1.x + u.z * w2.x + u.w * w3.x;
                    acc[nn].y += u.x * w0.y + u.y * w1.y + u.z * w2.y + u.w * w3.y;
                }
            }
#pragma unroll
            for (int nn = 0; nn < 8; nn++)
                ((float2*)&s_y2s[0][0])[nn * 32 + j] = acc[nn];
        } else if (tid < 240) {
            // y2v: single-matrix float4, tid 192..239
            int id = tid - 192, xx = id >> 4, j = id & 15;
            const float4* wp = (const float4*)(siv + layer * 4096) + j;
            const float* in = &s_yv[0][xx * 64];
            float4 acc[8];
#pragma unroll
            for (int nn = 0; nn < 8; nn++) acc[nn] = make_float4(0.f, 0.f, 0.f, 0.f);
            for (int c = 0; c < 64; c += 4) {
                float4 w0 = __ldg(wp + (c + 0) * 16);
                float4 w1 = __ldg(wp + (c + 1) * 16);
                float4 w2 = __ldg(wp + (c + 2) * 16);
                float4 w3 = __ldg(wp + (c + 3) * 16);
#pragma unroll
                for (int nn = 0; nn < 8; nn++) {
                    float4 u = *(const float4*)(in + nn * 192 + c);
                    acc[nn].x += u.x * w0.x + u.y * w1.x + u.z * w2.x + u.w * w3.x;
                    acc[nn].y += u.x * w0.y + u.y * w1.y + u.z * w2.y + u.w * w3.y;
                    acc[nn].z += u.x * w0.z + u.y * w1.z + u.z * w2.z + u.w * w3.z;
                    acc[nn].w += u.x * w0.w + u.y * w1.w + u.z * w2.w + u.w * w3.w;
                }
            }
#pragma unroll
            for (int nn = 0; nn < 8; nn++)
                ((float4*)&s_y2v[0][0])[nn * 48 + xx * 16 + j] = acc[nn];
        }
        __syncthreads();
        // ---- state update ----
        for (int t = tid; t < 512; t += 256) {
            int node = t >> 6, c = t & 63;
            int n = g_nidx[pbase + node];
            if (n >= 0) {
                float os = s_outs[node][c];
                float gs = os / (1.f + __expf(-os));
                float gate = 1.f / (1.f + __expf(-s_outs[node][64 + c]));
                float yo = ys_new[n * 64 + c];
                float ns = 2.f * s_ys[node][c] - yo + hh * (m * gs + (m - 1.f) * s_y2s[node][c]);
                ys_new[n * 64 + c] = ns;
#pragma unroll
                for (int xx = 0; xx < 3; xx++) {
                    float yov = yv_new[n * 192 + c * 3 + xx];
                    float nv = 2.f * s_yv[node][xx * 64 + c] - yov +
                               hh * (m * gate * s_outv[node][xx * 64 + c] +
                                     (m - 1.f) * s_y2v[node][xx * 64 + c]);
                    yv_new[n * 192 + c * 3 + xx] = nv;
                    s_newv[node][xx * 64 + c] = nv;
                }
            }
        }
        __syncthreads();
        // ---- projection ----
        if (tid < 48) {
            int node = tid / 6, r = tid % 6, k = r / 3, xx = r % 3;
            int n = g_nidx[pbase + node];
            if (n >= 0) {
                float acc = 0.f;
#pragma unroll 8
                for (int c = 0; c < 64; c++) acc += s_newv[node][xx * 64 + c] * s_Q[c * 2 + k];
                if (layer == 0) {
                    if (k == 0) g_pos[n * 3 + xx] = acc;
                } else {
                    outp[n * 6 + k * 3 + xx] = acc;
                }
            }
        }
        __syncthreads();
    }
}

// ---------------- launch ----------------
extern "C" void kernel_launch(void* const* d_in, const int* in_sizes, int n_in,
                              void* d_out, int out_size) {
    const float* x        = (const float*)d_in[0];
    const int*   attr     = (const int*)d_in[2];
    const int*   esrc     = (const int*)d_in[3];
    const int*   edst     = (const int*)d_in[4];
    const float* emb      = (const float*)d_in[5];
    const float* uplift   = (const float*)d_in[6];
    const float* h        = (const float*)d_in[7];
    const float* mix      = (const float*)d_in[8];
    const float* rW1      = (const float*)d_in[9];
    const float* rb1      = (const float*)d_in[10];
    const float* rW2      = (const float*)d_in[11];
    const float* lin1s    = (const float*)d_in[12];
    const float* lin1v    = (const float*)d_in[13];
    const float* lin2s    = (const float*)d_in[14];
    const float* lin2v    = (const float*)d_in[15];
    const float* scs      = (const float*)d_in[16];
    const float* scv      = (const float*)d_in[17];
    const float* sis      = (const float*)d_in[18];
    const float* siv      = (const float*)d_in[19];
    float* out = (float*)d_out;

    const int PB = NPAD / 16;  // 1300

    k_hist_e<<<1280, 256>>>(edst);                                  // 0 (counters pre-zeroed)
    k_scan_e<<<1, 512>>>();                                         // 1
    k_scat_e<<<1280, 256>>>(esrc, edst);                            // 2
    k_init<<<7401, 256>>>(x, uplift, emb, scs, scv, lin1v, attr);   // 3 <- profiled
    k_edge<<<2000, 256>>>(rW1, rb1, rW2, 0, 1);                     // 4 (layer0, s1==0)
    k_post<<<PB, 256>>>(lin2s, lin2v, sis, siv, h, mix, 0, 0, out); // 5
    k_zero<<<1024, 256>>>();                                        // 6 (agg + counter cleanup)
    k_pre<<<NN / 8, 256>>>(lin1s, lin1v, 1, 1);                     // 7
    k_edge<<<2000, 256>>>(rW1, rb1, rW2, 1, 0);                     // 8
    k_post<<<PB, 256>>>(lin2s, lin2v, sis, siv, h, mix, 1, 1, out); // 9
}

// round 9
// speedup vs baseline: 3.2871x; 1.0426x over previous
#include <cuda_runtime.h>
#include <cuda_bf16.h>
#include <math.h>

#define NN 20000
#define NE 640000
#define NL 2
#define MAXR 2.5f
#define INV_NN 0.17677669529663687f   // 1/sqrt(32)
#define NPAD 20800                    // attr-sorted node list padded to 8-aligned segments

// ---------------- scratch (device globals; no allocs) ----------------
static __device__ float g_Q[64 * 2];
static __device__ float g_ys[2][NN * 64];
static __device__ float g_yv[2][NN * 192];
static __device__ float g_s1[NN * 64];
static __device__ float g_v1[NN * 192];          // [n][3][64] x-major
static __device__ float g_agg[NN * 256];         // (n, c, 4): vx,vy,vz,s
static __device__ float g_pos[NN * 3];
static __device__ float g_Bs[NL * 100 * 64 * 128];
static __device__ float g_Bv[NL * 100 * 64 * 64];
// edge sort (by dst); counters zeroed by k_pre of the PREVIOUS call (.bss on first)
static __device__ int g_ecnt[NN];
static __device__ int g_eoff[NN];
static __device__ int g_eppos[NN];
static __device__ int g_ssrc[NE];
static __device__ int g_sdst[NE];
// node sort (by attr), 8-aligned segments, -1 = sentinel
static __device__ int g_nidx[NPAD];
static __device__ int g_nattr[NPAD];

// ---- fused init: Q + y init + layer0 v1 + B precompute + node sort + edge hist ----
__global__ void __launch_bounds__(256) k_init(const float* __restrict__ x,
                                              const float* __restrict__ M,
                                              const float* __restrict__ emb,
                                              const float* __restrict__ scs,
                                              const float* __restrict__ scv,
                                              const float* __restrict__ lin1v,
                                              const int* __restrict__ attr,
                                              const int* __restrict__ edst) {
    int tid = threadIdx.x;
    if (blockIdx.x < 5000) {
        __shared__ double dI[3];
        __shared__ float sQ[128];
        __shared__ float sR[128];
        if (tid < 32) {
            double m0a = M[2 * tid], m1a = M[2 * tid + 1];
            double m0b = M[2 * (tid + 32)], m1b = M[2 * (tid + 32) + 1];
            double pa = m0a * m0a + m0b * m0b;
            double pb = m0a * m1a + m0b * m1b;
            double pc = m1a * m1a + m1b * m1b;
#pragma unroll
            for (int off = 16; off > 0; off >>= 1) {
                pa += __shfl_down_sync(0xffffffffu, pa, off);
                pb += __shfl_down_sync(0xffffffffu, pb, off);
                pc += __shfl_down_sync(0xffffffffu, pc, off);
            }
            if (tid == 0) {
                double det = pa * pc - pb * pb;
                double s = sqrt(det);
                double t = pa + pc;
                double denom = sqrt(t + 2.0 * s);
                double p00 = (pa + s) / denom, p01 = pb / denom, p11 = (pc + s) / denom;
                double pdet = p00 * p11 - p01 * p01;
                dI[0] = p11 / pdet; dI[1] = -p01 / pdet; dI[2] = p00 / pdet;
            }
        }
        __syncthreads();
        if (tid < 64) {
            double m0 = M[2 * tid], m1 = M[2 * tid + 1];
            sQ[2 * tid]     = (float)(m0 * dI[0] + m1 * dI[1]);
            sQ[2 * tid + 1] = (float)(m0 * dI[1] + m1 * dI[2]);
        }
        __syncthreads();
        if (blockIdx.x == 0 && tid < 128) g_Q[tid] = sQ[tid];
        if (tid < 128) {
            int k = tid >> 6, d = tid & 63;
            float acc = 0.f;
#pragma unroll 8
            for (int c = 0; c < 64; c++) acc += sQ[c * 2 + k] * lin1v[c * 64 + d];
            sR[k * 64 + d] = acc;
        }
        __syncthreads();
        int i = blockIdx.x * 256 + tid;
        if (i >= NN * 64) return;
        int n = i >> 6, c = i & 63;
        float q0 = sQ[c * 2], q1 = sQ[c * 2 + 1];
        const float* xp = x + n * 6;
        float v0 = xp[0] * q0 + xp[3] * q1;
        float v1 = xp[1] * q0 + xp[4] * q1;
        float v2 = xp[2] * q0 + xp[5] * q1;
        int base = n * 192 + c * 3;
        g_yv[0][base + 0] = v0; g_yv[0][base + 1] = v1; g_yv[0][base + 2] = v2;
        g_yv[1][base + 0] = v0; g_yv[1][base + 1] = v1; g_yv[1][base + 2] = v2;
        g_ys[0][i] = 0.f; g_ys[1][i] = 0.f;
        if (c < 3) g_pos[n * 3 + c] = xp[c];
        reinterpret_cast<float4*>(g_agg)[i] = make_float4(0.f, 0.f, 0.f, 0.f);
        int d = c;
        float r0 = sR[d], r1 = sR[64 + d];
#pragma unroll
        for (int xx = 0; xx < 3; xx++)
            g_v1[n * 192 + xx * 64 + d] = xp[xx] * r0 + xp[3 + xx] * r1;
    } else if (blockIdx.x < 7400) {
        const int TOTS = NL * 100 * 64 * 128;
        const int TOTV = NL * 100 * 64 * 64;
        const int NB = 2400;
        for (int idx = (blockIdx.x - 5000) * 256 + tid; idx < TOTS + TOTV;
             idx += NB * 256) {
            if (idx < TOTS) {
                int o = idx & 127;
                int c = (idx >> 7) & 63;
                int a = (idx >> 13) % 100;
                int l = idx / (128 * 64 * 100);
                const float* w = scs + ((size_t)(l * 64 + c) * 32) * 128 + o;
                const float* em = emb + a * 32;
                float acc = 0.f;
#pragma unroll 8
                for (int e = 0; e < 32; e++) acc += em[e] * w[e * 128];
                g_Bs[idx] = acc;
            } else {
                int j = idx - TOTS;
                int o = j & 63;
                int c = (j >> 6) & 63;
                int a = (j >> 12) % 100;
                int l = j / (64 * 64 * 100);
                const float* w = scv + ((size_t)(l * 64 + c) * 32) * 64 + o;
                const float* em = emb + a * 32;
                float acc = 0.f;
#pragma unroll 8
                for (int e = 0; e < 32; e++) acc += em[e] * w[e * 64];
                g_Bv[j] = acc;
            }
        }
    } else if (blockIdx.x == 7400) {
        // single-block node counting sort by attr, segments padded to 8
        __shared__ int scnt[128], soff[128], spos[128];
        if (tid < 128) { scnt[tid] = 0; spos[tid] = 0; }
        __syncthreads();
        for (int n = tid; n < NN; n += 256) atomicAdd(&scnt[attr[n]], 1);
        __syncthreads();
        int pc = 0;
        if (tid < 128) { pc = (scnt[tid] + 7) & ~7; soff[tid] = pc; }
        __syncthreads();
        for (int off = 1; off < 128; off <<= 1) {
            int v = 0;
            if (tid < 128 && tid >= off) v = soff[tid - off];
            __syncthreads();
            if (tid < 128) soff[tid] += v;
            __syncthreads();
        }
        if (tid < 128) soff[tid] -= pc;  // exclusive, 8-aligned
        __syncthreads();
        for (int i = tid; i < NPAD; i += 256) g_nidx[i] = -1;
        __syncthreads();
        for (int n = tid; n < NN; n += 256) {
            int a = attr[n];
            int p = soff[a] + atomicAdd(&spos[a], 1);
            g_nidx[p] = n;
            g_nattr[p] = a;
        }
    } else {
        // edge histogram (counters pre-zeroed by previous call / .bss)
        for (int e = (blockIdx.x - 7401) * 256 + tid; e < NE; e += 1280 * 256)
            atomicAdd(&g_ecnt[edst[e]], 1);
    }
}

// ---------------- edge offset scan / scatter ----------------
__global__ void __launch_bounds__(512) k_scan_e() {
    __shared__ int sp[512];
    int t = threadIdx.x;
    const int CH = 40;
    int base = t * CH;
    int part = 0;
    for (int i = 0; i < CH; i++) {
        int idx = base + i;
        if (idx < NN) part += g_ecnt[idx];
    }
    sp[t] = part;
    __syncthreads();
    for (int off = 1; off < 512; off <<= 1) {
        int v = (t >= off) ? sp[t - off] : 0;
        __syncthreads();
        sp[t] += v;
        __syncthreads();
    }
    int run = sp[t] - part;
    for (int i = 0; i < CH; i++) {
        int idx = base + i;
        if (idx < NN) { g_eoff[idx] = run; run += g_ecnt[idx]; }
    }
}
__global__ void k_scat_e(const int* __restrict__ esrc, const int* __restrict__ edst) {
    for (int e = blockIdx.x * 256 + threadIdx.x; e < NE; e += 1280 * 256) {
        int d = edst[e];
        int p = g_eoff[d] + atomicAdd(&g_eppos[d], 1);
        g_ssrc[p] = esrc[e];
        g_sdst[p] = d;
    }
}

// ------- pre (layer 1) + sort-counter cleanup for next call's hist -------
__global__ void __launch_bounds__(256) k_pre(const float* __restrict__ lin1s,
                                             const float* __restrict__ lin1v,
                                             int layer, int cur) {
    __shared__ float sWs[4096], sWv[4096];
    __shared__ float sy[8][256];
    int tid = threadIdx.x;
    {
        int i = blockIdx.x * 256 + tid;
        if (i < NN) { g_ecnt[i] = 0; g_eppos[i] = 0; }
    }
    const float* Ws = lin1s + layer * 4096;
    const float* Wv = lin1v + layer * 4096;
    for (int k = tid; k < 4096; k += 256) { sWs[k] = Ws[k]; sWv[k] = Wv[k]; }
    const float* ys = g_ys[cur];
    const float* yv = g_yv[cur];
    int n0 = blockIdx.x * 8;
    for (int k = tid; k < 2048; k += 256) {
        int nn = k >> 8, j = k & 255;
        int n = n0 + nn;
        sy[nn][j] = (j < 64) ? ys[n * 64 + j] : yv[n * 192 + j - 64];
    }
    __syncthreads();
    for (int nn = 0; nn < 8; nn++) {
        int n = n0 + nn;
        if (tid < 64) {
            int d = tid;
            float acc = 0.f;
#pragma unroll 8
            for (int c = 0; c < 64; c++) acc += sy[nn][c] * sWs[c * 64 + d];
            g_s1[n * 64 + d] = acc;
        } else {
            int idx = tid - 64;
            int d = idx & 63, xx = idx >> 6;
            float acc = 0.f;
#pragma unroll 8
            for (int c = 0; c < 64; c++) acc += sy[nn][64 + c * 3 + xx] * sWv[c * 64 + d];
            g_v1[n * 192 + xx * 64 + d] = acc;
        }
    }
}

// -------- edge math common (bf16 W2 + HFMA2 accumulation) --------
__device__ __forceinline__ void edge_core(float ev0, float ev1, float ev2, float l2,
                                          const float* sW1, const float* sb1v,
                                          const unsigned* sW2b, int lane,
                                          float& ea0, float& ea1, float& ea2,
                                          float& w0, float& w1, float& w2, float& w3) {
    const float PI = 3.14159265358979f;
    float elen = sqrtf(l2);
    float safe = fmaxf(elen, 1e-9f);
    float inv = 1.0f / safe;
    float u = 2.f * (elen * (1.0f / MAXR) - 1.f);
    float cut = 0.5f * (1.f - __cosf(PI * u));
    float ca = cut * 1.7320508075688772f * inv;
    ea0 = ca * ev0; ea1 = ca * ev1; ea2 = ca * ev2;
    float th = (PI / MAXR) * safe;
    float sk = __sinf(th), c2 = 2.f * __cosf(th), skm1 = 0.f;
    float fac = 2.5298221281347035f * inv;
    float hs = sb1v[lane];
#pragma unroll
    for (int k = 0; k < 8; k++) {
        hs += (fac * sk) * sW1[k * 32 + lane];
        float t = c2 * sk - skm1; skm1 = sk; sk = t;
    }
    float hval = hs / (1.f + __expf(-hs));  // silu
    // duplicated bf16x2 of hval, shuffled per k; HFMA2 accumulation (2 chains)
    __nv_bfloat162 hd = __float2bfloat162_rn(hval);
    unsigned hdu = *reinterpret_cast<unsigned*>(&hd);
    __nv_bfloat162 z; z.x = __float2bfloat16(0.f); z.y = z.x;
    __nv_bfloat162 a01e = z, a01o = z, a23e = z, a23o = z;
#pragma unroll
    for (int k = 0; k < 32; k += 2) {
        unsigned hpe = __shfl_sync(0xffffffffu, hdu, k);
        unsigned hpo = __shfl_sync(0xffffffffu, hdu, k + 1);
        uint2 uve = *reinterpret_cast<const uint2*>(&sW2b[k * 64 + lane * 2]);
        uint2 uvo = *reinterpret_cast<const uint2*>(&sW2b[(k + 1) * 64 + lane * 2]);
        a01e = __hfma2(*reinterpret_cast<__nv_bfloat162*>(&hpe),
                       *reinterpret_cast<__nv_bfloat162*>(&uve.x), a01e);
        a23e = __hfma2(*reinterpret_cast<__nv_bfloat162*>(&hpe),
                       *reinterpret_cast<__nv_bfloat162*>(&uve.y), a23e);
        a01o = __hfma2(*reinterpret_cast<__nv_bfloat162*>(&hpo),
                       *reinterpret_cast<__nv_bfloat162*>(&uvo.x), a01o);
        a23o = __hfma2(*reinterpret_cast<__nv_bfloat162*>(&hpo),
                       *reinterpret_cast<__nv_bfloat162*>(&uvo.y), a23o);
    }
    float2 f01e = __bfloat1622float2(a01e), f01o = __bfloat1622float2(a01o);
    float2 f23e = __bfloat1622float2(a23e), f23o = __bfloat1622float2(a23o);
    w0 = f01e.x + f01o.x; w1 = f01e.y + f01o.y;
    w2 = f23e.x + f23o.x; w3 = f23e.y + f23o.y;
}

__device__ __forceinline__ void fill_w2(unsigned* sW2b, const float* rW2, int layer,
                                        int tid) {
    for (int t = tid; t < 2048; t += 256) {
        int k = t >> 6, r = t & 63, ln = r >> 1, g = r & 1;
        const float* base = rW2 + layer * 4096 + k * 128 + g * 64;
        __nv_bfloat162 p = __floats2bfloat162_rn(base[ln], base[32 + ln]);
        sW2b[t] = *reinterpret_cast<unsigned*>(&p);
    }
}

// -------- edge: dst-sorted, register accumulation (both layers) --------
__global__ void __launch_bounds__(256) k_edge(const float* __restrict__ rW1,
                                              const float* __restrict__ rb1,
                                              const float* __restrict__ rW2,
                                              int layer, int skip_s1) {
    __shared__ float sW1[256];
    __shared__ float sb1v[32];
    __shared__ unsigned sW2b[2048];
    int tid = threadIdx.x;
    for (int k = tid; k < 256; k += 256) sW1[k] = rW1[layer * 256 + k];
    if (tid < 32) sb1v[tid] = rb1[layer * 32 + tid];
    fill_w2(sW2b, rW2, layer, tid);
    __syncthreads();
    int lane = tid & 31;
    int warp = (blockIdx.x * 256 + tid) >> 5;
    const int K = 40;
    int e0 = warp * K;
    if (e0 >= NE) return;
    int e1 = e0 + K; if (e1 > NE) e1 = NE;
    float4 acc0 = make_float4(0.f, 0.f, 0.f, 0.f);
    float4 acc1 = make_float4(0.f, 0.f, 0.f, 0.f);
    bool touched = false;
    int cur = -1;
    float dp0 = 0.f, dp1 = 0.f, dp2 = 0.f;
    for (int e = e0; e < e1; e++) {
        int dst = g_sdst[e];
        if (dst != cur) {
            if (touched) {
                float4* ap = reinterpret_cast<float4*>(g_agg + (size_t)cur * 256);
                atomicAdd(ap + lane, acc0);
                atomicAdd(ap + lane + 32, acc1);
                acc0 = make_float4(0.f, 0.f, 0.f, 0.f);
                acc1 = make_float4(0.f, 0.f, 0.f, 0.f);
                touched = false;
            }
            cur = dst;
            dp0 = g_pos[dst * 3 + 0];
            dp1 = g_pos[dst * 3 + 1];
            dp2 = g_pos[dst * 3 + 2];
        }
        int src = g_ssrc[e];
        float ev0 = g_pos[src * 3 + 0] - dp0;
        float ev1 = g_pos[src * 3 + 1] - dp1;
        float ev2 = g_pos[src * 3 + 2] - dp2;
        float l2 = ev0 * ev0 + ev1 * ev1 + ev2 * ev2;
        if (l2 >= MAXR * MAXR) continue;
        float ea0, ea1, ea2, w0, w1, w2, w3;
        edge_core(ev0, ev1, ev2, l2, sW1, sb1v, sW2b, lane, ea0, ea1, ea2, w0, w1, w2, w3);
        float sa = 0.f, sb = 0.f;
        if (!skip_s1) {
            const float* s1p = g_s1 + (size_t)src * 64;
            sa = s1p[lane] * w0;
            sb = s1p[lane + 32] * w1;
        }
        const float* v1p = g_v1 + (size_t)src * 192;
        float da = w2 * (v1p[lane] * ea0 + v1p[64 + lane] * ea1 + v1p[128 + lane] * ea2);
        float db = w3 * (v1p[lane + 32] * ea0 + v1p[96 + lane] * ea1 + v1p[160 + lane] * ea2);
        acc0.x += sa * ea0; acc0.y += sa * ea1; acc0.z += sa * ea2; acc0.w += da;
        acc1.x += sb * ea0; acc1.y += sb * ea1; acc1.z += sb * ea2; acc1.w += db;
        touched = true;
    }
    if (touched) {
        float4* ap = reinterpret_cast<float4*>(g_agg + (size_t)cur * 256);
        atomicAdd(ap + lane, acc0);
        atomicAdd(ap + lane + 32, acc1);
    }
}

// ------ post v7: float4 input LDS, float2 tasks, zeroes agg (layer 0) ------
__global__ void __launch_bounds__(256, 3) k_post(const float* __restrict__ lin2s,
                                                 const float* __restrict__ lin2v,
                                                 const float* __restrict__ sis,
                                                 const float* __restrict__ siv,
                                                 const float* __restrict__ hv,
                                                 const float* __restrict__ mv,
                                                 int layer, int cur,
                                                 float* __restrict__ outp) {
    __shared__ float s_Q[128];
    __shared__ __align__(16) float s_ys[8][64], s_aggs[8][64];
    __shared__ __align__(16) float s_yv[8][192], s_aggv[8][192];   // [xx*64+c]
    __shared__ __align__(16) float s_outs[8][128];
    __shared__ __align__(16) float s_outv[8][192];
    __shared__ __align__(16) float s_y2s[8][64];
    __shared__ __align__(16) float s_y2v[8][192];
    __shared__ float s_newv[8][192];
    int tid = threadIdx.x;
    int wid = tid >> 5;
    if (tid < 128) s_Q[tid] = g_Q[tid];
    float hh = hv[layer] * hv[layer];
    float m = mv[layer];
    float* ys_new = g_ys[cur ^ 1];
    float* yv_new = g_yv[cur ^ 1];
    const float* ys_cur = g_ys[cur];
    const float* yv_cur = g_yv[cur];
    for (int it = 0; it < 2; it++) {
        int pbase = blockIdx.x * 16 + it * 8;
        // ---- stage (and zero agg for next layer's accumulation) ----
        for (int t = tid; t < 512; t += 256) {
            int node = t >> 6, j = t & 63;
            int n = g_nidx[pbase + node];
            if (n >= 0) {
                s_ys[node][j] = ys_cur[n * 64 + j];
                float4 a4 = ((const float4*)g_agg)[n * 64 + j];
                if (layer == 0)
                    ((float4*)g_agg)[n * 64 + j] = make_float4(0.f, 0.f, 0.f, 0.f);
                s_aggs[node][j] = a4.w * INV_NN;
                s_aggv[node][j] = a4.x * INV_NN;
                s_aggv[node][64 + j] = a4.y * INV_NN;
                s_aggv[node][128 + j] = a4.z * INV_NN;
                const float* yvp = yv_cur + n * 192 + j * 3;
                s_yv[node][j] = yvp[0];
                s_yv[node][64 + j] = yvp[1];
                s_yv[node][128 + j] = yvp[2];
            }
        }
        __syncthreads();
        int a = g_nattr[pbase];   // chunk is attr-uniform
        if (wid < 5) {
            const float2 *wp, *bp;
            int wstr;
            const float *in1, *in2;
            int istr;
            float2* o2;
            int ostr;
            if (tid < 64) {
                int j = tid;
                wp = (const float2*)(lin2s + layer * 8192) + j;
                bp = (const float2*)(g_Bs + (size_t)(layer * 100 + a) * 8192) + j;
                wstr = 64;
                in1 = &s_aggs[0][0]; in2 = &s_ys[0][0]; istr = 64;
                o2 = (float2*)&s_outs[0][0] + j; ostr = 64;
            } else {
                int id = tid - 64, xx = id >> 5, j = id & 31;
                wp = (const float2*)(lin2v + layer * 4096) + j;
                bp = (const float2*)(g_Bv + (size_t)(layer * 100 + a) * 4096) + j;
                wstr = 32;
                in1 = &s_aggv[0][xx * 64]; in2 = &s_yv[0][xx * 64]; istr = 192;
                o2 = (float2*)&s_outv[0][0] + xx * 32 + j; ostr = 96;
            }
            float2 acc[8];
#pragma unroll
            for (int nn = 0; nn < 8; nn++) acc[nn] = make_float2(0.f, 0.f);
            for (int c = 0; c < 64; c += 4) {
                float2 w0 = __ldg(wp + (c + 0) * wstr);
                float2 w1 = __ldg(wp + (c + 1) * wstr);
                float2 w2 = __ldg(wp + (c + 2) * wstr);
                float2 w3 = __ldg(wp + (c + 3) * wstr);
                float2 b0 = __ldg(bp + (c + 0) * wstr);
                float2 b1 = __ldg(bp + (c + 1) * wstr);
                float2 b2 = __ldg(bp + (c + 2) * wstr);
                float2 b3 = __ldg(bp + (c + 3) * wstr);
#pragma unroll
                for (int nn = 0; nn < 8; nn++) {
                    float4 u1 = *(const float4*)(in1 + nn * istr + c);
                    float4 u2 = *(const float4*)(in2 + nn * istr + c);
                    acc[nn].x += u1.x * w0.x + u2.x * b0.x;
                    acc[nn].y += u1.x * w0.y + u2.x * b0.y;
                    acc[nn].x += u1.y * w1.x + u2.y * b1.x;
                    acc[nn].y += u1.y * w1.y + u2.y * b1.y;
                    acc[nn].x += u1.z * w2.x + u2.z * b2.x;
                    acc[nn].y += u1.z * w2.y + u2.z * b2.y;
                    acc[nn].x += u1.w * w3.x + u2.w * b3.x;
                    acc[nn].y += u1.w * w3.y + u2.w * b3.y;
                }
            }
#pragma unroll
            for (int nn = 0; nn < 8; nn++) o2[nn * ostr] = acc[nn];
        } else if (wid == 5) {
            int j = tid - 160;
            const float2* wp = (const float2*)(sis + layer * 4096) + j;
            float2 acc[8];
#pragma unroll
            for (int nn = 0; nn < 8; nn++) acc[nn] = make_float2(0.f, 0.f);
            for (int c = 0; c < 64; c += 4) {
                float2 w0 = __ldg(wp + (c + 0) * 32);
                float2 w1 = __ldg(wp + (c + 1) * 32);
                float2 w2 = __ldg(wp + (c + 2) * 32);
                float2 w3 = __ldg(wp + (c + 3) * 32);
#pragma unroll
                for (int nn = 0; nn < 8; nn++) {
                    float4 u = *(const float4*)(&s_ys[nn][c]);
                    acc[nn].x += u.x * w0.x + u.y * w1.x + u.z * w2.x + u.w * w3.x;
                    acc[nn].y += u.x * w0.y + u.y * w1.y + u.z * w2.y + u.w * w3.y;
                }
            }
#pragma unroll
            for (int nn = 0; nn < 8; nn++)
                ((float2*)&s_y2s[0][0])[nn * 32 + j] = acc[nn];
        } else if (tid < 240) {
            int id = tid - 192, xx = id >> 4, j = id & 15;
            const float4* wp = (const float4*)(siv + layer * 4096) + j;
            const float* in = &s_yv[0][xx * 64];
            float4 acc[8];
#pragma unroll
            for (int nn = 0; nn < 8; nn++) acc[nn] = make_float4(0.f, 0.f, 0.f, 0.f);
            for (int c = 0; c < 64; c += 4) {
                float4 w0 = __ldg(wp + (c + 0) * 16);
                float4 w1 = __ldg(wp + (c + 1) * 16);
                float4 w2 = __ldg(wp + (c + 2) * 16);
                float4 w3 = __ldg(wp + (c + 3) * 16);
#pragma unroll
                for (int nn = 0; nn < 8; nn++) {
                    float4 u = *(const float4*)(in + nn * 192 + c);
                    acc[nn].x += u.x * w0.x + u.y * w1.x + u.z * w2.x + u.w * w3.x;
                    acc[nn].y += u.x * w0.y + u.y * w1.y + u.z * w2.y + u.w * w3.y;
                    acc[nn].z += u.x * w0.z + u.y * w1.z + u.z * w2.z + u.w * w3.z;
                    acc[nn].w += u.x * w0.w + u.y * w1.w + u.z * w2.w + u.w * w3.w;
                }
            }
#pragma unroll
            for (int nn = 0; nn < 8; nn++)
                ((float4*)&s_y2v[0][0])[nn * 48 + xx * 16 + j] = acc[nn];
        }
        __syncthreads();
        // ---- state update ----
        for (int t = tid; t < 512; t += 256) {
            int node = t >> 6, c = t & 63;
            int n = g_nidx[pbase + node];
            if (n >= 0) {
                float os = s_outs[node][c];
                float gs = os / (1.f + __expf(-os));
                float gate = 1.f / (1.f + __expf(-s_outs[node][64 + c]));
                float yo = ys_new[n * 64 + c];
                float ns = 2.f * s_ys[node][c] - yo + hh * (m * gs + (m - 1.f) * s_y2s[node][c]);
                ys_new[n * 64 + c] = ns;
#pragma unroll
                for (int xx = 0; xx < 3; xx++) {
                    float yov = yv_new[n * 192 + c * 3 + xx];
                    float nv = 2.f * s_yv[node][xx * 64 + c] - yov +
                               hh * (m * gate * s_outv[node][xx * 64 + c] +
                                     (m - 1.f) * s_y2v[node][xx * 64 + c]);
                    yv_new[n * 192 + c * 3 + xx] = nv;
                    s_newv[node][xx * 64 + c] = nv;
                }
            }
        }
        __syncthreads();
        // ---- projection ----
        if (tid < 48) {
            int node = tid / 6, r = tid % 6, k = r / 3, xx = r % 3;
            int n = g_nidx[pbase + node];
            if (n >= 0) {
                float acc = 0.f;
#pragma unroll 8
                for (int c = 0; c < 64; c++) acc += s_newv[node][xx * 64 + c] * s_Q[c * 2 + k];
                if (layer == 0) {
                    if (k == 0) g_pos[n * 3 + xx] = acc;
                } else {
                    outp[n * 6 + k * 3 + xx] = acc;
                }
            }
        }
        __syncthreads();
    }
}

// ---------------- launch ----------------
extern "C" void kernel_launch(void* const* d_in, const int* in_sizes, int n_in,
                              void* d_out, int out_size) {
    const float* x        = (const float*)d_in[0];
    const int*   attr     = (const int*)d_in[2];
    const int*   esrc     = (const int*)d_in[3];
    const int*   edst     = (const int*)d_in[4];
    const float* emb      = (const float*)d_in[5];
    const float* uplift   = (const float*)d_in[6];
    const float* h        = (const float*)d_in[7];
    const float* mix      = (const float*)d_in[8];
    const float* rW1      = (const float*)d_in[9];
    const float* rb1      = (const float*)d_in[10];
    const float* rW2      = (const float*)d_in[11];
    const float* lin1s    = (const float*)d_in[12];
    const float* lin1v    = (const float*)d_in[13];
    const float* lin2s    = (const float*)d_in[14];
    const float* lin2v    = (const float*)d_in[15];
    const float* scs      = (const float*)d_in[16];
    const float* scv      = (const float*)d_in[17];
    const float* sis      = (const float*)d_in[18];
    const float* siv      = (const float*)d_in[19];
    float* out = (float*)d_out;

    const int PB = NPAD / 16;  // 1300

    k_init<<<8681, 256>>>(x, uplift, emb, scs, scv, lin1v, attr, edst);  // 0 (+hist)
    k_scan_e<<<1, 512>>>();                                              // 1
    k_scat_e<<<1280, 256>>>(esrc, edst);                                 // 2
    k_edge<<<2000, 256>>>(rW1, rb1, rW2, 0, 1);                          // 3 <- profiled
    k_post<<<PB, 256>>>(lin2s, lin2v, sis, siv, h, mix, 0, 0, out);      // 4
    k_pre<<<NN / 8, 256>>>(lin1s, lin1v, 1, 1);                          // 5 (+cnt cleanup)
    k_edge<<<2000, 256>>>(rW1, rb1, rW2, 1, 0);                          // 6
    k_post<<<PB, 256>>>(lin2s, lin2v, sis, siv, h, mix, 1, 1, out);      // 7
}

// round 10
// speedup vs baseline: 3.4611x; 1.0529x over previous
#include <cuda_runtime.h>
#include <cuda_bf16.h>
#include <math.h>

#define NN 20000
#define NE 640000
#define NL 2
#define MAXR 2.5f
#define INV_NN 0.17677669529663687f   // 1/sqrt(32)
#define NPAD 20800                    // attr-sorted node list padded to 8-aligned segments

// ---------------- scratch (device globals; no allocs) ----------------
static __device__ float g_Q[64 * 2];
static __device__ float g_ys[2][NN * 64];
static __device__ float g_yv[2][NN * 192];
static __device__ float g_s1[NN * 64];
static __device__ float g_v1[NN * 192];          // [n][3][64] x-major
static __device__ float g_agg[NN * 256];         // (n, c, 4): vx,vy,vz,s
static __device__ float g_pos[NN * 3];
static __device__ float g_Bs[NL * 100 * 64 * 128];
static __device__ float g_Bv[NL * 100 * 64 * 64];
// edge sort (by dst, filtered); counters zeroed by k_pre of the PREVIOUS call (.bss first)
static __device__ int g_ecnt[NN];
static __device__ int g_eoff[NN];
static __device__ int g_eppos[NN];
static __device__ int g_nesurv;
static __device__ int g_ssrc[NE];
static __device__ int g_sdst[NE];
// node sort (by attr), 8-aligned segments, -1 = sentinel
static __device__ int g_nidx[NPAD];
static __device__ int g_nattr[NPAD];

// ---- fused init: Q + y init + layer0 v1 + B precompute + node sort + FILTERED hist ----
__global__ void __launch_bounds__(256) k_init(const float* __restrict__ x,
                                              const float* __restrict__ M,
                                              const float* __restrict__ emb,
                                              const float* __restrict__ scs,
                                              const float* __restrict__ scv,
                                              const float* __restrict__ lin1v,
                                              const int* __restrict__ attr,
                                              const int* __restrict__ esrc,
                                              const int* __restrict__ edst) {
    int tid = threadIdx.x;
    if (blockIdx.x < 5000) {
        __shared__ double dI[3];
        __shared__ float sQ[128];
        __shared__ float sR[128];
        if (tid < 32) {
            double m0a = M[2 * tid], m1a = M[2 * tid + 1];
            double m0b = M[2 * (tid + 32)], m1b = M[2 * (tid + 32) + 1];
            double pa = m0a * m0a + m0b * m0b;
            double pb = m0a * m1a + m0b * m1b;
            double pc = m1a * m1a + m1b * m1b;
#pragma unroll
            for (int off = 16; off > 0; off >>= 1) {
                pa += __shfl_down_sync(0xffffffffu, pa, off);
                pb += __shfl_down_sync(0xffffffffu, pb, off);
                pc += __shfl_down_sync(0xffffffffu, pc, off);
            }
            if (tid == 0) {
                double det = pa * pc - pb * pb;
                double s = sqrt(det);
                double t = pa + pc;
                double denom = sqrt(t + 2.0 * s);
                double p00 = (pa + s) / denom, p01 = pb / denom, p11 = (pc + s) / denom;
                double pdet = p00 * p11 - p01 * p01;
                dI[0] = p11 / pdet; dI[1] = -p01 / pdet; dI[2] = p00 / pdet;
            }
        }
        __syncthreads();
        if (tid < 64) {
            double m0 = M[2 * tid], m1 = M[2 * tid + 1];
            sQ[2 * tid]     = (float)(m0 * dI[0] + m1 * dI[1]);
            sQ[2 * tid + 1] = (float)(m0 * dI[1] + m1 * dI[2]);
        }
        __syncthreads();
        if (blockIdx.x == 0 && tid < 128) g_Q[tid] = sQ[tid];
        if (tid < 128) {
            int k = tid >> 6, d = tid & 63;
            float acc = 0.f;
#pragma unroll 8
            for (int c = 0; c < 64; c++) acc += sQ[c * 2 + k] * lin1v[c * 64 + d];
            sR[k * 64 + d] = acc;
        }
        __syncthreads();
        int i = blockIdx.x * 256 + tid;
        if (i >= NN * 64) return;
        int n = i >> 6, c = i & 63;
        float q0 = sQ[c * 2], q1 = sQ[c * 2 + 1];
        const float* xp = x + n * 6;
        float v0 = xp[0] * q0 + xp[3] * q1;
        float v1 = xp[1] * q0 + xp[4] * q1;
        float v2 = xp[2] * q0 + xp[5] * q1;
        int base = n * 192 + c * 3;
        g_yv[0][base + 0] = v0; g_yv[0][base + 1] = v1; g_yv[0][base + 2] = v2;
        g_yv[1][base + 0] = v0; g_yv[1][base + 1] = v1; g_yv[1][base + 2] = v2;
        g_ys[0][i] = 0.f; g_ys[1][i] = 0.f;
        if (c < 3) g_pos[n * 3 + c] = xp[c];
        reinterpret_cast<float4*>(g_agg)[i] = make_float4(0.f, 0.f, 0.f, 0.f);
        int d = c;
        float r0 = sR[d], r1 = sR[64 + d];
#pragma unroll
        for (int xx = 0; xx < 3; xx++)
            g_v1[n * 192 + xx * 64 + d] = xp[xx] * r0 + xp[3 + xx] * r1;
    } else if (blockIdx.x < 7400) {
        const int TOTS = NL * 100 * 64 * 128;
        const int TOTV = NL * 100 * 64 * 64;
        const int NB = 2400;
        for (int idx = (blockIdx.x - 5000) * 256 + tid; idx < TOTS + TOTV;
             idx += NB * 256) {
            if (idx < TOTS) {
                int o = idx & 127;
                int c = (idx >> 7) & 63;
                int a = (idx >> 13) % 100;
                int l = idx / (128 * 64 * 100);
                const float* w = scs + ((size_t)(l * 64 + c) * 32) * 128 + o;
                const float* em = emb + a * 32;
                float acc = 0.f;
#pragma unroll 8
                for (int e = 0; e < 32; e++) acc += em[e] * w[e * 128];
                g_Bs[idx] = acc;
            } else {
                int j = idx - TOTS;
                int o = j & 63;
                int c = (j >> 6) & 63;
                int a = (j >> 12) % 100;
                int l = j / (64 * 64 * 100);
                const float* w = scv + ((size_t)(l * 64 + c) * 32) * 64 + o;
                const float* em = emb + a * 32;
                float acc = 0.f;
#pragma unroll 8
                for (int e = 0; e < 32; e++) acc += em[e] * w[e * 64];
                g_Bv[j] = acc;
            }
        }
    } else if (blockIdx.x == 7400) {
        // single-block node counting sort by attr, segments padded to 8
        __shared__ int scnt[128], soff[128], spos[128];
        if (tid < 128) { scnt[tid] = 0; spos[tid] = 0; }
        __syncthreads();
        for (int n = tid; n < NN; n += 256) atomicAdd(&scnt[attr[n]], 1);
        __syncthreads();
        int pc = 0;
        if (tid < 128) { pc = (scnt[tid] + 7) & ~7; soff[tid] = pc; }
        __syncthreads();
        for (int off = 1; off < 128; off <<= 1) {
            int v = 0;
            if (tid < 128 && tid >= off) v = soff[tid - off];
            __syncthreads();
            if (tid < 128) soff[tid] += v;
            __syncthreads();
        }
        if (tid < 128) soff[tid] -= pc;  // exclusive, 8-aligned
        __syncthreads();
        for (int i = tid; i < NPAD; i += 256) g_nidx[i] = -1;
        __syncthreads();
        for (int n = tid; n < NN; n += 256) {
            int a = attr[n];
            int p = soff[a] + atomicAdd(&spos[a], 1);
            g_nidx[p] = n;
            g_nattr[p] = a;
        }
    } else {
        // FILTERED edge histogram: only edges with len < MAXR (layer-0 positions = x)
        for (int e = (blockIdx.x - 7401) * 256 + tid; e < NE; e += 1280 * 256) {
            int s = esrc[e], d = edst[e];
            float dx = x[s * 6 + 0] - x[d * 6 + 0];
            float dy = x[s * 6 + 1] - x[d * 6 + 1];
            float dz = x[s * 6 + 2] - x[d * 6 + 2];
            if (dx * dx + dy * dy + dz * dz < MAXR * MAXR)
                atomicAdd(&g_ecnt[d], 1);
        }
    }
}

// ---------------- edge offset scan (writes surviving count) ----------------
__global__ void __launch_bounds__(512) k_scan_e() {
    __shared__ int sp[512];
    int t = threadIdx.x;
    const int CH = 40;
    int base = t * CH;
    int part = 0;
    for (int i = 0; i < CH; i++) {
        int idx = base + i;
        if (idx < NN) part += g_ecnt[idx];
    }
    sp[t] = part;
    __syncthreads();
    for (int off = 1; off < 512; off <<= 1) {
        int v = (t >= off) ? sp[t - off] : 0;
        __syncthreads();
        sp[t] += v;
        __syncthreads();
    }
    if (t == 511) g_nesurv = sp[511];
    int run = sp[t] - part;
    for (int i = 0; i < CH; i++) {
        int idx = base + i;
        if (idx < NN) { g_eoff[idx] = run; run += g_ecnt[idx]; }
    }
}

// ---------------- filtered edge scatter ----------------
__global__ void k_scat_e(const int* __restrict__ esrc, const int* __restrict__ edst,
                         const float* __restrict__ x) {
    for (int e = blockIdx.x * 256 + threadIdx.x; e < NE; e += 1280 * 256) {
        int s = esrc[e], d = edst[e];
        float dx = x[s * 6 + 0] - x[d * 6 + 0];
        float dy = x[s * 6 + 1] - x[d * 6 + 1];
        float dz = x[s * 6 + 2] - x[d * 6 + 2];
        if (dx * dx + dy * dy + dz * dz < MAXR * MAXR) {
            int p = g_eoff[d] + atomicAdd(&g_eppos[d], 1);
            g_ssrc[p] = s;
            g_sdst[p] = d;
        }
    }
}

// ------- pre (layer 1) + sort-counter cleanup for next call's hist -------
__global__ void __launch_bounds__(256) k_pre(const float* __restrict__ lin1s,
                                             const float* __restrict__ lin1v,
                                             int layer, int cur) {
    __shared__ float sWs[4096], sWv[4096];
    __shared__ float sy[8][256];
    int tid = threadIdx.x;
    {
        int i = blockIdx.x * 256 + tid;
        if (i < NN) { g_ecnt[i] = 0; g_eppos[i] = 0; }
    }
    const float* Ws = lin1s + layer * 4096;
    const float* Wv = lin1v + layer * 4096;
    for (int k = tid; k < 4096; k += 256) { sWs[k] = Ws[k]; sWv[k] = Wv[k]; }
    const float* ys = g_ys[cur];
    const float* yv = g_yv[cur];
    int n0 = blockIdx.x * 8;
    for (int k = tid; k < 2048; k += 256) {
        int nn = k >> 8, j = k & 255;
        int n = n0 + nn;
        sy[nn][j] = (j < 64) ? ys[n * 64 + j] : yv[n * 192 + j - 64];
    }
    __syncthreads();
    for (int nn = 0; nn < 8; nn++) {
        int n = n0 + nn;
        if (tid < 64) {
            int d = tid;
            float acc = 0.f;
#pragma unroll 8
            for (int c = 0; c < 64; c++) acc += sy[nn][c] * sWs[c * 64 + d];
            g_s1[n * 64 + d] = acc;
        } else {
            int idx = tid - 64;
            int d = idx & 63, xx = idx >> 6;
            float acc = 0.f;
#pragma unroll 8
            for (int c = 0; c < 64; c++) acc += sy[nn][64 + c * 3 + xx] * sWv[c * 64 + d];
            g_v1[n * 192 + xx * 64 + d] = acc;
        }
    }
}

// -------- edge math common (W1 in regs, bf16 W2 + HFMA2) --------
__device__ __forceinline__ void edge_core(float ev0, float ev1, float ev2, float l2,
                                          const float* w1r, float br,
                                          const unsigned* sW2b, int lane,
                                          float& ea0, float& ea1, float& ea2,
                                          float& w0, float& w1, float& w2, float& w3) {
    const float PI = 3.14159265358979f;
    float elen = sqrtf(l2);
    float safe = fmaxf(elen, 1e-9f);
    float inv = 1.0f / safe;
    float u = 2.f * (elen * (1.0f / MAXR) - 1.f);
    float cut = 0.5f * (1.f - __cosf(PI * u));
    float ca = cut * 1.7320508075688772f * inv;
    ea0 = ca * ev0; ea1 = ca * ev1; ea2 = ca * ev2;
    float th = (PI / MAXR) * safe;
    float sk = __sinf(th), c2 = 2.f * __cosf(th), skm1 = 0.f;
    float fac = 2.5298221281347035f * inv;
    float hs = br;
#pragma unroll
    for (int k = 0; k < 8; k++) {
        hs += (fac * sk) * w1r[k];
        float t = c2 * sk - skm1; skm1 = sk; sk = t;
    }
    float hval = hs / (1.f + __expf(-hs));  // silu
    __nv_bfloat162 hd = __float2bfloat162_rn(hval);
    unsigned hdu = *reinterpret_cast<unsigned*>(&hd);
    __nv_bfloat162 z; z.x = __float2bfloat16(0.f); z.y = z.x;
    __nv_bfloat162 a01e = z, a01o = z, a23e = z, a23o = z;
#pragma unroll
    for (int k = 0; k < 32; k += 2) {
        unsigned hpe = __shfl_sync(0xffffffffu, hdu, k);
        unsigned hpo = __shfl_sync(0xffffffffu, hdu, k + 1);
        uint2 uve = *reinterpret_cast<const uint2*>(&sW2b[k * 64 + lane * 2]);
        uint2 uvo = *reinterpret_cast<const uint2*>(&sW2b[(k + 1) * 64 + lane * 2]);
        a01e = __hfma2(*reinterpret_cast<__nv_bfloat162*>(&hpe),
                       *reinterpret_cast<__nv_bfloat162*>(&uve.x), a01e);
        a23e = __hfma2(*reinterpret_cast<__nv_bfloat162*>(&hpe),
                       *reinterpret_cast<__nv_bfloat162*>(&uve.y), a23e);
        a01o = __hfma2(*reinterpret_cast<__nv_bfloat162*>(&hpo),
                       *reinterpret_cast<__nv_bfloat162*>(&uvo.x), a01o);
        a23o = __hfma2(*reinterpret_cast<__nv_bfloat162*>(&hpo),
                       *reinterpret_cast<__nv_bfloat162*>(&uvo.y), a23o);
    }
    float2 f01e = __bfloat1622float2(a01e), f01o = __bfloat1622float2(a01o);
    float2 f23e = __bfloat1622float2(a23e), f23o = __bfloat1622float2(a23o);
    w0 = f01e.x + f01o.x; w1 = f01e.y + f01o.y;
    w2 = f23e.x + f23o.x; w3 = f23e.y + f23o.y;
}

__device__ __forceinline__ void fill_w2(unsigned* sW2b, const float* rW2, int layer,
                                        int tid) {
    for (int t = tid; t < 2048; t += 256) {
        int k = t >> 6, r = t & 63, ln = r >> 1, g = r & 1;
        const float* base = rW2 + layer * 4096 + k * 128 + g * 64;
        __nv_bfloat162 p = __floats2bfloat162_rn(base[ln], base[32 + ln]);
        sW2b[t] = *reinterpret_cast<unsigned*>(&p);
    }
}

// -------- edge: dst-sorted filtered list, register accumulation --------
__global__ void __launch_bounds__(256) k_edge(const float* __restrict__ rW1,
                                              const float* __restrict__ rb1,
                                              const float* __restrict__ rW2,
                                              int layer, int skip_s1) {
    __shared__ unsigned sW2b[2048];
    int tid = threadIdx.x;
    int lane = tid & 31;
    fill_w2(sW2b, rW2, layer, tid);
    float w1r[8];
#pragma unroll
    for (int k = 0; k < 8; k++) w1r[k] = rW1[layer * 256 + k * 32 + lane];
    float br = rb1[layer * 32 + lane];
    __syncthreads();
    int cnt = g_nesurv;
    int warp = (blockIdx.x * 256 + tid) >> 5;
    int nw = gridDim.x * 8;
    int K = (cnt + nw - 1) / nw;
    int e0 = warp * K;
    if (e0 >= cnt) return;
    int e1 = e0 + K; if (e1 > cnt) e1 = cnt;
    float4 acc0 = make_float4(0.f, 0.f, 0.f, 0.f);
    float4 acc1 = make_float4(0.f, 0.f, 0.f, 0.f);
    bool touched = false;
    int cur = -1;
    float dp0 = 0.f, dp1 = 0.f, dp2 = 0.f;
    for (int e = e0; e < e1; e++) {
        int dst = g_sdst[e];
        if (dst != cur) {
            if (touched) {
                float4* ap = reinterpret_cast<float4*>(g_agg + (size_t)cur * 256);
                atomicAdd(ap + lane, acc0);
                atomicAdd(ap + lane + 32, acc1);
                acc0 = make_float4(0.f, 0.f, 0.f, 0.f);
                acc1 = make_float4(0.f, 0.f, 0.f, 0.f);
                touched = false;
            }
            cur = dst;
            dp0 = g_pos[dst * 3 + 0];
            dp1 = g_pos[dst * 3 + 1];
            dp2 = g_pos[dst * 3 + 2];
        }
        int src = g_ssrc[e];
        float ev0 = g_pos[src * 3 + 0] - dp0;
        float ev1 = g_pos[src * 3 + 1] - dp1;
        float ev2 = g_pos[src * 3 + 2] - dp2;
        float l2 = ev0 * ev0 + ev1 * ev1 + ev2 * ev2;
        if (l2 >= MAXR * MAXR) continue;  // almost never (filtered)
        float ea0, ea1, ea2, w0, w1, w2, w3;
        edge_core(ev0, ev1, ev2, l2, w1r, br, sW2b, lane, ea0, ea1, ea2, w0, w1, w2, w3);
        float sa = 0.f, sb = 0.f;
        if (!skip_s1) {
            const float* s1p = g_s1 + (size_t)src * 64;
            sa = s1p[lane] * w0;
            sb = s1p[lane + 32] * w1;
        }
        const float* v1p = g_v1 + (size_t)src * 192;
        float da = w2 * (v1p[lane] * ea0 + v1p[64 + lane] * ea1 + v1p[128 + lane] * ea2);
        float db = w3 * (v1p[lane + 32] * ea0 + v1p[96 + lane] * ea1 + v1p[160 + lane] * ea2);
        acc0.x += sa * ea0; acc0.y += sa * ea1; acc0.z += sa * ea2; acc0.w += da;
        acc1.x += sb * ea0; acc1.y += sb * ea1; acc1.z += sb * ea2; acc1.w += db;
        touched = true;
    }
    if (touched) {
        float4* ap = reinterpret_cast<float4*>(g_agg + (size_t)cur * 256);
        atomicAdd(ap + lane, acc0);
        atomicAdd(ap + lane + 32, acc1);
    }
}

// ------ post v7: float4 input LDS, float2 tasks, zeroes agg (layer 0) ------
__global__ void __launch_bounds__(256, 3) k_post(const float* __restrict__ lin2s,
                                                 const float* __restrict__ lin2v,
                                                 const float* __restrict__ sis,
                                                 const float* __restrict__ siv,
                                                 const float* __restrict__ hv,
                                                 const float* __restrict__ mv,
                                                 int layer, int cur,
                                                 float* __restrict__ outp) {
    __shared__ float s_Q[128];
    __shared__ __align__(16) float s_ys[8][64], s_aggs[8][64];
    __shared__ __align__(16) float s_yv[8][192], s_aggv[8][192];   // [xx*64+c]
    __shared__ __align__(16) float s_outs[8][128];
    __shared__ __align__(16) float s_outv[8][192];
    __shared__ __align__(16) float s_y2s[8][64];
    __shared__ __align__(16) float s_y2v[8][192];
    __shared__ float s_newv[8][192];
    int tid = threadIdx.x;
    int wid = tid >> 5;
    if (tid < 128) s_Q[tid] = g_Q[tid];
    float hh = hv[layer] * hv[layer];
    float m = mv[layer];
    float* ys_new = g_ys[cur ^ 1];
    float* yv_new = g_yv[cur ^ 1];
    const float* ys_cur = g_ys[cur];
    const float* yv_cur = g_yv[cur];
    for (int it = 0; it < 2; it++) {
        int pbase = blockIdx.x * 16 + it * 8;
        for (int t = tid; t < 512; t += 256) {
            int node = t >> 6, j = t & 63;
            int n = g_nidx[pbase + node];
            if (n >= 0) {
                s_ys[node][j] = ys_cur[n * 64 + j];
                float4 a4 = ((const float4*)g_agg)[n * 64 + j];
                if (layer == 0)
                    ((float4*)g_agg)[n * 64 + j] = make_float4(0.f, 0.f, 0.f, 0.f);
                s_aggs[node][j] = a4.w * INV_NN;
                s_aggv[node][j] = a4.x * INV_NN;
                s_aggv[node][64 + j] = a4.y * INV_NN;
                s_aggv[node][128 + j] = a4.z * INV_NN;
                const float* yvp = yv_cur + n * 192 + j * 3;
                s_yv[node][j] = yvp[0];
                s_yv[node][64 + j] = yvp[1];
                s_yv[node][128 + j] = yvp[2];
            }
        }
        __syncthreads();
        int a = g_nattr[pbase];   // chunk is attr-uniform
        if (wid < 5) {
            const float2 *wp, *bp;
            int wstr;
            const float *in1, *in2;
            int istr;
            float2* o2;
            int ostr;
            if (tid < 64) {
                int j = tid;
                wp = (const float2*)(lin2s + layer * 8192) + j;
                bp = (const float2*)(g_Bs + (size_t)(layer * 100 + a) * 8192) + j;
                wstr = 64;
                in1 = &s_aggs[0][0]; in2 = &s_ys[0][0]; istr = 64;
                o2 = (float2*)&s_outs[0][0] + j; ostr = 64;
            } else {
                int id = tid - 64, xx = id >> 5, j = id & 31;
                wp = (const float2*)(lin2v + layer * 4096) + j;
                bp = (const float2*)(g_Bv + (size_t)(layer * 100 + a) * 4096) + j;
                wstr = 32;
                in1 = &s_aggv[0][xx * 64]; in2 = &s_yv[0][xx * 64]; istr = 192;
                o2 = (float2*)&s_outv[0][0] + xx * 32 + j; ostr = 96;
            }
            float2 acc[8];
#pragma unroll
            for (int nn = 0; nn < 8; nn++) acc[nn] = make_float2(0.f, 0.f);
            for (int c = 0; c < 64; c += 4) {
                float2 w0 = __ldg(wp + (c + 0) * wstr);
                float2 w1 = __ldg(wp + (c + 1) * wstr);
                float2 w2 = __ldg(wp + (c + 2) * wstr);
                float2 w3 = __ldg(wp + (c + 3) * wstr);
                float2 b0 = __ldg(bp + (c + 0) * wstr);
                float2 b1 = __ldg(bp + (c + 1) * wstr);
                float2 b2 = __ldg(bp + (c + 2) * wstr);
                float2 b3 = __ldg(bp + (c + 3) * wstr);
#pragma unroll
                for (int nn = 0; nn < 8; nn++) {
                    float4 u1 = *(const float4*)(in1 + nn * istr + c);
                    float4 u2 = *(const float4*)(in2 + nn * istr + c);
                    acc[nn].x += u1.x * w0.x + u2.x * b0.x;
                    acc[nn].y += u1.x * w0.y + u2.x * b0.y;
                    acc[nn].x += u1.y * w1.x + u2.y * b1.x;
                    acc[nn].y += u1.y * w1.y + u2.y * b1.y;
                    acc[nn].x += u1.z * w2.x + u2.z * b2.x;
                    acc[nn].y += u1.z * w2.y + u2.z * b2.y;
                    acc[nn].x += u1.w * w3.x + u2.w * b3.x;
                    acc[nn].y += u1.w * w3.y + u2.w * b3.y;
                }
            }
#pragma unroll
            for (int nn = 0; nn < 8; nn++) o2[nn * ostr] = acc[nn];
        } else if (wid == 5) {
            int j = tid - 160;
            const float2* wp = (const float2*)(sis + layer * 4096) + j;
            float2 acc[8];
#pragma unroll
            for (int nn = 0; nn < 8; nn++) acc[nn] = make_float2(0.f, 0.f);
            for (int c = 0; c < 64; c += 4) {
                float2 w0 = __ldg(wp + (c + 0) * 32);
                float2 w1 = __ldg(wp + (c + 1) * 32);
                float2 w2 = __ldg(wp + (c + 2) * 32);
                float2 w3 = __ldg(wp + (c + 3) * 32);
#pragma unroll
                for (int nn = 0; nn < 8; nn++) {
                    float4 u = *(const float4*)(&s_ys[nn][c]);
                    acc[nn].x += u.x * w0.x + u.y * w1.x + u.z * w2.x + u.w * w3.x;
                    acc[nn].y += u.x * w0.y + u.y * w1.y + u.z * w2.y + u.w * w3.y;
                }
            }
#pragma unroll
            for (int nn = 0; nn < 8; nn++)
                ((float2*)&s_y2s[0][0])[nn * 32 + j] = acc[nn];
        } else if (tid < 240) {
            int id = tid - 192, xx = id >> 4, j = id & 15;
            const float4* wp = (const float4*)(siv + layer * 4096) + j;
            const float* in = &s_yv[0][xx * 64];
            float4 acc[8];
#pragma unroll
            for (int nn = 0; nn < 8; nn++) acc[nn] = make_float4(0.f, 0.f, 0.f, 0.f);
            for (int c = 0; c < 64; c += 4) {
                float4 w0 = __ldg(wp + (c + 0) * 16);
                float4 w1 = __ldg(wp + (c + 1) * 16);
                float4 w2 = __ldg(wp + (c + 2) * 16);
                float4 w3 = __ldg(wp + (c + 3) * 16);
#pragma unroll
                for (int nn = 0; nn < 8; nn++) {
                    float4 u = *(const float4*)(in + nn * 192 + c);
                    acc[nn].x += u.x * w0.x + u.y * w1.x + u.z * w2.x + u.w * w3.x;
                    acc[nn].y += u.x * w0.y + u.y * w1.y + u.z * w2.y + u.w * w3.y;
                    acc[nn].z += u.x * w0.z + u.y * w1.z + u.z * w2.z + u.w * w3.z;
                    acc[nn].w += u.x * w0.w + u.y * w1.w + u.z * w2.w + u.w * w3.w;
                }
            }
#pragma unroll
            for (int nn = 0; nn < 8; nn++)
                ((float4*)&s_y2v[0][0])[nn * 48 + xx * 16 + j] = acc[nn];
        }
        __syncthreads();
        for (int t = tid; t < 512; t += 256) {
            int node = t >> 6, c = t & 63;
            int n = g_nidx[pbase + node];
            if (n >= 0) {
                float os = s_outs[node][c];
                float gs = os / (1.f + __expf(-os));
                float gate = 1.f / (1.f + __expf(-s_outs[node][64 + c]));
                float yo = ys_new[n * 64 + c];
                float ns = 2.f * s_ys[node][c] - yo + hh * (m * gs + (m - 1.f) * s_y2s[node][c]);
                ys_new[n * 64 + c] = ns;
#pragma unroll
                for (int xx = 0; xx < 3; xx++) {
                    float yov = yv_new[n * 192 + c * 3 + xx];
                    float nv = 2.f * s_yv[node][xx * 64 + c] - yov +
                               hh * (m * gate * s_outv[node][xx * 64 + c] +
                                     (m - 1.f) * s_y2v[node][xx * 64 + c]);
                    yv_new[n * 192 + c * 3 + xx] = nv;
                    s_newv[node][xx * 64 + c] = nv;
                }
            }
        }
        __syncthreads();
        if (tid < 48) {
            int node = tid / 6, r = tid % 6, k = r / 3, xx = r % 3;
            int n = g_nidx[pbase + node];
            if (n >= 0) {
                float acc = 0.f;
#pragma unroll 8
                for (int c = 0; c < 64; c++) acc += s_newv[node][xx * 64 + c] * s_Q[c * 2 + k];
                if (layer == 0) {
                    if (k == 0) g_pos[n * 3 + xx] = acc;
                } else {
                    outp[n * 6 + k * 3 + xx] = acc;
                }
            }
        }
        __syncthreads();
    }
}

// ---------------- launch ----------------
extern "C" void kernel_launch(void* const* d_in, const int* in_sizes, int n_in,
                              void* d_out, int out_size) {
    const float* x        = (const float*)d_in[0];
    const int*   attr     = (const int*)d_in[2];
    const int*   esrc     = (const int*)d_in[3];
    const int*   edst     = (const int*)d_in[4];
    const float* emb      = (const float*)d_in[5];
    const float* uplift   = (const float*)d_in[6];
    const float* h        = (const float*)d_in[7];
    const float* mix      = (const float*)d_in[8];
    const float* rW1      = (const float*)d_in[9];
    const float* rb1      = (const float*)d_in[10];
    const float* rW2      = (const float*)d_in[11];
    const float* lin1s    = (const float*)d_in[12];
    const float* lin1v    = (const float*)d_in[13];
    const float* lin2s    = (const float*)d_in[14];
    const float* lin2v    = (const float*)d_in[15];
    const float* scs      = (const float*)d_in[16];
    const float* scv      = (const float*)d_in[17];
    const float* sis      = (const float*)d_in[18];
    const float* siv      = (const float*)d_in[19];
    float* out = (float*)d_out;

    const int PB = NPAD / 16;  // 1300

    k_init<<<8681, 256>>>(x, uplift, emb, scs, scv, lin1v, attr, esrc, edst); // 0 (+filtered hist)
    k_scan_e<<<1, 512>>>();                                                   // 1
    k_scat_e<<<1280, 256>>>(esrc, edst, x);                                   // 2
    k_edge<<<2000, 256>>>(rW1, rb1, rW2, 0, 1);                               // 3 <- profiled
    k_post<<<PB, 256>>>(lin2s, lin2v, sis, siv, h, mix, 0, 0, out);           // 4
    k_pre<<<NN / 8, 256>>>(lin1s, lin1v, 1, 1);                               // 5 (+cnt cleanup)
    k_edge<<<2000, 256>>>(rW1, rb1, rW2, 1, 0);                               // 6
    k_post<<<PB, 256>>>(lin2s, lin2v, sis, siv, h, mix, 1, 1, out);           // 7
}

// round 11
// speedup vs baseline: 3.6410x; 1.0520x over previous
#include <cuda_runtime.h>
#include <cuda_bf16.h>
#include <math.h>

#define NN 20000
#define NE 640000
#define NL 2
#define MAXR 2.5f
#define INV_NN 0.17677669529663687f   // 1/sqrt(32)
#define NPAD 20800                    // attr-sorted node list padded to 8-aligned segments

// ---------------- scratch (device globals; no allocs) ----------------
static __device__ float g_Q[64 * 2];
static __device__ float g_ys[2][NN * 64];
static __device__ float g_yv[2][NN * 192];
static __device__ float g_s1[NN * 64];
static __device__ float g_v1[NN * 192];          // [n][3][64] x-major
static __device__ float g_agg[NN * 256];         // (n, c, 4): vx,vy,vz,s
static __device__ float g_pos[NN * 3];
static __device__ float g_Bs[NL * 100 * 64 * 128];
static __device__ float g_Bv[NL * 100 * 64 * 64];
// edge sort (by dst, filtered); counters zeroed by k_pre of the PREVIOUS call (.bss first)
static __device__ int g_ecnt[NN];
static __device__ int g_eoff[NN];
static __device__ int g_eppos[NN];
static __device__ int g_nesurv;
static __device__ int g_ssrc[NE];
static __device__ int g_sdst[NE];
// node sort (by attr), 8-aligned segments, -1 = sentinel
static __device__ int g_nidx[NPAD];
static __device__ int g_nattr[NPAD];

// ---- fused init: Q + y init + layer0 v1 + B precompute + node sort + FILTERED hist ----
__global__ void __launch_bounds__(256) k_init(const float* __restrict__ x,
                                              const float* __restrict__ M,
                                              const float* __restrict__ emb,
                                              const float* __restrict__ scs,
                                              const float* __restrict__ scv,
                                              const float* __restrict__ lin1v,
                                              const int* __restrict__ attr,
                                              const int* __restrict__ esrc,
                                              const int* __restrict__ edst) {
    int tid = threadIdx.x;
    if (blockIdx.x < 5000) {
        __shared__ double dI[3];
        __shared__ float sQ[128];
        __shared__ float sR[128];
        if (tid < 32) {
            double m0a = M[2 * tid], m1a = M[2 * tid + 1];
            double m0b = M[2 * (tid + 32)], m1b = M[2 * (tid + 32) + 1];
            double pa = m0a * m0a + m0b * m0b;
            double pb = m0a * m1a + m0b * m1b;
            double pc = m1a * m1a + m1b * m1b;
#pragma unroll
            for (int off = 16; off > 0; off >>= 1) {
                pa += __shfl_down_sync(0xffffffffu, pa, off);
                pb += __shfl_down_sync(0xffffffffu, pb, off);
                pc += __shfl_down_sync(0xffffffffu, pc, off);
            }
            if (tid == 0) {
                double det = pa * pc - pb * pb;
                double s = sqrt(det);
                double t = pa + pc;
                double denom = sqrt(t + 2.0 * s);
                double p00 = (pa + s) / denom, p01 = pb / denom, p11 = (pc + s) / denom;
                double pdet = p00 * p11 - p01 * p01;
                dI[0] = p11 / pdet; dI[1] = -p01 / pdet; dI[2] = p00 / pdet;
            }
        }
        __syncthreads();
        if (tid < 64) {
            double m0 = M[2 * tid], m1 = M[2 * tid + 1];
            sQ[2 * tid]     = (float)(m0 * dI[0] + m1 * dI[1]);
            sQ[2 * tid + 1] = (float)(m0 * dI[1] + m1 * dI[2]);
        }
        __syncthreads();
        if (blockIdx.x == 0 && tid < 128) g_Q[tid] = sQ[tid];
        if (tid < 128) {
            int k = tid >> 6, d = tid & 63;
            float acc = 0.f;
#pragma unroll 8
            for (int c = 0; c < 64; c++) acc += sQ[c * 2 + k] * lin1v[c * 64 + d];
            sR[k * 64 + d] = acc;
        }
        __syncthreads();
        int i = blockIdx.x * 256 + tid;
        if (i >= NN * 64) return;
        int n = i >> 6, c = i & 63;
        float q0 = sQ[c * 2], q1 = sQ[c * 2 + 1];
        const float* xp = x + n * 6;
        float v0 = xp[0] * q0 + xp[3] * q1;
        float v1 = xp[1] * q0 + xp[4] * q1;
        float v2 = xp[2] * q0 + xp[5] * q1;
        int base = n * 192 + c * 3;
        g_yv[0][base + 0] = v0; g_yv[0][base + 1] = v1; g_yv[0][base + 2] = v2;
        g_yv[1][base + 0] = v0; g_yv[1][base + 1] = v1; g_yv[1][base + 2] = v2;
        g_ys[0][i] = 0.f; g_ys[1][i] = 0.f;
        if (c < 3) g_pos[n * 3 + c] = xp[c];
        reinterpret_cast<float4*>(g_agg)[i] = make_float4(0.f, 0.f, 0.f, 0.f);
        int d = c;
        float r0 = sR[d], r1 = sR[64 + d];
#pragma unroll
        for (int xx = 0; xx < 3; xx++)
            g_v1[n * 192 + xx * 64 + d] = xp[xx] * r0 + xp[3 + xx] * r1;
    } else if (blockIdx.x < 7400) {
        const int TOTS = NL * 100 * 64 * 128;
        const int TOTV = NL * 100 * 64 * 64;
        const int NB = 2400;
        for (int idx = (blockIdx.x - 5000) * 256 + tid; idx < TOTS + TOTV;
             idx += NB * 256) {
            if (idx < TOTS) {
                int o = idx & 127;
                int c = (idx >> 7) & 63;
                int a = (idx >> 13) % 100;
                int l = idx / (128 * 64 * 100);
                const float* w = scs + ((size_t)(l * 64 + c) * 32) * 128 + o;
                const float* em = emb + a * 32;
                float acc = 0.f;
#pragma unroll 8
                for (int e = 0; e < 32; e++) acc += em[e] * w[e * 128];
                g_Bs[idx] = acc;
            } else {
                int j = idx - TOTS;
                int o = j & 63;
                int c = (j >> 6) & 63;
                int a = (j >> 12) % 100;
                int l = j / (64 * 64 * 100);
                const float* w = scv + ((size_t)(l * 64 + c) * 32) * 64 + o;
                const float* em = emb + a * 32;
                float acc = 0.f;
#pragma unroll 8
                for (int e = 0; e < 32; e++) acc += em[e] * w[e * 64];
                g_Bv[j] = acc;
            }
        }
    } else if (blockIdx.x == 7400) {
        // single-block node counting sort by attr, segments padded to 8
        __shared__ int scnt[128], soff[128], spos[128];
        if (tid < 128) { scnt[tid] = 0; spos[tid] = 0; }
        __syncthreads();
        for (int n = tid; n < NN; n += 256) atomicAdd(&scnt[attr[n]], 1);
        __syncthreads();
        int pc = 0;
        if (tid < 128) { pc = (scnt[tid] + 7) & ~7; soff[tid] = pc; }
        __syncthreads();
        for (int off = 1; off < 128; off <<= 1) {
            int v = 0;
            if (tid < 128 && tid >= off) v = soff[tid - off];
            __syncthreads();
            if (tid < 128) soff[tid] += v;
            __syncthreads();
        }
        if (tid < 128) soff[tid] -= pc;  // exclusive, 8-aligned
        __syncthreads();
        for (int i = tid; i < NPAD; i += 256) g_nidx[i] = -1;
        __syncthreads();
        for (int n = tid; n < NN; n += 256) {
            int a = attr[n];
            int p = soff[a] + atomicAdd(&spos[a], 1);
            g_nidx[p] = n;
            g_nattr[p] = a;
        }
    } else {
        // FILTERED edge histogram: only edges with len < MAXR (layer-0 positions = x)
        for (int e = (blockIdx.x - 7401) * 256 + tid; e < NE; e += 1280 * 256) {
            int s = esrc[e], d = edst[e];
            float dx = x[s * 6 + 0] - x[d * 6 + 0];
            float dy = x[s * 6 + 1] - x[d * 6 + 1];
            float dz = x[s * 6 + 2] - x[d * 6 + 2];
            if (dx * dx + dy * dy + dz * dz < MAXR * MAXR)
                atomicAdd(&g_ecnt[d], 1);
        }
    }
}

// ---------------- edge offset scan (writes surviving count) ----------------
__global__ void __launch_bounds__(512) k_scan_e() {
    __shared__ int sp[512];
    int t = threadIdx.x;
    const int CH = 40;
    int base = t * CH;
    int part = 0;
    for (int i = 0; i < CH; i++) {
        int idx = base + i;
        if (idx < NN) part += g_ecnt[idx];
    }
    sp[t] = part;
    __syncthreads();
    for (int off = 1; off < 512; off <<= 1) {
        int v = (t >= off) ? sp[t - off] : 0;
        __syncthreads();
        sp[t] += v;
        __syncthreads();
    }
    if (t == 511) g_nesurv = sp[511];
    int run = sp[t] - part;
    for (int i = 0; i < CH; i++) {
        int idx = base + i;
        if (idx < NN) { g_eoff[idx] = run; run += g_ecnt[idx]; }
    }
}

// ---------------- filtered edge scatter ----------------
__global__ void k_scat_e(const int* __restrict__ esrc, const int* __restrict__ edst,
                         const float* __restrict__ x) {
    for (int e = blockIdx.x * 256 + threadIdx.x; e < NE; e += 1280 * 256) {
        int s = esrc[e], d = edst[e];
        float dx = x[s * 6 + 0] - x[d * 6 + 0];
        float dy = x[s * 6 + 1] - x[d * 6 + 1];
        float dz = x[s * 6 + 2] - x[d * 6 + 2];
        if (dx * dx + dy * dy + dz * dz < MAXR * MAXR) {
            int p = g_eoff[d] + atomicAdd(&g_eppos[d], 1);
            g_ssrc[p] = s;
            g_sdst[p] = d;
        }
    }
}

// ------- pre (layer 1) + sort-counter cleanup for next call's hist -------
__global__ void __launch_bounds__(256) k_pre(const float* __restrict__ lin1s,
                                             const float* __restrict__ lin1v,
                                             int layer, int cur) {
    __shared__ float sWs[4096], sWv[4096];
    __shared__ float sy[8][256];
    int tid = threadIdx.x;
    {
        int i = blockIdx.x * 256 + tid;
        if (i < NN) { g_ecnt[i] = 0; g_eppos[i] = 0; }
    }
    const float* Ws = lin1s + layer * 4096;
    const float* Wv = lin1v + layer * 4096;
    for (int k = tid; k < 4096; k += 256) { sWs[k] = Ws[k]; sWv[k] = Wv[k]; }
    const float* ys = g_ys[cur];
    const float* yv = g_yv[cur];
    int n0 = blockIdx.x * 8;
    for (int k = tid; k < 2048; k += 256) {
        int nn = k >> 8, j = k & 255;
        int n = n0 + nn;
        sy[nn][j] = (j < 64) ? ys[n * 64 + j] : yv[n * 192 + j - 64];
    }
    __syncthreads();
    for (int nn = 0; nn < 8; nn++) {
        int n = n0 + nn;
        if (tid < 64) {
            int d = tid;
            float acc = 0.f;
#pragma unroll 8
            for (int c = 0; c < 64; c++) acc += sy[nn][c] * sWs[c * 64 + d];
            g_s1[n * 64 + d] = acc;
        } else {
            int idx = tid - 64;
            int d = idx & 63, xx = idx >> 6;
            float acc = 0.f;
#pragma unroll 8
            for (int c = 0; c < 64; c++) acc += sy[nn][64 + c * 3 + xx] * sWv[c * 64 + d];
            g_v1[n * 192 + xx * 64 + d] = acc;
        }
    }
}

// -------- per-edge scalar math (W1 in regs); returns silu(h) for this lane --------
__device__ __forceinline__ float edge_scalar(float ev0, float ev1, float ev2, float l2,
                                             const float* w1r, float br,
                                             float& ea0, float& ea1, float& ea2) {
    const float PI = 3.14159265358979f;
    float elen = sqrtf(l2);
    float safe = fmaxf(elen, 1e-9f);
    float inv = 1.0f / safe;
    float u = fminf(2.f * (elen * (1.0f / MAXR) - 1.f), 0.f);  // clamp: cut=0 beyond MAXR
    float cut = 0.5f * (1.f - __cosf(PI * u));
    float ca = cut * 1.7320508075688772f * inv;
    ea0 = ca * ev0; ea1 = ca * ev1; ea2 = ca * ev2;
    float th = (PI / MAXR) * safe;
    float sk = __sinf(th), c2 = 2.f * __cosf(th), skm1 = 0.f;
    float fac = 2.5298221281347035f * inv;
    float hs = br;
#pragma unroll
    for (int k = 0; k < 8; k++) {
        hs += (fac * sk) * w1r[k];
        float t = c2 * sk - skm1; skm1 = sk; sk = t;
    }
    return hs / (1.f + __expf(-hs));  // silu
}

// W2 duplicated-bf16x2 layout: sW2d[k*32+lane] = {dup(w0),dup(w1),dup(w2),dup(w3)}
__device__ __forceinline__ void fill_w2d(uint4* sW2d, const float* rW2, int layer,
                                         int tid) {
    for (int t = tid; t < 1024; t += 256) {
        int k = t >> 5, ln = t & 31;
        const float* base = rW2 + layer * 4096 + k * 128;
        uint4 v;
        __nv_bfloat162 p0 = __float2bfloat162_rn(base[ln]);
        __nv_bfloat162 p1 = __float2bfloat162_rn(base[32 + ln]);
        __nv_bfloat162 p2 = __float2bfloat162_rn(base[64 + ln]);
        __nv_bfloat162 p3 = __float2bfloat162_rn(base[96 + ln]);
        v.x = *reinterpret_cast<unsigned*>(&p0);
        v.y = *reinterpret_cast<unsigned*>(&p1);
        v.z = *reinterpret_cast<unsigned*>(&p2);
        v.w = *reinterpret_cast<unsigned*>(&p3);
        sW2d[t] = v;
    }
}

// -------- edge: dst-sorted filtered list, PAIRED edges, register accumulation --------
__global__ void __launch_bounds__(256) k_edge(const float* __restrict__ rW1,
                                              const float* __restrict__ rb1,
                                              const float* __restrict__ rW2,
                                              int layer, int skip_s1) {
    __shared__ uint4 sW2d[1024];   // 16 KB
    int tid = threadIdx.x;
    int lane = tid & 31;
    fill_w2d(sW2d, rW2, layer, tid);
    float w1r[8];
#pragma unroll
    for (int k = 0; k < 8; k++) w1r[k] = rW1[layer * 256 + k * 32 + lane];
    float br = rb1[layer * 32 + lane];
    __syncthreads();
    int cnt = g_nesurv;
    int warp = (blockIdx.x * 256 + tid) >> 5;
    int nw = gridDim.x * 8;
    int K = (cnt + nw - 1) / nw;
    int e0 = warp * K;
    if (e0 >= cnt) return;
    int e1 = e0 + K; if (e1 > cnt) e1 = cnt;
    float4 acc0 = make_float4(0.f, 0.f, 0.f, 0.f);
    float4 acc1 = make_float4(0.f, 0.f, 0.f, 0.f);
    bool touched = false;
    int cur = -1;
    float dp0 = 0.f, dp1 = 0.f, dp2 = 0.f;
    __nv_bfloat162 zz; zz.x = __float2bfloat16(0.f); zz.y = zz.x;
    for (int e = e0; e < e1; e += 2) {
        // ---- edge A ----
        int dstA = g_sdst[e], srcA = g_ssrc[e];
        if (dstA != cur) {
            if (touched) {
                float4* ap = reinterpret_cast<float4*>(g_agg + (size_t)cur * 256);
                atomicAdd(ap + lane, acc0);
                atomicAdd(ap + lane + 32, acc1);
                acc0 = make_float4(0.f, 0.f, 0.f, 0.f);
                acc1 = make_float4(0.f, 0.f, 0.f, 0.f);
                touched = false;
            }
            cur = dstA;
            dp0 = g_pos[dstA * 3 + 0];
            dp1 = g_pos[dstA * 3 + 1];
            dp2 = g_pos[dstA * 3 + 2];
        }
        float evA0 = g_pos[srcA * 3 + 0] - dp0;
        float evA1 = g_pos[srcA * 3 + 1] - dp1;
        float evA2 = g_pos[srcA * 3 + 2] - dp2;
        float l2A = evA0 * evA0 + evA1 * evA1 + evA2 * evA2;
        float eaA0, eaA1, eaA2;
        float hA = edge_scalar(evA0, evA1, evA2, l2A, w1r, br, eaA0, eaA1, eaA2);
        // ---- edge B (speculative) ----
        bool has2 = (e + 1 < e1);
        int dstB = cur, srcB = srcA;
        float db0 = dp0, db1 = dp1, db2 = dp2;
        float hB = 0.f, eaB0 = 0.f, eaB1 = 0.f, eaB2 = 0.f;
        if (has2) {
            dstB = g_sdst[e + 1]; srcB = g_ssrc[e + 1];
            if (dstB != cur) {
                db0 = g_pos[dstB * 3 + 0];
                db1 = g_pos[dstB * 3 + 1];
                db2 = g_pos[dstB * 3 + 2];
            }
            float evB0 = g_pos[srcB * 3 + 0] - db0;
            float evB1 = g_pos[srcB * 3 + 1] - db1;
            float evB2 = g_pos[srcB * 3 + 2] - db2;
            float l2B = evB0 * evB0 + evB1 * evB1 + evB2 * evB2;
            hB = edge_scalar(evB0, evB1, evB2, l2B, w1r, br, eaB0, eaB1, eaB2);
        }
        // ---- paired W2 matvec: (hA,hB) bf16x2, 1 SHFL + 1 LDS.128 + 4 HFMA2 per k ----
        __nv_bfloat162 hd = __floats2bfloat162_rn(hA, hB);
        unsigned hdu = *reinterpret_cast<unsigned*>(&hd);
        __nv_bfloat162 a0 = zz, a1 = zz, a2 = zz, a3 = zz;
#pragma unroll
        for (int k = 0; k < 32; k++) {
            unsigned hp = __shfl_sync(0xffffffffu, hdu, k);
            uint4 wv = sW2d[k * 32 + lane];
            __nv_bfloat162 hpb = *reinterpret_cast<__nv_bfloat162*>(&hp);
            a0 = __hfma2(hpb, *reinterpret_cast<__nv_bfloat162*>(&wv.x), a0);
            a1 = __hfma2(hpb, *reinterpret_cast<__nv_bfloat162*>(&wv.y), a1);
            a2 = __hfma2(hpb, *reinterpret_cast<__nv_bfloat162*>(&wv.z), a2);
            a3 = __hfma2(hpb, *reinterpret_cast<__nv_bfloat162*>(&wv.w), a3);
        }
        float2 f0 = __bfloat1622float2(a0), f1 = __bfloat1622float2(a1);
        float2 f2 = __bfloat1622float2(a2), f3 = __bfloat1622float2(a3);
        // ---- accumulate A (cur == dstA) ----
        {
            float sa = 0.f, sb = 0.f;
            if (!skip_s1) {
                const float* s1p = g_s1 + (size_t)srcA * 64;
                sa = s1p[lane] * f0.x;
                sb = s1p[lane + 32] * f1.x;
            }
            const float* v1p = g_v1 + (size_t)srcA * 192;
            float da = f2.x * (v1p[lane] * eaA0 + v1p[64 + lane] * eaA1 + v1p[128 + lane] * eaA2);
            float db_ = f3.x * (v1p[lane + 32] * eaA0 + v1p[96 + lane] * eaA1 + v1p[160 + lane] * eaA2);
            acc0.x += sa * eaA0; acc0.y += sa * eaA1; acc0.z += sa * eaA2; acc0.w += da;
            acc1.x += sb * eaA0; acc1.y += sb * eaA1; acc1.z += sb * eaA2; acc1.w += db_;
            touched = true;
        }
        // ---- accumulate B ----
        if (has2) {
            if (dstB != cur) {
                // flush A's run, start B's
                float4* ap = reinterpret_cast<float4*>(g_agg + (size_t)cur * 256);
                atomicAdd(ap + lane, acc0);
                atomicAdd(ap + lane + 32, acc1);
                acc0 = make_float4(0.f, 0.f, 0.f, 0.f);
                acc1 = make_float4(0.f, 0.f, 0.f, 0.f);
                cur = dstB;
                dp0 = db0; dp1 = db1; dp2 = db2;
            }
            float sa = 0.f, sb = 0.f;
            if (!skip_s1) {
                const float* s1p = g_s1 + (size_t)srcB * 64;
                sa = s1p[lane] * f0.y;
                sb = s1p[lane + 32] * f1.y;
            }
            const float* v1p = g_v1 + (size_t)srcB * 192;
            float da = f2.y * (v1p[lane] * eaB0 + v1p[64 + lane] * eaB1 + v1p[128 + lane] * eaB2);
            float db_ = f3.y * (v1p[lane + 32] * eaB0 + v1p[96 + lane] * eaB1 + v1p[160 + lane] * eaB2);
            acc0.x += sa * eaB0; acc0.y += sa * eaB1; acc0.z += sa * eaB2; acc0.w += da;
            acc1.x += sb * eaB0; acc1.y += sb * eaB1; acc1.z += sb * eaB2; acc1.w += db_;
            touched = true;
        }
    }
    if (touched) {
        float4* ap = reinterpret_cast<float4*>(g_agg + (size_t)cur * 256);
        atomicAdd(ap + lane, acc0);
        atomicAdd(ap + lane + 32, acc1);
    }
}

// ------ post v7: float4 input LDS, float2 tasks, zeroes agg (layer 0) ------
__global__ void __launch_bounds__(256, 3) k_post(const float* __restrict__ lin2s,
                                                 const float* __restrict__ lin2v,
                                                 const float* __restrict__ sis,
                                                 const float* __restrict__ siv,
                                                 const float* __restrict__ hv,
                                                 const float* __restrict__ mv,
                                                 int layer, int cur,
                                                 float* __restrict__ outp) {
    __shared__ float s_Q[128];
    __shared__ __align__(16) float s_ys[8][64], s_aggs[8][64];
    __shared__ __align__(16) float s_yv[8][192], s_aggv[8][192];   // [xx*64+c]
    __shared__ __align__(16) float s_outs[8][128];
    __shared__ __align__(16) float s_outv[8][192];
    __shared__ __align__(16) float s_y2s[8][64];
    __shared__ __align__(16) float s_y2v[8][192];
    __shared__ float s_newv[8][192];
    int tid = threadIdx.x;
    int wid = tid >> 5;
    if (tid < 128) s_Q[tid] = g_Q[tid];
    float hh = hv[layer] * hv[layer];
    float m = mv[layer];
    float* ys_new = g_ys[cur ^ 1];
    float* yv_new = g_yv[cur ^ 1];
    const float* ys_cur = g_ys[cur];
    const float* yv_cur = g_yv[cur];
    for (int it = 0; it < 2; it++) {
        int pbase = blockIdx.x * 16 + it * 8;
        for (int t = tid; t < 512; t += 256) {
            int node = t >> 6, j = t & 63;
            int n = g_nidx[pbase + node];
            if (n >= 0) {
                s_ys[node][j] = ys_cur[n * 64 + j];
                float4 a4 = ((const float4*)g_agg)[n * 64 + j];
                if (layer == 0)
                    ((float4*)g_agg)[n * 64 + j] = make_float4(0.f, 0.f, 0.f, 0.f);
                s_aggs[node][j] = a4.w * INV_NN;
                s_aggv[node][j] = a4.x * INV_NN;
                s_aggv[node][64 + j] = a4.y * INV_NN;
                s_aggv[node][128 + j] = a4.z * INV_NN;
                const float* yvp = yv_cur + n * 192 + j * 3;
                s_yv[node][j] = yvp[0];
                s_yv[node][64 + j] = yvp[1];
                s_yv[node][128 + j] = yvp[2];
            }
        }
        __syncthreads();
        int a = g_nattr[pbase];   // chunk is attr-uniform
        if (wid < 5) {
            const float2 *wp, *bp;
            int wstr;
            const float *in1, *in2;
            int istr;
            float2* o2;
            int ostr;
            if (tid < 64) {
                int j = tid;
                wp = (const float2*)(lin2s + layer * 8192) + j;
                bp = (const float2*)(g_Bs + (size_t)(layer * 100 + a) * 8192) + j;
                wstr = 64;
                in1 = &s_aggs[0][0]; in2 = &s_ys[0][0]; istr = 64;
                o2 = (float2*)&s_outs[0][0] + j; ostr = 64;
            } else {
                int id = tid - 64, xx = id >> 5, j = id & 31;
                wp = (const float2*)(lin2v + layer * 4096) + j;
                bp = (const float2*)(g_Bv + (size_t)(layer * 100 + a) * 4096) + j;
                wstr = 32;
                in1 = &s_aggv[0][xx * 64]; in2 = &s_yv[0][xx * 64]; istr = 192;
                o2 = (float2*)&s_outv[0][0] + xx * 32 + j; ostr = 96;
            }
            float2 acc[8];
#pragma unroll
            for (int nn = 0; nn < 8; nn++) acc[nn] = make_float2(0.f, 0.f);
            for (int c = 0; c < 64; c += 4) {
                float2 w0 = __ldg(wp + (c + 0) * wstr);
                float2 w1 = __ldg(wp + (c + 1) * wstr);
                float2 w2 = __ldg(wp + (c + 2) * wstr);
                float2 w3 = __ldg(wp + (c + 3) * wstr);
                float2 b0 = __ldg(bp + (c + 0) * wstr);
                float2 b1 = __ldg(bp + (c + 1) * wstr);
                float2 b2 = __ldg(bp + (c + 2) * wstr);
                float2 b3 = __ldg(bp + (c + 3) * wstr);
#pragma unroll
                for (int nn = 0; nn < 8; nn++) {
                    float4 u1 = *(const float4*)(in1 + nn * istr + c);
                    float4 u2 = *(const float4*)(in2 + nn * istr + c);
                    acc[nn].x += u1.x * w0.x + u2.x * b0.x;
                    acc[nn].y += u1.x * w0.y + u2.x * b0.y;
                    acc[nn].x += u1.y * w1.x + u2.y * b1.x;
                    acc[nn].y += u1.y * w1.y + u2.y * b1.y;
                    acc[nn].x += u1.z * w2.x + u2.z * b2.x;
                    acc[nn].y += u1.z * w2.y + u2.z * b2.y;
                    acc[nn].x += u1.w * w3.x + u2.w * b3.x;
                    acc[nn].y += u1.w * w3.y + u2.w * b3.y;
                }
            }
#pragma unroll
            for (int nn = 0; nn < 8; nn++) o2[nn * ostr] = acc[nn];
        } else if (wid == 5) {
            int j = tid - 160;
            const float2* wp = (const float2*)(sis + layer * 4096) + j;
            float2 acc[8];
#pragma unroll
            for (int nn = 0; nn < 8; nn++) acc[nn] = make_float2(0.f, 0.f);
            for (int c = 0; c < 64; c += 4) {
                float2 w0 = __ldg(wp + (c + 0) * 32);
                float2 w1 = __ldg(wp + (c + 1) * 32);
                float2 w2 = __ldg(wp + (c + 2) * 32);
                float2 w3 = __ldg(wp + (c + 3) * 32);
#pragma unroll
                for (int nn = 0; nn < 8; nn++) {
                    float4 u = *(const float4*)(&s_ys[nn][c]);
                    acc[nn].x += u.x * w0.x + u.y * w1.x + u.z * w2.x + u.w * w3.x;
                    acc[nn].y += u.x * w0.y + u.y * w1.y + u.z * w2.y + u.w * w3.y;
                }
            }
#pragma unroll
            for (int nn = 0; nn < 8; nn++)
                ((float2*)&s_y2s[0][0])[nn * 32 + j] = acc[nn];
        } else if (tid < 240) {
            int id = tid - 192, xx = id >> 4, j = id & 15;
            const float4* wp = (const float4*)(siv + layer * 4096) + j;
            const float* in = &s_yv[0][xx * 64];
            float4 acc[8];
#pragma unroll
            for (int nn = 0; nn < 8; nn++) acc[nn] = make_float4(0.f, 0.f, 0.f, 0.f);
            for (int c = 0; c < 64; c += 4) {
                float4 w0 = __ldg(wp + (c + 0) * 16);
                float4 w1 = __ldg(wp + (c + 1) * 16);
                float4 w2 = __ldg(wp + (c + 2) * 16);
                float4 w3 = __ldg(wp + (c + 3) * 16);
#pragma unroll
                for (int nn = 0; nn < 8; nn++) {
                    float4 u = *(const float4*)(in + nn * 192 + c);
                    acc[nn].x += u.x * w0.x + u.y * w1.x + u.z * w2.x + u.w * w3.x;
                    acc[nn].y += u.x * w0.y + u.y * w1.y + u.z * w2.y + u.w * w3.y;
                    acc[nn].z += u.x * w0.z + u.y * w1.z + u.z * w2.z + u.w * w3.z;
                    acc[nn].w += u.x * w0.w + u.y * w1.w + u.z * w2.w + u.w * w3.w;
                }
            }
#pragma unroll
            for (int nn = 0; nn < 8; nn++)
                ((float4*)&s_y2v[0][0])[nn * 48 + xx * 16 + j] = acc[nn];
        }
        __syncthreads();
        for (int t = tid; t < 512; t += 256) {
            int node = t >> 6, c = t & 63;
            int n = g_nidx[pbase + node];
            if (n >= 0) {
                float os = s_outs[node][c];
                float gs = os / (1.f + __expf(-os));
                float gate = 1.f / (1.f + __expf(-s_outs[node][64 + c]));
                float yo = ys_new[n * 64 + c];
                float ns = 2.f * s_ys[node][c] - yo + hh * (m * gs + (m - 1.f) * s_y2s[node][c]);
                ys_new[n * 64 + c] = ns;
#pragma unroll
                for (int xx = 0; xx < 3; xx++) {
                    float yov = yv_new[n * 192 + c * 3 + xx];
                    float nv = 2.f * s_yv[node][xx * 64 + c] - yov +
                               hh * (m * gate * s_outv[node][xx * 64 + c] +
                                     (m - 1.f) * s_y2v[node][xx * 64 + c]);
                    yv_new[n * 192 + c * 3 + xx] = nv;
                    s_newv[node][xx * 64 + c] = nv;
                }
            }
        }
        __syncthreads();
        if (tid < 48) {
            int node = tid / 6, r = tid % 6, k = r / 3, xx = r % 3;
            int n = g_nidx[pbase + node];
            if (n >= 0) {
                float acc = 0.f;
#pragma unroll 8
                for (int c = 0; c < 64; c++) acc += s_newv[node][xx * 64 + c] * s_Q[c * 2 + k];
                if (layer == 0) {
                    if (k == 0) g_pos[n * 3 + xx] = acc;
                } else {
                    outp[n * 6 + k * 3 + xx] = acc;
                }
            }
        }
        __syncthreads();
    }
}

// ---------------- launch ----------------
extern "C" void kernel_launch(void* const* d_in, const int* in_sizes, int n_in,
                              void* d_out, int out_size) {
    const float* x        = (const float*)d_in[0];
    const int*   attr     = (const int*)d_in[2];
    const int*   esrc     = (const int*)d_in[3];
    const int*   edst     = (const int*)d_in[4];
    const float* emb      = (const float*)d_in[5];
    const float* uplift   = (const float*)d_in[6];
    const float* h        = (const float*)d_in[7];
    const float* mix      = (const float*)d_in[8];
    const float* rW1      = (const float*)d_in[9];
    const float* rb1      = (const float*)d_in[10];
    const float* rW2      = (const float*)d_in[11];
    const float* lin1s    = (const float*)d_in[12];
    const float* lin1v    = (const float*)d_in[13];
    const float* lin2s    = (const float*)d_in[14];
    const float* lin2v    = (const float*)d_in[15];
    const float* scs      = (const float*)d_in[16];
    const float* scv      = (const float*)d_in[17];
    const float* sis      = (const float*)d_in[18];
    const float* siv      = (const float*)d_in[19];
    float* out = (float*)d_out;

    const int PB = NPAD / 16;  // 1300

    k_init<<<8681, 256>>>(x, uplift, emb, scs, scv, lin1v, attr, esrc, edst); // 0 (+filtered hist)
    k_scan_e<<<1, 512>>>();                                                   // 1
    k_scat_e<<<1280, 256>>>(esrc, edst, x);                                   // 2
    k_edge<<<2000, 256>>>(rW1, rb1, rW2, 0, 1);                               // 3 <- profiled
    k_post<<<PB, 256>>>(lin2s, lin2v, sis, siv, h, mix, 0, 0, out);           // 4
    k_pre<<<NN / 8, 256>>>(lin1s, lin1v, 1, 1);                               // 5 (+cnt cleanup)
    k_edge<<<2000, 256>>>(rW1, rb1, rW2, 1, 0);                               // 6
    k_post<<<PB, 256>>>(lin2s, lin2v, sis, siv, h, mix, 1, 1, out);           // 7
}

// round 13
// speedup vs baseline: 3.7014x; 1.0166x over previous
#include <cuda_runtime.h>
#include <cuda_bf16.h>
#include <math.h>

#define NN 20000
#define NE 640000
#define NL 2
#define MAXR 2.5f
#define INV_NN 0.17677669529663687f   // 1/sqrt(32)
#define NPAD 20800                    // attr-sorted node list padded to 8-aligned segments

// ---------------- scratch (device globals; no allocs) ----------------
static __device__ float g_Q[64 * 2];
static __device__ float g_ys[2][NN * 64];
static __device__ float g_yv[2][NN * 192];
static __device__ float g_s1[NN * 64];
static __device__ float g_v1[NN * 192];          // [n][3][64] x-major
static __device__ float g_agg[NN * 256];         // (n, c, 4): vx,vy,vz,s
static __device__ float g_pos[NN * 3];
static __device__ float g_Bs[NL * 100 * 64 * 128];
static __device__ float g_Bv[NL * 100 * 64 * 64];
// edge sort (by dst, filtered); counters zeroed by k_pre of the PREVIOUS call (.bss first)
static __device__ int g_ecnt[NN];
static __device__ int g_eoff[NN];
static __device__ int g_eppos[NN];
static __device__ int g_nesurv;
static __device__ int g_ssrc[NE];
static __device__ int g_sdst[NE];
// node sort (by attr), 8-aligned segments, -1 = sentinel
static __device__ int g_nidx[NPAD];
static __device__ int g_nattr[NPAD];

// ---- fused init: Q + y init + layer0 v1 + B precompute (tiled) + node sort + hist ----
__global__ void __launch_bounds__(256) k_init(const float* __restrict__ x,
                                              const float* __restrict__ M,
                                              const float* __restrict__ emb,
                                              const float* __restrict__ scs,
                                              const float* __restrict__ scv,
                                              const float* __restrict__ lin1v,
                                              const int* __restrict__ attr,
                                              const int* __restrict__ esrc,
                                              const int* __restrict__ edst) {
    int tid = threadIdx.x;
    if (blockIdx.x < 5000) {
        __shared__ double dI[3];
        __shared__ float sQ[128];
        __shared__ float sR[128];
        if (tid < 32) {
            double m0a = M[2 * tid], m1a = M[2 * tid + 1];
            double m0b = M[2 * (tid + 32)], m1b = M[2 * (tid + 32) + 1];
            double pa = m0a * m0a + m0b * m0b;
            double pb = m0a * m1a + m0b * m1b;
            double pc = m1a * m1a + m1b * m1b;
#pragma unroll
            for (int off = 16; off > 0; off >>= 1) {
                pa += __shfl_down_sync(0xffffffffu, pa, off);
                pb += __shfl_down_sync(0xffffffffu, pb, off);
                pc += __shfl_down_sync(0xffffffffu, pc, off);
            }
            if (tid == 0) {
                double det = pa * pc - pb * pb;
                double s = sqrt(det);
                double t = pa + pc;
                double denom = sqrt(t + 2.0 * s);
                double p00 = (pa + s) / denom, p01 = pb / denom, p11 = (pc + s) / denom;
                double pdet = p00 * p11 - p01 * p01;
                dI[0] = p11 / pdet; dI[1] = -p01 / pdet; dI[2] = p00 / pdet;
            }
        }
        __syncthreads();
        if (tid < 64) {
            double m0 = M[2 * tid], m1 = M[2 * tid + 1];
            sQ[2 * tid]     = (float)(m0 * dI[0] + m1 * dI[1]);
            sQ[2 * tid + 1] = (float)(m0 * dI[1] + m1 * dI[2]);
        }
        __syncthreads();
        if (blockIdx.x == 0 && tid < 128) g_Q[tid] = sQ[tid];
        if (tid < 128) {
            int k = tid >> 6, d = tid & 63;
            float acc = 0.f;
#pragma unroll 8
            for (int c = 0; c < 64; c++) acc += sQ[c * 2 + k] * lin1v[c * 64 + d];
            sR[k * 64 + d] = acc;
        }
        __syncthreads();
        int i = blockIdx.x * 256 + tid;
        if (i >= NN * 64) return;
        int n = i >> 6, c = i & 63;
        float q0 = sQ[c * 2], q1 = sQ[c * 2 + 1];
        const float* xp = x + n * 6;
        float v0 = xp[0] * q0 + xp[3] * q1;
        float v1 = xp[1] * q0 + xp[4] * q1;
        float v2 = xp[2] * q0 + xp[5] * q1;
        int base = n * 192 + c * 3;
        g_yv[0][base + 0] = v0; g_yv[0][base + 1] = v1; g_yv[0][base + 2] = v2;
        g_yv[1][base + 0] = v0; g_yv[1][base + 1] = v1; g_yv[1][base + 2] = v2;
        g_ys[0][i] = 0.f; g_ys[1][i] = 0.f;
        if (c < 3) g_pos[n * 3 + c] = xp[c];
        reinterpret_cast<float4*>(g_agg)[i] = make_float4(0.f, 0.f, 0.f, 0.f);
        int d = c;
        float r0 = sR[d], r1 = sR[64 + d];
#pragma unroll
        for (int xx = 0; xx < 3; xx++)
            g_v1[n * 192 + xx * 64 + d] = xp[xx] * r0 + xp[3 + xx] * r1;
    } else if (blockIdx.x < 5256) {
        // ---- B precompute, tiled: one block per (l,c); W column in regs ----
        int b = blockIdx.x - 5000;
        __shared__ __align__(16) float semb[3200];   // 100 x 32 (16B-aligned for LDS.128)
        for (int i = tid; i < 3200; i += 256) semb[i] = emb[i];
        __syncthreads();
        if (b < 128) {
            int l = b >> 6, c = b & 63;
            int o = tid & 127, ah = tid >> 7;       // a-half: 0 -> [0,50), 1 -> [50,100)
            float wcol[32];
            const float* w = scs + ((size_t)(l * 64 + c) * 32) * 128 + o;
#pragma unroll
            for (int e2 = 0; e2 < 32; e2++) wcol[e2] = w[e2 * 128];
            int a0 = ah * 50, a1 = a0 + 50;
            for (int a = a0; a < a1; a++) {
                const float4* em = (const float4*)(semb + a * 32);
                float acc = 0.f;
#pragma unroll
                for (int e4 = 0; e4 < 8; e4++) {
                    float4 u = em[e4];
                    acc += u.x * wcol[e4 * 4] + u.y * wcol[e4 * 4 + 1] +
                           u.z * wcol[e4 * 4 + 2] + u.w * wcol[e4 * 4 + 3];
                }
                g_Bs[((size_t)(l * 100 + a) * 64 + c) * 128 + o] = acc;
            }
        } else {
            int b2 = b - 128;
            int l = b2 >> 6, c = b2 & 63;
            int o = tid & 63, ah = tid >> 6;        // a-quarter: 25 each
            float wcol[32];
            const float* w = scv + ((size_t)(l * 64 + c) * 32) * 64 + o;
#pragma unroll
            for (int e2 = 0; e2 < 32; e2++) wcol[e2] = w[e2 * 64];
            int a0 = ah * 25, a1 = a0 + 25;
            for (int a = a0; a < a1; a++) {
                const float4* em = (const float4*)(semb + a * 32);
                float acc = 0.f;
#pragma unroll
                for (int e4 = 0; e4 < 8; e4++) {
                    float4 u = em[e4];
                    acc += u.x * wcol[e4 * 4] + u.y * wcol[e4 * 4 + 1] +
                           u.z * wcol[e4 * 4 + 2] + u.w * wcol[e4 * 4 + 3];
                }
                g_Bv[((size_t)(l * 100 + a) * 64 + c) * 64 + o] = acc;
            }
        }
    } else if (blockIdx.x == 5256) {
        // single-block node counting sort by attr, segments padded to 8
        __shared__ int scnt[128], soff[128], spos[128];
        if (tid < 128) { scnt[tid] = 0; spos[tid] = 0; }
        __syncthreads();
        for (int n = tid; n < NN; n += 256) atomicAdd(&scnt[attr[n]], 1);
        __syncthreads();
        int pc = 0;
        if (tid < 128) { pc = (scnt[tid] + 7) & ~7; soff[tid] = pc; }
        __syncthreads();
        for (int off = 1; off < 128; off <<= 1) {
            int v = 0;
            if (tid < 128 && tid >= off) v = soff[tid - off];
            __syncthreads();
            if (tid < 128) soff[tid] += v;
            __syncthreads();
        }
        if (tid < 128) soff[tid] -= pc;  // exclusive, 8-aligned
        __syncthreads();
        for (int i = tid; i < NPAD; i += 256) g_nidx[i] = -1;
        __syncthreads();
        for (int n = tid; n < NN; n += 256) {
            int a = attr[n];
            int p = soff[a] + atomicAdd(&spos[a], 1);
            g_nidx[p] = n;
            g_nattr[p] = a;
        }
    } else {
        // FILTERED edge histogram (layer-0 positions = x)
        for (int e = (blockIdx.x - 5257) * 256 + tid; e < NE; e += 1280 * 256) {
            int s = esrc[e], d = edst[e];
            float dx = x[s * 6 + 0] - x[d * 6 + 0];
            float dy = x[s * 6 + 1] - x[d * 6 + 1];
            float dz = x[s * 6 + 2] - x[d * 6 + 2];
            if (dx * dx + dy * dy + dz * dz < MAXR * MAXR)
                atomicAdd(&g_ecnt[d], 1);
        }
    }
}

// ---------------- edge offset scan (writes surviving count) ----------------
__global__ void __launch_bounds__(512) k_scan_e() {
    __shared__ int sp[512];
    int t = threadIdx.x;
    const int CH = 40;
    int base = t * CH;
    int part = 0;
    for (int i = 0; i < CH; i++) {
        int idx = base + i;
        if (idx < NN) part += g_ecnt[idx];
    }
    sp[t] = part;
    __syncthreads();
    for (int off = 1; off < 512; off <<= 1) {
        int v = (t >= off) ? sp[t - off] : 0;
        __syncthreads();
        sp[t] += v;
        __syncthreads();
    }
    if (t == 511) g_nesurv = sp[511];
    int run = sp[t] - part;
    for (int i = 0; i < CH; i++) {
        int idx = base + i;
        if (idx < NN) { g_eoff[idx] = run; run += g_ecnt[idx]; }
    }
}

// ---------------- filtered edge scatter ----------------
__global__ void k_scat_e(const int* __restrict__ esrc, const int* __restrict__ edst,
                         const float* __restrict__ x) {
    for (int e = blockIdx.x * 256 + threadIdx.x; e < NE; e += 1280 * 256) {
        int s = esrc[e], d = edst[e];
        float dx = x[s * 6 + 0] - x[d * 6 + 0];
        float dy = x[s * 6 + 1] - x[d * 6 + 1];
        float dz = x[s * 6 + 2] - x[d * 6 + 2];
        if (dx * dx + dy * dy + dz * dz < MAXR * MAXR) {
            int p = g_eoff[d] + atomicAdd(&g_eppos[d], 1);
            g_ssrc[p] = s;
            g_sdst[p] = d;
        }
    }
}

// ------- pre (layer 1) + sort-counter cleanup for next call's hist -------
__global__ void __launch_bounds__(256) k_pre(const float* __restrict__ lin1s,
                                             const float* __restrict__ lin1v,
                                             int layer, int cur) {
    __shared__ float sWs[4096], sWv[4096];
    __shared__ float sy[8][256];
    int tid = threadIdx.x;
    {
        int i = blockIdx.x * 256 + tid;
        if (i < NN) { g_ecnt[i] = 0; g_eppos[i] = 0; }
    }
    const float* Ws = lin1s + layer * 4096;
    const float* Wv = lin1v + layer * 4096;
    for (int k = tid; k < 4096; k += 256) { sWs[k] = Ws[k]; sWv[k] = Wv[k]; }
    const float* ys = g_ys[cur];
    const float* yv = g_yv[cur];
    int n0 = blockIdx.x * 8;
    for (int k = tid; k < 2048; k += 256) {
        int nn = k >> 8, j = k & 255;
        int n = n0 + nn;
        sy[nn][j] = (j < 64) ? ys[n * 64 + j] : yv[n * 192 + j - 64];
    }
    __syncthreads();
    for (int nn = 0; nn < 8; nn++) {
        int n = n0 + nn;
        if (tid < 64) {
            int d = tid;
            float acc = 0.f;
#pragma unroll 8
            for (int c = 0; c < 64; c++) acc += sy[nn][c] * sWs[c * 64 + d];
            g_s1[n * 64 + d] = acc;
        } else {
            int idx = tid - 64;
            int d = idx & 63, xx = idx >> 6;
            float acc = 0.f;
#pragma unroll 8
            for (int c = 0; c < 64; c++) acc += sy[nn][64 + c * 3 + xx] * sWv[c * 64 + d];
            g_v1[n * 192 + xx * 64 + d] = acc;
        }
    }
}

// -------- per-edge scalar math (W1 in regs); returns silu(h) for this lane --------
__device__ __forceinline__ float edge_scalar(float ev0, float ev1, float ev2, float l2,
                                             const float* w1r, float br,
                                             float& ea0, float& ea1, float& ea2) {
    const float PI = 3.14159265358979f;
    float elen = sqrtf(l2);
    float safe = fmaxf(elen, 1e-9f);
    float inv = 1.0f / safe;
    float u = fminf(2.f * (elen * (1.0f / MAXR) - 1.f), 0.f);  // clamp: cut=0 beyond MAXR
    float cut = 0.5f * (1.f - __cosf(PI * u));
    float ca = cut * 1.7320508075688772f * inv;
    ea0 = ca * ev0; ea1 = ca * ev1; ea2 = ca * ev2;
    float th = (PI / MAXR) * safe;
    float sk = __sinf(th), c2 = 2.f * __cosf(th), skm1 = 0.f;
    float fac = 2.5298221281347035f * inv;
    float hs = br;
#pragma unroll
    for (int k = 0; k < 8; k++) {
        hs += (fac * sk) * w1r[k];
        float t = c2 * sk - skm1; skm1 = sk; sk = t;
    }
    return hs / (1.f + __expf(-hs));  // silu
}

// W2 duplicated-bf16x2 layout: sW2d[k*32+lane] = {dup(w0),dup(w1),dup(w2),dup(w3)}
__device__ __forceinline__ void fill_w2d(uint4* sW2d, const float* rW2, int layer,
                                         int tid) {
    for (int t = tid; t < 1024; t += 256) {
        int k = t >> 5, ln = t & 31;
        const float* base = rW2 + layer * 4096 + k * 128;
        uint4 v;
        __nv_bfloat162 p0 = __float2bfloat162_rn(base[ln]);
        __nv_bfloat162 p1 = __float2bfloat162_rn(base[32 + ln]);
        __nv_bfloat162 p2 = __float2bfloat162_rn(base[64 + ln]);
        __nv_bfloat162 p3 = __float2bfloat162_rn(base[96 + ln]);
        v.x = *reinterpret_cast<unsigned*>(&p0);
        v.y = *reinterpret_cast<unsigned*>(&p1);
        v.z = *reinterpret_cast<unsigned*>(&p2);
        v.w = *reinterpret_cast<unsigned*>(&p3);
        sW2d[t] = v;
    }
}

// -------- edge: dst-sorted filtered list, 4-edge groups, register accumulation --------
__global__ void __launch_bounds__(256) k_edge(const float* __restrict__ rW1,
                                              const float* __restrict__ rb1,
                                              const float* __restrict__ rW2,
                                              int layer, int skip_s1) {
    __shared__ uint4 sW2d[1024];   // 16 KB
    int tid = threadIdx.x;
    int lane = tid & 31;
    fill_w2d(sW2d, rW2, layer, tid);
    float w1r[8];
#pragma unroll
    for (int k = 0; k < 8; k++) w1r[k] = rW1[layer * 256 + k * 32 + lane];
    float br = rb1[layer * 32 + lane];
    __syncthreads();
    int cnt = g_nesurv;
    int warp = (blockIdx.x * 256 + tid) >> 5;
    int nw = gridDim.x * 8;
    int K = (cnt + nw - 1) / nw;
    int e0 = warp * K;
    if (e0 >= cnt) return;
    int e1 = e0 + K; if (e1 > cnt) e1 = cnt;
    float4 acc0 = make_float4(0.f, 0.f, 0.f, 0.f);
    float4 acc1 = make_float4(0.f, 0.f, 0.f, 0.f);
    bool touched = false;
    int cur = -1;
    __nv_bfloat162 zz; zz.x = __float2bfloat16(0.f); zz.y = zz.x;
    for (int e = e0; e < e1; e += 4) {
        int cnt4 = e1 - e; if (cnt4 > 4) cnt4 = 4;
        int srcs[4], dsts[4];
        float hv4[4], eaX[4], eaY[4], eaZ[4];
#pragma unroll
        for (int i = 0; i < 4; i++) {
            int idx = (i < cnt4) ? (e + i) : (e + cnt4 - 1);
            int d = g_sdst[idx], s = g_ssrc[idx];
            srcs[i] = s; dsts[i] = d;
            float dp0 = g_pos[d * 3 + 0], dp1 = g_pos[d * 3 + 1], dp2 = g_pos[d * 3 + 2];
            float ev0 = g_pos[s * 3 + 0] - dp0;
            float ev1 = g_pos[s * 3 + 1] - dp1;
            float ev2 = g_pos[s * 3 + 2] - dp2;
            float l2 = ev0 * ev0 + ev1 * ev1 + ev2 * ev2;
            float h = edge_scalar(ev0, ev1, ev2, l2, w1r, br, eaX[i], eaY[i], eaZ[i]);
            hv4[i] = (i < cnt4) ? h : 0.f;   // padded edges contribute zero
        }
        // ---- grouped W2 matvec: 2 SHFL + 1 LDS.128 + 8 HFMA2 per k for 4 edges ----
        __nv_bfloat162 h01 = __floats2bfloat162_rn(hv4[0], hv4[1]);
        __nv_bfloat162 h23 = __floats2bfloat162_rn(hv4[2], hv4[3]);
        unsigned u01 = *reinterpret_cast<unsigned*>(&h01);
        unsigned u23 = *reinterpret_cast<unsigned*>(&h23);
        __nv_bfloat162 p0 = zz, p1 = zz, p2 = zz, p3 = zz;
        __nv_bfloat162 q0 = zz, q1 = zz, q2 = zz, q3 = zz;
#pragma unroll
        for (int k = 0; k < 32; k++) {
            unsigned s01 = __shfl_sync(0xffffffffu, u01, k);
            unsigned s23 = __shfl_sync(0xffffffffu, u23, k);
            uint4 wv = sW2d[k * 32 + lane];
            __nv_bfloat162 b01 = *reinterpret_cast<__nv_bfloat162*>(&s01);
            __nv_bfloat162 b23 = *reinterpret_cast<__nv_bfloat162*>(&s23);
            p0 = __hfma2(b01, *reinterpret_cast<__nv_bfloat162*>(&wv.x), p0);
            p1 = __hfma2(b01, *reinterpret_cast<__nv_bfloat162*>(&wv.y), p1);
            p2 = __hfma2(b01, *reinterpret_cast<__nv_bfloat162*>(&wv.z), p2);
            p3 = __hfma2(b01, *reinterpret_cast<__nv_bfloat162*>(&wv.w), p3);
            q0 = __hfma2(b23, *reinterpret_cast<__nv_bfloat162*>(&wv.x), q0);
            q1 = __hfma2(b23, *reinterpret_cast<__nv_bfloat162*>(&wv.y), q1);
            q2 = __hfma2(b23, *reinterpret_cast<__nv_bfloat162*>(&wv.z), q2);
            q3 = __hfma2(b23, *reinterpret_cast<__nv_bfloat162*>(&wv.w), q3);
        }
        float2 f0p = __bfloat1622float2(p0), f1p = __bfloat1622float2(p1);
        float2 f2p = __bfloat1622float2(p2), f3p = __bfloat1622float2(p3);
        float2 f0q = __bfloat1622float2(q0), f1q = __bfloat1622float2(q1);
        float2 f2q = __bfloat1622float2(q2), f3q = __bfloat1622float2(q3);
        float w0v[4] = {f0p.x, f0p.y, f0q.x, f0q.y};
        float w1v[4] = {f1p.x, f1p.y, f1q.x, f1q.y};
        float w2v[4] = {f2p.x, f2p.y, f2q.x, f2q.y};
        float w3v[4] = {f3p.x, f3p.y, f3q.x, f3q.y};
        // ---- accumulate each edge in order ----
#pragma unroll
        for (int i = 0; i < 4; i++) {
            int dst = dsts[i];
            if (dst != cur) {
                if (touched) {
                    float4* ap = reinterpret_cast<float4*>(g_agg + (size_t)cur * 256);
                    atomicAdd(ap + lane, acc0);
                    atomicAdd(ap + lane + 32, acc1);
                    acc0 = make_float4(0.f, 0.f, 0.f, 0.f);
                    acc1 = make_float4(0.f, 0.f, 0.f, 0.f);
                    touched = false;
                }
                cur = dst;
            }
            int src = srcs[i];
            float sa = 0.f, sb = 0.f;
            if (!skip_s1) {
                const float* s1p = g_s1 + (size_t)src * 64;
                sa = s1p[lane] * w0v[i];
                sb = s1p[lane + 32] * w1v[i];
            }
            const float* v1p = g_v1 + (size_t)src * 192;
            float ex = eaX[i], ey = eaY[i], ez = eaZ[i];
            float da = w2v[i] * (v1p[lane] * ex + v1p[64 + lane] * ey + v1p[128 + lane] * ez);
            float db = w3v[i] * (v1p[lane + 32] * ex + v1p[96 + lane] * ey + v1p[160 + lane] * ez);
            acc0.x += sa * ex; acc0.y += sa * ey; acc0.z += sa * ez; acc0.w += da;
            acc1.x += sb * ex; acc1.y += sb * ey; acc1.z += sb * ez; acc1.w += db;
            touched = true;
        }
    }
    if (touched) {
        float4* ap = reinterpret_cast<float4*>(g_agg + (size_t)cur * 256);
        atomicAdd(ap + lane, acc0);
        atomicAdd(ap + lane + 32, acc1);
    }
}

// ------ post v7: float4 input LDS, float2 tasks, zeroes agg (layer 0) ------
__global__ void __launch_bounds__(256, 3) k_post(const float* __restrict__ lin2s,
                                                 const float* __restrict__ lin2v,
                                                 const float* __restrict__ sis,
                                                 const float* __restrict__ siv,
                                                 const float* __restrict__ hv,
                                                 const float* __restrict__ mv,
                                                 int layer, int cur,
                                                 float* __restrict__ outp) {
    __shared__ float s_Q[128];
    __shared__ __align__(16) float s_ys[8][64], s_aggs[8][64];
    __shared__ __align__(16) float s_yv[8][192], s_aggv[8][192];   // [xx*64+c]
    __shared__ __align__(16) float s_outs[8][128];
    __shared__ __align__(16) float s_outv[8][192];
    __shared__ __align__(16) float s_y2s[8][64];
    __shared__ __align__(16) float s_y2v[8][192];
    __shared__ float s_newv[8][192];
    int tid = threadIdx.x;
    int wid = tid >> 5;
    if (tid < 128) s_Q[tid] = g_Q[tid];
    float hh = hv[layer] * hv[layer];
    float m = mv[layer];
    float* ys_new = g_ys[cur ^ 1];
    float* yv_new = g_yv[cur ^ 1];
    const float* ys_cur = g_ys[cur];
    const float* yv_cur = g_yv[cur];
    for (int it = 0; it < 2; it++) {
        int pbase = blockIdx.x * 16 + it * 8;
        for (int t = tid; t < 512; t += 256) {
            int node = t >> 6, j = t & 63;
            int n = g_nidx[pbase + node];
            if (n >= 0) {
                s_ys[node][j] = ys_cur[n * 64 + j];
                float4 a4 = ((const float4*)g_agg)[n * 64 + j];
                if (layer == 0)
                    ((float4*)g_agg)[n * 64 + j] = make_float4(0.f, 0.f, 0.f, 0.f);
                s_aggs[node][j] = a4.w * INV_NN;
                s_aggv[node][j] = a4.x * INV_NN;
                s_aggv[node][64 + j] = a4.y * INV_NN;
                s_aggv[node][128 + j] = a4.z * INV_NN;
                const float* yvp = yv_cur + n * 192 + j * 3;
                s_yv[node][j] = yvp[0];
                s_yv[node][64 + j] = yvp[1];
                s_yv[node][128 + j] = yvp[2];
            }
        }
        __syncthreads();
        int a = g_nattr[pbase];   // chunk is attr-uniform
        if (wid < 5) {
            const float2 *wp, *bp;
            int wstr;
            const float *in1, *in2;
            int istr;
            float2* o2;
            int ostr;
            if (tid < 64) {
                int j = tid;
                wp = (const float2*)(lin2s + layer * 8192) + j;
                bp = (const float2*)(g_Bs + (size_t)(layer * 100 + a) * 8192) + j;
                wstr = 64;
                in1 = &s_aggs[0][0]; in2 = &s_ys[0][0]; istr = 64;
                o2 = (float2*)&s_outs[0][0] + j; ostr = 64;
            } else {
                int id = tid - 64, xx = id >> 5, j = id & 31;
                wp = (const float2*)(lin2v + layer * 4096) + j;
                bp = (const float2*)(g_Bv + (size_t)(layer * 100 + a) * 4096) + j;
                wstr = 32;
                in1 = &s_aggv[0][xx * 64]; in2 = &s_yv[0][xx * 64]; istr = 192;
                o2 = (float2*)&s_outv[0][0] + xx * 32 + j; ostr = 96;
            }
            float2 acc[8];
#pragma unroll
            for (int nn = 0; nn < 8; nn++) acc[nn] = make_float2(0.f, 0.f);
            for (int c = 0; c < 64; c += 4) {
                float2 w0 = __ldg(wp + (c + 0) * wstr);
                float2 w1 = __ldg(wp + (c + 1) * wstr);
                float2 w2 = __ldg(wp + (c + 2) * wstr);
                float2 w3 = __ldg(wp + (c + 3) * wstr);
                float2 b0 = __ldg(bp + (c + 0) * wstr);
                float2 b1 = __ldg(bp + (c + 1) * wstr);
                float2 b2 = __ldg(bp + (c + 2) * wstr);
                float2 b3 = __ldg(bp + (c + 3) * wstr);
#pragma unroll
                for (int nn = 0; nn < 8; nn++) {
                    float4 u1 = *(const float4*)(in1 + nn * istr + c);
                    float4 u2 = *(const float4*)(in2 + nn * istr + c);
                    acc[nn].x += u1.x * w0.x + u2.x * b0.x;
                    acc[nn].y += u1.x * w0.y + u2.x * b0.y;
                    acc[nn].x += u1.y * w1.x + u2.y * b1.x;
                    acc[nn].y += u1.y * w1.y + u2.y * b1.y;
                    acc[nn].x += u1.z * w2.x + u2.z * b2.x;
                    acc[nn].y += u1.z * w2.y + u2.z * b2.y;
                    acc[nn].x += u1.w * w3.x + u2.w * b3.x;
                    acc[nn].y += u1.w * w3.y + u2.w * b3.y;
                }
            }
#pragma unroll
            for (int nn = 0; nn < 8; nn++) o2[nn * ostr] = acc[nn];
        } else if (wid == 5) {
            int j = tid - 160;
            const float2* wp = (const float2*)(sis + layer * 4096) + j;
            float2 acc[8];
#pragma unroll
            for (int nn = 0; nn < 8; nn++) acc[nn] = make_float2(0.f, 0.f);
            for (int c = 0; c < 64; c += 4) {
                float2 w0 = __ldg(wp + (c + 0) * 32);
                float2 w1 = __ldg(wp + (c + 1) * 32);
                float2 w2 = __ldg(wp + (c + 2) * 32);
                float2 w3 = __ldg(wp + (c + 3) * 32);
#pragma unroll
                for (int nn = 0; nn < 8; nn++) {
                    float4 u = *(const float4*)(&s_ys[nn][c]);
                    acc[nn].x += u.x * w0.x + u.y * w1.x + u.z * w2.x + u.w * w3.x;
                    acc[nn].y += u.x * w0.y + u.y * w1.y + u.z * w2.y + u.w * w3.y;
                }
            }
#pragma unroll
            for (int nn = 0; nn < 8; nn++)
                ((float2*)&s_y2s[0][0])[nn * 32 + j] = acc[nn];
        } else if (tid < 240) {
            int id = tid - 192, xx = id >> 4, j = id & 15;
            const float4* wp = (const float4*)(siv + layer * 4096) + j;
            const float* in = &s_yv[0][xx * 64];
            float4 acc[8];
#pragma unroll
            for (int nn = 0; nn < 8; nn++) acc[nn] = make_float4(0.f, 0.f, 0.f, 0.f);
            for (int c = 0; c < 64; c += 4) {
                float4 w0 = __ldg(wp + (c + 0) * 16);
                float4 w1 = __ldg(wp + (c + 1) * 16);
                float4 w2 = __ldg(wp + (c + 2) * 16);
                float4 w3 = __ldg(wp + (c + 3) * 16);
#pragma unroll
                for (int nn = 0; nn < 8; nn++) {
                    float4 u = *(const float4*)(in + nn * 192 + c);
                    acc[nn].x += u.x * w0.x + u.y * w1.x + u.z * w2.x + u.w * w3.x;
                    acc[nn].y += u.x * w0.y + u.y * w1.y + u.z * w2.y + u.w * w3.y;
                    acc[nn].z += u.x * w0.z + u.y * w1.z + u.z * w2.z + u.w * w3.z;
                    acc[nn].w += u.x * w0.w + u.y * w1.w + u.z * w2.w + u.w * w3.w;
                }
            }
#pragma unroll
            for (int nn = 0; nn < 8; nn++)
                ((float4*)&s_y2v[0][0])[nn * 48 + xx * 16 + j] = acc[nn];
        }
        __syncthreads();
        for (int t = tid; t < 512; t += 256) {
            int node = t >> 6, c = t & 63;
            int n = g_nidx[pbase + node];
            if (n >= 0) {
                float os = s_outs[node][c];
                float gs = os / (1.f + __expf(-os));
                float gate = 1.f / (1.f + __expf(-s_outs[node][64 + c]));
                float yo = ys_new[n * 64 + c];
                float ns = 2.f * s_ys[node][c] - yo + hh * (m * gs + (m - 1.f) * s_y2s[node][c]);
                ys_new[n * 64 + c] = ns;
#pragma unroll
                for (int xx = 0; xx < 3; xx++) {
                    float yov = yv_new[n * 192 + c * 3 + xx];
                    float nv = 2.f * s_yv[node][xx * 64 + c] - yov +
                               hh * (m * gate * s_outv[node][xx * 64 + c] +
                                     (m - 1.f) * s_y2v[node][xx * 64 + c]);
                    yv_new[n * 192 + c * 3 + xx] = nv;
                    s_newv[node][xx * 64 + c] = nv;
                }
            }
        }
        __syncthreads();
        if (tid < 48) {
            int node = tid / 6, r = tid % 6, k = r / 3, xx = r % 3;
            int n = g_nidx[pbase + node];
            if (n >= 0) {
                float acc = 0.f;
#pragma unroll 8
                for (int c = 0; c < 64; c++) acc += s_newv[node][xx * 64 + c] * s_Q[c * 2 + k];
                if (layer == 0) {
                    if (k == 0) g_pos[n * 3 + xx] = acc;
                } else {
                    outp[n * 6 + k * 3 + xx] = acc;
                }
            }
        }
        __syncthreads();
    }
}

// ---------------- launch ----------------
extern "C" void kernel_launch(void* const* d_in, const int* in_sizes, int n_in,
                              void* d_out, int out_size) {
    const float* x        = (const float*)d_in[0];
    const int*   attr     = (const int*)d_in[2];
    const int*   esrc     = (const int*)d_in[3];
    const int*   edst     = (const int*)d_in[4];
    const float* emb      = (const float*)d_in[5];
    const float* uplift   = (const float*)d_in[6];
    const float* h        = (const float*)d_in[7];
    const float* mix      = (const float*)d_in[8];
    const float* rW1      = (const float*)d_in[9];
    const float* rb1      = (const float*)d_in[10];
    const float* rW2      = (const float*)d_in[11];
    const float* lin1s    = (const float*)d_in[12];
    const float* lin1v    = (const float*)d_in[13];
    const float* lin2s    = (const float*)d_in[14];
    const float* lin2v    = (const float*)d_in[15];
    const float* scs      = (const float*)d_in[16];
    const float* scv      = (const float*)d_in[17];
    const float* sis      = (const float*)d_in[18];
    const float* siv      = (const float*)d_in[19];
    float* out = (float*)d_out;

    const int PB = NPAD / 16;  // 1300

    k_init<<<6537, 256>>>(x, uplift, emb, scs, scv, lin1v, attr, esrc, edst); // 0
    k_scan_e<<<1, 512>>>();                                                   // 1
    k_scat_e<<<1280, 256>>>(esrc, edst, x);                                   // 2
    k_edge<<<2000, 256>>>(rW1, rb1, rW2, 0, 1);                               // 3 <- profiled
    k_post<<<PB, 256>>>(lin2s, lin2v, sis, siv, h, mix, 0, 0, out);           // 4
    k_pre<<<NN / 8, 256>>>(lin1s, lin1v, 1, 1);                               // 5 (+cnt cleanup)
    k_edge<<<2000, 256>>>(rW1, rb1, rW2, 1, 0);                               // 6
    k_post<<<PB, 256>>>(lin2s, lin2v, sis, siv, h, mix, 1, 1, out);           // 7
}